// round 2
// baseline (speedup 1.0000x reference)
#include <cuda_runtime.h>
#include <math.h>

// Problem constants
#define B_  16
#define S_  2048
#define H_  768
#define HH_ 384
#define C_  64
#define L_  4

// ---------------- scratch (static __device__ arrays; no allocation) ----------
__device__ float g_q   [12582912];   // B*S*HH
__device__ float g_k   [12582912];   // B*S*HH
__device__ float g_attn[67108864];   // B*S*S
__device__ float g_ctx [25165824];   // B*S*H
__device__ float g_hpre[12582912];   // B*S*HH
__device__ float g_ts  [32768];      // B*S
__device__ float g_pool[12288];      // B*H

// ---------------- generic SGEMM: C = alpha * A @ (B or B^T) + bias -----------
// A row-major [M,K]; TRANSB=false: B row-major [K,N]; TRANSB=true: B row-major [N,K].
// Tiles: 128x128x8, 256 threads, 8x8 register tile. Requires M%128==0, N%128==0, K%8==0.
template<bool TRANSB>
__global__ __launch_bounds__(256)
void sgemm_kernel(const float* __restrict__ A, const float* __restrict__ Bm,
                  float* __restrict__ C, const float* __restrict__ bias,
                  int M, int N, int K, float alpha,
                  size_t sA, size_t sB, size_t sC)
{
    __shared__ float As[8][128];
    __shared__ float Bs[8][128];
    const int tid = threadIdx.x;
    const int mBase = blockIdx.y * 128;
    const int nBase = blockIdx.x * 128;
    A  += (size_t)blockIdx.z * sA;
    Bm += (size_t)blockIdx.z * sB;
    C  += (size_t)blockIdx.z * sC;

    const int tm = (tid >> 4) << 3;   // 0..120
    const int tn = (tid & 15) << 3;   // 0..120

    float acc[8][8];
#pragma unroll
    for (int i = 0; i < 8; i++)
#pragma unroll
        for (int j = 0; j < 8; j++) acc[i][j] = 0.f;

    const int arow = tid >> 1,  acol = (tid & 1) * 4;   // A tile load mapping
    const int brow = tid >> 5,  bcol = (tid & 31) * 4;  // NN B mapping
    const int nrow = tid >> 1,  kcol = (tid & 1) * 4;   // NT B mapping

    for (int kt = 0; kt < K; kt += 8) {
        float4 av = *(const float4*)(A + (size_t)(mBase + arow) * K + kt + acol);
        As[acol + 0][arow] = av.x; As[acol + 1][arow] = av.y;
        As[acol + 2][arow] = av.z; As[acol + 3][arow] = av.w;
        if (TRANSB) {
            float4 bv = *(const float4*)(Bm + (size_t)(nBase + nrow) * K + kt + kcol);
            Bs[kcol + 0][nrow] = bv.x; Bs[kcol + 1][nrow] = bv.y;
            Bs[kcol + 2][nrow] = bv.z; Bs[kcol + 3][nrow] = bv.w;
        } else {
            float4 bv = *(const float4*)(Bm + (size_t)(kt + brow) * N + nBase + bcol);
            *(float4*)&Bs[brow][bcol] = bv;
        }
        __syncthreads();
#pragma unroll
        for (int k = 0; k < 8; k++) {
            float a[8], bb[8];
            *(float4*)&a[0]  = *(const float4*)&As[k][tm];
            *(float4*)&a[4]  = *(const float4*)&As[k][tm + 4];
            *(float4*)&bb[0] = *(const float4*)&Bs[k][tn];
            *(float4*)&bb[4] = *(const float4*)&Bs[k][tn + 4];
#pragma unroll
            for (int i = 0; i < 8; i++)
#pragma unroll
                for (int j = 0; j < 8; j++) acc[i][j] += a[i] * bb[j];
        }
        __syncthreads();
    }

#pragma unroll
    for (int i = 0; i < 8; i++) {
        size_t roff = (size_t)(mBase + tm + i) * N + nBase + tn;
#pragma unroll
        for (int j = 0; j < 8; j++) {
            float v = acc[i][j] * alpha;
            if (bias) v += bias[nBase + tn + j];
            C[roff + j] = v;
        }
    }
}

// ---------------- softmax over last dim (2048), in place, with key mask ------
__global__ __launch_bounds__(256)
void softmax_kernel(float* __restrict__ attn, const int* __restrict__ am)
{
    __shared__ float red[256];
    const size_t row = blockIdx.x;           // b*S + s
    const int b = (int)(row >> 11);
    float* a = attn + row * (size_t)S_;
    const int* amb = am + (size_t)b * S_;
    const int t = threadIdx.x;

    float vals[8];
    float mx = -3.0e38f;
#pragma unroll
    for (int i = 0; i < 8; i++) {
        int idx = t + i * 256;
        float v = a[idx];
        if (amb[idx] == 0) v = -10000.f;
        vals[i] = v;
        mx = fmaxf(mx, v);
    }
    red[t] = mx; __syncthreads();
    for (int o = 128; o > 0; o >>= 1) { if (t < o) red[t] = fmaxf(red[t], red[t + o]); __syncthreads(); }
    const float rmax = red[0];
    __syncthreads();

    float se = 0.f;
#pragma unroll
    for (int i = 0; i < 8; i++) { float e = __expf(vals[i] - rmax); vals[i] = e; se += e; }
    red[t] = se; __syncthreads();
    for (int o = 128; o > 0; o >>= 1) { if (t < o) red[t] += red[t + o]; __syncthreads(); }
    const float inv = 1.f / red[0];
#pragma unroll
    for (int i = 0; i < 8; i++) a[t + i * 256] = vals[i] * inv;
}

// ---------------- per-row LayerNorm + ReLU + dot(W2) -> token score ----------
__global__ __launch_bounds__(128)
void lnscore_kernel(const float* __restrict__ hpre, const float* __restrict__ g1,
                    const float* __restrict__ be1, const float* __restrict__ W2,
                    const float* __restrict__ b2, const int* __restrict__ am,
                    float* __restrict__ ts)
{
    __shared__ float red[128];
    const int row = blockIdx.x, t = threadIdx.x;
    const float* hr = hpre + (size_t)row * HH_;
    const float v0 = hr[t], v1 = hr[t + 128], v2 = hr[t + 256];

    red[t] = v0 + v1 + v2; __syncthreads();
    for (int o = 64; o > 0; o >>= 1) { if (t < o) red[t] += red[t + o]; __syncthreads(); }
    const float mean = red[0] * (1.f / HH_);
    __syncthreads();

    const float d0 = v0 - mean, d1 = v1 - mean, d2 = v2 - mean;
    red[t] = d0 * d0 + d1 * d1 + d2 * d2; __syncthreads();
    for (int o = 64; o > 0; o >>= 1) { if (t < o) red[t] += red[t + o]; __syncthreads(); }
    const float inv = rsqrtf(red[0] * (1.f / HH_) + 1e-5f);
    __syncthreads();

    float sp = fmaxf(d0 * inv * g1[t]       + be1[t],       0.f) * W2[t]
             + fmaxf(d1 * inv * g1[t + 128] + be1[t + 128], 0.f) * W2[t + 128]
             + fmaxf(d2 * inv * g1[t + 256] + be1[t + 256], 0.f) * W2[t + 256];
    red[t] = sp; __syncthreads();
    for (int o = 64; o > 0; o >>= 1) { if (t < o) red[t] += red[t + o]; __syncthreads(); }
    if (t == 0) {
        float v = red[0] + b2[0];
        if (am[row] == 0) v = -10000.f;
        ts[row] = v;
    }
}

// ---------------- span search (argmax over [18, S] flat) + mean pooling ------
__global__ __launch_bounds__(256)
void span_pool_kernel(const float* __restrict__ ts, const int* __restrict__ am,
                      const float* __restrict__ x, float* __restrict__ pooled)
{
    __shared__ float sc[2048];
    __shared__ float cum[2049];
    __shared__ float part[256];
    __shared__ int   ired[256];
    __shared__ float bvs[256];
    __shared__ int   bis[256];
    __shared__ int   s_start, s_len;

    const int b = blockIdx.x, t = threadIdx.x;

    int vc = 0;
    for (int i = t; i < S_; i += 256) {
        sc[i] = ts[(size_t)b * S_ + i];
        vc += am[(size_t)b * S_ + i];
    }
    ired[t] = vc; __syncthreads();
    for (int o = 128; o > 0; o >>= 1) { if (t < o) ired[t] += ired[t + o]; __syncthreads(); }
    const int vl = ired[0];

    // exclusive prefix sum of scores (cum[i] = sum of sc[0..i-1])
    float ps = 0.f;
    for (int i = 0; i < 8; i++) ps += sc[t * 8 + i];
    part[t] = ps; __syncthreads();
    if (t == 0) {
        float run = 0.f;
        for (int i = 0; i < 256; i++) { float v = part[i]; part[i] = run; run += v; }
        cum[2048] = run;
    }
    __syncthreads();
    float run = part[t];
    for (int i = 0; i < 8; i++) { int idx = t * 8 + i; cum[idx] = run; run += sc[idx]; }
    __syncthreads();

    // argmax over flat = l_idx * S + start, first-max tie-break (matches jnp.argmax)
    float bestV = -3.0e38f; int bestI = 0x7fffffff;
    for (int flat = t; flat < 18 * S_; flat += 256) {
        const int li = flat >> 11, start = flat & 2047;
        const int L = 3 + li, end = start + L;
        const int endc = end > S_ ? S_ : end;
        const float fL = (float)L;
        float avg = (cum[endc] - cum[start]) / fL + 0.01f * fL / 20.0f;
        if (end > vl) avg = -1e30f;
        if (avg > bestV) { bestV = avg; bestI = flat; }
    }
    bvs[t] = bestV; bis[t] = bestI; __syncthreads();
    for (int o = 128; o > 0; o >>= 1) {
        if (t < o) {
            if (bvs[t + o] > bvs[t] || (bvs[t + o] == bvs[t] && bis[t + o] < bis[t])) {
                bvs[t] = bvs[t + o]; bis[t] = bis[t + o];
            }
        }
        __syncthreads();
    }
    if (t == 0) {
        const int fi = bis[0];
        int start = fi & 2047, L = 3 + (fi >> 11);
        if (vl <= 3) { start = 0; L = vl; }
        s_start = start; s_len = L;
    }
    __syncthreads();

    const int start = s_start, L = s_len;
    const float inv = 1.0f / ((float)L + 1e-6f);
    for (int h = t; h < H_; h += 256) {
        float s = 0.f;
        for (int r = 0; r < L; r++) s += x[((size_t)b * S_ + start + r) * H_ + h];
        pooled[b * H_ + h] = s * inv;
    }
}

// ---------------- classification head (tiny): one block per batch ------------
__global__ __launch_bounds__(384)
void head_kernel(const float* __restrict__ pooled, const float* __restrict__ x,
                 const float* __restrict__ Wc1, const float* __restrict__ bc1,
                 const float* __restrict__ g2, const float* __restrict__ be2,
                 const float* __restrict__ Wc2, const float* __restrict__ bc2,
                 const float* __restrict__ Mint,
                 const float* __restrict__ Wcls, const float* __restrict__ bcls,
                 float* __restrict__ out)
{
    __shared__ float pl[768];
    __shared__ float hc[384];
    __shared__ float cs[64];
    __shared__ float cp[64];
    __shared__ float red[512];
    const int b = blockIdx.x, t = threadIdx.x;

    for (int i = t; i < H_; i += 384) pl[i] = pooled[b * H_ + i];
    if (t < 128) red[384 + t] = 0.f;
    __syncthreads();

    float acc = bc1[t];
    for (int k = 0; k < H_; k++) acc += pl[k] * Wc1[(size_t)k * HH_ + t];

    red[t] = acc; __syncthreads();
    for (int o = 256; o > 0; o >>= 1) { if (t < o) red[t] += red[t + o]; __syncthreads(); }
    const float mean = red[0] * (1.f / HH_);
    __syncthreads();
    const float d = acc - mean;
    red[t] = d * d; __syncthreads();
    for (int o = 256; o > 0; o >>= 1) { if (t < o) red[t] += red[t + o]; __syncthreads(); }
    const float var = red[0] * (1.f / HH_);
    const float yn = d * rsqrtf(var + 1e-5f) * g2[t] + be2[t];
    hc[t] = fmaxf(yn, 0.f);
    __syncthreads();

    if (t < C_) {
        float c = bc2[t];
        for (int k = 0; k < HH_; k++) c += hc[k] * Wc2[(size_t)k * C_ + t];
        cs[t] = c;
    }
    __syncthreads();
    if (t < C_) {
        float add = cs[t];
        for (int i = 0; i < C_; i++) {
            const float m = 0.5f * (Mint[i * C_ + t] + Mint[t * C_ + i]);
            const float sg = 1.f / (1.f + expf(-m));
            add += cs[i] * sg;
        }
        cp[t] = 1.f / (1.f + expf(-add));
    }
    __syncthreads();
    if (t < L_) {
        float lg = bcls[t];
        for (int c = 0; c < C_; c++) lg += cp[c] * Wcls[c * L_ + t];
        const float* xr = x + (size_t)b * S_ * H_;     // cls_emb = x[b, 0, :]
        for (int h = 0; h < H_; h++) lg += xr[h] * Wcls[(C_ + h) * L_ + t];
        out[b * L_ + t] = lg;
    }
}

// ---------------------------- launcher ---------------------------------------
extern "C" void kernel_launch(void* const* d_in, const int* in_sizes, int n_in,
                              void* d_out, int out_size)
{
    const float* x    = (const float*)d_in[0];
    const int*   am   = (const int*)  d_in[1];
    const float* Wq   = (const float*)d_in[2];
    const float* bq   = (const float*)d_in[3];
    const float* Wk   = (const float*)d_in[4];
    const float* bk   = (const float*)d_in[5];
    const float* W1   = (const float*)d_in[6];
    const float* b1   = (const float*)d_in[7];
    const float* g1   = (const float*)d_in[8];
    const float* be1  = (const float*)d_in[9];
    const float* W2   = (const float*)d_in[10];
    const float* b2   = (const float*)d_in[11];
    const float* Wc1  = (const float*)d_in[12];
    const float* bc1  = (const float*)d_in[13];
    const float* g2   = (const float*)d_in[14];
    const float* be2  = (const float*)d_in[15];
    const float* Wc2  = (const float*)d_in[16];
    const float* bc2  = (const float*)d_in[17];
    const float* Mint = (const float*)d_in[18];
    const float* Wcls = (const float*)d_in[19];
    const float* bcls = (const float*)d_in[20];
    float* out = (float*)d_out;

    float *qp, *kp, *ap, *ctxp, *hp, *tp, *pp;
    cudaGetSymbolAddress((void**)&qp,   g_q);
    cudaGetSymbolAddress((void**)&kp,   g_k);
    cudaGetSymbolAddress((void**)&ap,   g_attn);
    cudaGetSymbolAddress((void**)&ctxp, g_ctx);
    cudaGetSymbolAddress((void**)&hp,   g_hpre);
    cudaGetSymbolAddress((void**)&tp,   g_ts);
    cudaGetSymbolAddress((void**)&pp,   g_pool);

    // 1. q = x@Wq + bq ; k = x@Wk + bk    ([32768,768] @ [768,384])
    sgemm_kernel<false><<<dim3(3, 256, 1), 256>>>(x, Wq, qp, bq, B_ * S_, HH_, H_, 1.f, 0, 0, 0);
    sgemm_kernel<false><<<dim3(3, 256, 1), 256>>>(x, Wk, kp, bk, B_ * S_, HH_, H_, 1.f, 0, 0, 0);

    // 2. attn = q @ k^T / sqrt(HH)   (batched NT, 16 x [2048,384]x[2048,384]^T)
    const float alpha = 1.0f / sqrtf((float)HH_);
    sgemm_kernel<true><<<dim3(16, 16, B_), 256>>>(qp, kp, ap, nullptr, S_, S_, HH_, alpha,
        (size_t)S_ * HH_, (size_t)S_ * HH_, (size_t)S_ * S_);

    // 3. softmax (in place) with key mask
    softmax_kernel<<<B_ * S_, 256>>>(ap, am);

    // 4. ctx = p @ x   (batched NN, 16 x [2048,2048]x[2048,768])
    sgemm_kernel<false><<<dim3(6, 16, B_), 256>>>(ap, x, ctxp, nullptr, S_, H_, S_, 1.f,
        (size_t)S_ * S_, (size_t)S_ * H_, (size_t)S_ * H_);

    // 5. h_pre = ctx @ W1 + b1   ([32768,768] @ [768,384])
    sgemm_kernel<false><<<dim3(3, 256, 1), 256>>>(ctxp, W1, hp, b1, B_ * S_, HH_, H_, 1.f, 0, 0, 0);

    // 6. token_scores = mask(relu(LN(h_pre)) @ W2 + b2)
    lnscore_kernel<<<B_ * S_, 128>>>(hp, g1, be1, W2, b2, am, tp);

    // 7. span argmax + mean pooling over selected span
    span_pool_kernel<<<B_, 256>>>(tp, am, x, pp);

    // 8. concept head + classifier -> logits [16,4]
    head_kernel<<<B_, 384>>>(pp, x, Wc1, bc1, g2, be2, Wc2, bc2, Mint, Wcls, bcls, out);
}

// round 4
// speedup vs baseline: 2.6226x; 2.6226x over previous
#include <cuda_runtime.h>
#include <cuda_bf16.h>
#include <math.h>
#include <stdint.h>

// Problem constants
#define B_  16
#define S_  2048
#define H_  768
#define HH_ 384
#define C_  64
#define L_  4

// ---------------- scratch (static __device__ arrays; no allocation) ----------
__device__ __nv_bfloat16 g_xhi [25165824], g_xlo [25165824];   // x split       [B*S,H]
__device__ __nv_bfloat16 g_xThi[25165824], g_xTlo[25165824];   // x^T split     [B,H,S]
__device__ __nv_bfloat16 g_qhi [12582912], g_qlo [12582912];   // q split       [B*S,HH]
__device__ __nv_bfloat16 g_khi [12582912], g_klo [12582912];   // k split       [B*S,HH]
__device__ float         g_attn[67108864];                     // attn logits   [B,S,S]
__device__ __nv_bfloat16 g_phi [67108864], g_plo [67108864];   // softmax split [B,S,S]
__device__ __nv_bfloat16 g_chi [25165824], g_clo [25165824];   // ctx split     [B*S,H]
__device__ float         g_hpre[12582912];                     // h_pre fp32    [B*S,HH]
__device__ float         g_ts  [32768];
__device__ float         g_pool[12288];
__device__ __nv_bfloat16 g_WqThi[294912], g_WqTlo[294912];     // Wq^T split [HH,H]
__device__ __nv_bfloat16 g_WkThi[294912], g_WkTlo[294912];
__device__ __nv_bfloat16 g_W1Thi[294912], g_W1Tlo[294912];

// ============================ PTX helpers ====================================
__device__ __forceinline__ uint32_t smem_u32(const void* p) {
    return (uint32_t)__cvta_generic_to_shared(p);
}

__device__ __forceinline__ void cp16(uint32_t dst, const void* src) {
    asm volatile("cp.async.cg.shared.global [%0], [%1], 16;" :: "r"(dst), "l"(src));
}
#define CP_COMMIT() asm volatile("cp.async.commit_group;" ::: "memory")
#define CP_WAIT1()  asm volatile("cp.async.wait_group 1;" ::: "memory")
#define CP_WAIT0()  asm volatile("cp.async.wait_group 0;" ::: "memory")

#define LDSM4(r, addr) \
    asm volatile("ldmatrix.sync.aligned.m8n8.x4.shared.b16 {%0,%1,%2,%3}, [%4];" \
        : "=r"((r)[0]), "=r"((r)[1]), "=r"((r)[2]), "=r"((r)[3]) : "r"(addr))

#define MMA16816(d, a, b) \
    asm volatile("mma.sync.aligned.m16n8k16.row.col.f32.bf16.bf16.f32 " \
        "{%0,%1,%2,%3}, {%4,%5,%6,%7}, {%8,%9}, {%0,%1,%2,%3};" \
        : "+f"((d)[0]), "+f"((d)[1]), "+f"((d)[2]), "+f"((d)[3]) \
        : "r"((a)[0]), "r"((a)[1]), "r"((a)[2]), "r"((a)[3]), \
          "r"((b)[0]), "r"((b)[1]))

// SMEM tile geometry: 128 rows x 32 bf16 (64B data) padded to 80B/row
#define LDSROW 80
#define TILEB  (128 * LDSROW)         // 10240 B
#define BUFB   (4 * TILEB)            // Ahi, Alo, Bhi, Blo = 40960 B
#define GEMM_SMEM (2 * BUFB)          // double buffered = 81920 B

// =============== split conversions ==========================================
__device__ __forceinline__ void split_one(float v, __nv_bfloat16& hi, __nv_bfloat16& lo) {
    hi = __float2bfloat16(v);
    lo = __float2bfloat16(v - __bfloat162float(hi));
}

__global__ __launch_bounds__(256)
void split_f32_kernel(const float* __restrict__ src, __nv_bfloat16* __restrict__ hi,
                      __nv_bfloat16* __restrict__ lo)
{
    const size_t i = ((size_t)blockIdx.x * 256 + threadIdx.x) * 4;
    float4 v = *(const float4*)(src + i);
    __nv_bfloat16 h0, l0, h1, l1, h2, l2, h3, l3;
    split_one(v.x, h0, l0); split_one(v.y, h1, l1);
    split_one(v.z, h2, l2); split_one(v.w, h3, l3);
    hi[i] = h0; hi[i+1] = h1; hi[i+2] = h2; hi[i+3] = h3;
    lo[i] = l0; lo[i+1] = l1; lo[i+2] = l2; lo[i+3] = l3;
}

// in [R, C] -> out [C, R] with bf16 split; per-z offset = z*R*C
__global__ __launch_bounds__(256)
void transpose_split_kernel(const float* __restrict__ in, __nv_bfloat16* __restrict__ ohi,
                            __nv_bfloat16* __restrict__ olo, int R, int Cc)
{
    __shared__ float tile[32][33];
    const size_t zoff = (size_t)blockIdx.z * R * Cc;
    in += zoff; ohi += zoff; olo += zoff;
    const int r0 = blockIdx.x * 32, c0 = blockIdx.y * 32;
    const int tx = threadIdx.x, ty = threadIdx.y;   // block (32,8)
#pragma unroll
    for (int j = 0; j < 32; j += 8)
        tile[ty + j][tx] = in[(size_t)(r0 + ty + j) * Cc + c0 + tx];
    __syncthreads();
#pragma unroll
    for (int j = 0; j < 32; j += 8) {
        float v = tile[tx][ty + j];
        __nv_bfloat16 h, l; split_one(v, h, l);
        size_t o = (size_t)(c0 + ty + j) * R + r0 + tx;
        ohi[o] = h; olo[o] = l;
    }
}

// =============== warp-MMA bf16x3 GEMM =======================================
// C[M,N] = alpha * A @ B^T (+bias). A:[M,K] K-major split, B:[N,K] K-major split.
// CTA tile 128x128, 8 warps of 64x32, K chunk 32, double-buffered cp.async.
// Requires M%128==0, N%128==0, K%32==0.
template<bool OUT_SPLIT>
__global__ __launch_bounds__(256)
void gemm_bf16x3(const __nv_bfloat16* __restrict__ Ahi, const __nv_bfloat16* __restrict__ Alo,
                 const __nv_bfloat16* __restrict__ Bhi, const __nv_bfloat16* __restrict__ Blo,
                 float* __restrict__ Cf, __nv_bfloat16* __restrict__ Chi,
                 __nv_bfloat16* __restrict__ Clo, const float* __restrict__ bias,
                 int N, int K, float alpha, size_t sA, size_t sB, size_t sC)
{
    extern __shared__ char smem[];
    const uint32_t sbase = smem_u32(smem);
    const int t = threadIdx.x;
    const int mBase = blockIdx.y * 128, nBase = blockIdx.x * 128;
    Ahi += (size_t)blockIdx.z * sA; Alo += (size_t)blockIdx.z * sA;
    Bhi += (size_t)blockIdx.z * sB; Blo += (size_t)blockIdx.z * sB;

    const int lane = t & 31, w = t >> 5;
    const int mW = (w & 1) * 64, nW = (w >> 1) * 32;
    // ldmatrix lane address offsets (within a 16-row x 32B k16 window)
    const uint32_t aOff = (uint32_t)(lane & 15) * LDSROW + (uint32_t)(lane >> 4) * 16;
    const uint32_t bOff = (uint32_t)(((lane >> 4) << 3) + (lane & 7)) * LDSROW
                        + (uint32_t)((lane >> 3) & 1) * 16;

    // loader mapping: 512 x 16B chunks per tile, 2 per thread
    const int lrow0 = t >> 2,           lseg0 = t & 3;          // chunk t
    const int lrow1 = (t + 256) >> 2,   lseg1 = t & 3;          // chunk t+256

    float acc[4][4][4];
#pragma unroll
    for (int i = 0; i < 4; i++)
#pragma unroll
        for (int j = 0; j < 4; j++)
#pragma unroll
            for (int r = 0; r < 4; r++) acc[i][j][r] = 0.f;

    const __nv_bfloat16* srcs[4] = { Ahi, Alo, Bhi, Blo };

    auto load_chunk = [&](int c, int buf) {
        const int kt = c * 32;
        const uint32_t bb = sbase + (uint32_t)buf * BUFB;
#pragma unroll
        for (int tl = 0; tl < 4; tl++) {
            const int rb = (tl < 2) ? mBase : nBase;
            const __nv_bfloat16* sp = srcs[tl];
            cp16(bb + tl * TILEB + lrow0 * LDSROW + lseg0 * 16,
                 sp + (size_t)(rb + lrow0) * K + kt + lseg0 * 8);
            cp16(bb + tl * TILEB + lrow1 * LDSROW + lseg1 * 16,
                 sp + (size_t)(rb + lrow1) * K + kt + lseg1 * 8);
        }
    };

    const int NC = K >> 5;

    load_chunk(0, 0);
    CP_COMMIT();

    for (int c = 0; c < NC; c++) {
        if (c + 1 < NC) {
            load_chunk(c + 1, (c + 1) & 1);
            CP_COMMIT();
            CP_WAIT1();
        } else {
            CP_WAIT0();
        }
        __syncthreads();

        const uint32_t bb  = sbase + (uint32_t)(c & 1) * BUFB;
        const uint32_t bAh = bb + (uint32_t)mW * LDSROW;
        const uint32_t bAl = bAh + TILEB;
        const uint32_t bBh = bb + 2 * TILEB + (uint32_t)nW * LDSROW;
        const uint32_t bBl = bBh + TILEB;

#pragma unroll
        for (int ks = 0; ks < 2; ks++) {
            const uint32_t ko = (uint32_t)ks * 32;
            uint32_t aH[4][4], aL[4][4], bH[4][2], bL[4][2];
#pragma unroll
            for (int i = 0; i < 4; i++)
                LDSM4(aH[i], bAh + (uint32_t)(i * 16) * LDSROW + ko + aOff);
#pragma unroll
            for (int i = 0; i < 4; i++)
                LDSM4(aL[i], bAl + (uint32_t)(i * 16) * LDSROW + ko + aOff);
#pragma unroll
            for (int j = 0; j < 2; j++) {
                uint32_t r[4];
                LDSM4(r, bBh + (uint32_t)(j * 16) * LDSROW + ko + bOff);
                bH[2*j][0] = r[0]; bH[2*j][1] = r[1];
                bH[2*j+1][0] = r[2]; bH[2*j+1][1] = r[3];
            }
#pragma unroll
            for (int j = 0; j < 2; j++) {
                uint32_t r[4];
                LDSM4(r, bBl + (uint32_t)(j * 16) * LDSROW + ko + bOff);
                bL[2*j][0] = r[0]; bL[2*j][1] = r[1];
                bL[2*j+1][0] = r[2]; bL[2*j+1][1] = r[3];
            }
#pragma unroll
            for (int i = 0; i < 4; i++)
#pragma unroll
                for (int j = 0; j < 4; j++) {
                    MMA16816(acc[i][j], aH[i], bH[j]);
                    MMA16816(acc[i][j], aH[i], bL[j]);
                    MMA16816(acc[i][j], aL[i], bH[j]);
                }
        }
        __syncthreads();
    }

    // ---------------- epilogue: direct coalesced writes ----------------------
    const int g = lane >> 2, tg2 = (lane & 3) * 2;
    if (OUT_SPLIT) {
        __nv_bfloat16* ohi = Chi + (size_t)blockIdx.z * sC;
        __nv_bfloat16* olo = Clo + (size_t)blockIdx.z * sC;
#pragma unroll
        for (int i = 0; i < 4; i++) {
            const int r0 = mBase + mW + i * 16 + g, r1 = r0 + 8;
#pragma unroll
            for (int j = 0; j < 4; j++) {
                const int c0 = nBase + nW + j * 8 + tg2;
                float b0 = 0.f, b1 = 0.f;
                if (bias) { b0 = bias[c0]; b1 = bias[c0 + 1]; }
                float v00 = acc[i][j][0] * alpha + b0, v01 = acc[i][j][1] * alpha + b1;
                float v10 = acc[i][j][2] * alpha + b0, v11 = acc[i][j][3] * alpha + b1;
                __nv_bfloat16 h0, l0, h1, l1;
                split_one(v00, h0, l0); split_one(v01, h1, l1);
                *(__nv_bfloat162*)(ohi + (size_t)r0 * N + c0) = __nv_bfloat162(h0, h1);
                *(__nv_bfloat162*)(olo + (size_t)r0 * N + c0) = __nv_bfloat162(l0, l1);
                split_one(v10, h0, l0); split_one(v11, h1, l1);
                *(__nv_bfloat162*)(ohi + (size_t)r1 * N + c0) = __nv_bfloat162(h0, h1);
                *(__nv_bfloat162*)(olo + (size_t)r1 * N + c0) = __nv_bfloat162(l0, l1);
            }
        }
    } else {
        float* oc = Cf + (size_t)blockIdx.z * sC;
#pragma unroll
        for (int i = 0; i < 4; i++) {
            const int r0 = mBase + mW + i * 16 + g, r1 = r0 + 8;
#pragma unroll
            for (int j = 0; j < 4; j++) {
                const int c0 = nBase + nW + j * 8 + tg2;
                float b0 = 0.f, b1 = 0.f;
                if (bias) { b0 = bias[c0]; b1 = bias[c0 + 1]; }
                float2 va = make_float2(acc[i][j][0] * alpha + b0, acc[i][j][1] * alpha + b1);
                float2 vb = make_float2(acc[i][j][2] * alpha + b0, acc[i][j][3] * alpha + b1);
                *(float2*)(oc + (size_t)r0 * N + c0) = va;
                *(float2*)(oc + (size_t)r1 * N + c0) = vb;
            }
        }
    }
}

// ---------------- softmax over last dim (2048) -> split bf16 p ---------------
__global__ __launch_bounds__(256)
void softmax_split_kernel(const float* __restrict__ attn, const int* __restrict__ am,
                          __nv_bfloat16* __restrict__ phi, __nv_bfloat16* __restrict__ plo)
{
    __shared__ float red[256];
    const size_t row = blockIdx.x;
    const int b = (int)(row >> 11);
    const float* a = attn + row * (size_t)S_;
    const int* amb = am + (size_t)b * S_;
    const int t = threadIdx.x;

    float vals[8];
    float mx = -3.0e38f;
#pragma unroll
    for (int i = 0; i < 8; i++) {
        int idx = t + i * 256;
        float v = a[idx];
        if (amb[idx] == 0) v = -10000.f;
        vals[i] = v;
        mx = fmaxf(mx, v);
    }
    red[t] = mx; __syncthreads();
    for (int o = 128; o > 0; o >>= 1) { if (t < o) red[t] = fmaxf(red[t], red[t + o]); __syncthreads(); }
    const float rmax = red[0];
    __syncthreads();

    float se = 0.f;
#pragma unroll
    for (int i = 0; i < 8; i++) { float e = __expf(vals[i] - rmax); vals[i] = e; se += e; }
    red[t] = se; __syncthreads();
    for (int o = 128; o > 0; o >>= 1) { if (t < o) red[t] += red[t + o]; __syncthreads(); }
    const float inv = 1.f / red[0];
#pragma unroll
    for (int i = 0; i < 8; i++) {
        float v = vals[i] * inv;
        __nv_bfloat16 h, l; split_one(v, h, l);
        size_t o = row * (size_t)S_ + t + i * 256;
        phi[o] = h; plo[o] = l;
    }
}

// ---------------- per-row LayerNorm + ReLU + dot(W2) -> token score ----------
__global__ __launch_bounds__(128)
void lnscore_kernel(const float* __restrict__ hpre, const float* __restrict__ g1,
                    const float* __restrict__ be1, const float* __restrict__ W2,
                    const float* __restrict__ b2, const int* __restrict__ am,
                    float* __restrict__ ts)
{
    __shared__ float red[128];
    const int row = blockIdx.x, t = threadIdx.x;
    const float* hr = hpre + (size_t)row * HH_;
    const float v0 = hr[t], v1 = hr[t + 128], v2 = hr[t + 256];

    red[t] = v0 + v1 + v2; __syncthreads();
    for (int o = 64; o > 0; o >>= 1) { if (t < o) red[t] += red[t + o]; __syncthreads(); }
    const float mean = red[0] * (1.f / HH_);
    __syncthreads();

    const float d0 = v0 - mean, d1 = v1 - mean, d2 = v2 - mean;
    red[t] = d0 * d0 + d1 * d1 + d2 * d2; __syncthreads();
    for (int o = 64; o > 0; o >>= 1) { if (t < o) red[t] += red[t + o]; __syncthreads(); }
    const float inv = rsqrtf(red[0] * (1.f / HH_) + 1e-5f);
    __syncthreads();

    float sp = fmaxf(d0 * inv * g1[t]       + be1[t],       0.f) * W2[t]
             + fmaxf(d1 * inv * g1[t + 128] + be1[t + 128], 0.f) * W2[t + 128]
             + fmaxf(d2 * inv * g1[t + 256] + be1[t + 256], 0.f) * W2[t + 256];
    red[t] = sp; __syncthreads();
    for (int o = 64; o > 0; o >>= 1) { if (t < o) red[t] += red[t + o]; __syncthreads(); }
    if (t == 0) {
        float v = red[0] + b2[0];
        if (am[row] == 0) v = -10000.f;
        ts[row] = v;
    }
}

// ---------------- span search + mean pooling ---------------------------------
__global__ __launch_bounds__(256)
void span_pool_kernel(const float* __restrict__ ts, const int* __restrict__ am,
                      const float* __restrict__ x, float* __restrict__ pooled)
{
    __shared__ float sc[2048];
    __shared__ float cum[2049];
    __shared__ float part[256];
    __shared__ int   ired[256];
    __shared__ float bvs[256];
    __shared__ int   bis[256];
    __shared__ int   s_start, s_len;

    const int b = blockIdx.x, t = threadIdx.x;

    int vc = 0;
    for (int i = t; i < S_; i += 256) {
        sc[i] = ts[(size_t)b * S_ + i];
        vc += am[(size_t)b * S_ + i];
    }
    ired[t] = vc; __syncthreads();
    for (int o = 128; o > 0; o >>= 1) { if (t < o) ired[t] += ired[t + o]; __syncthreads(); }
    const int vl = ired[0];

    float ps = 0.f;
    for (int i = 0; i < 8; i++) ps += sc[t * 8 + i];
    part[t] = ps; __syncthreads();
    if (t == 0) {
        float run = 0.f;
        for (int i = 0; i < 256; i++) { float v = part[i]; part[i] = run; run += v; }
        cum[2048] = run;
    }
    __syncthreads();
    float run = part[t];
    for (int i = 0; i < 8; i++) { int idx = t * 8 + i; cum[idx] = run; run += sc[idx]; }
    __syncthreads();

    float bestV = -3.0e38f; int bestI = 0x7fffffff;
    for (int flat = t; flat < 18 * S_; flat += 256) {
        const int li = flat >> 11, start = flat & 2047;
        const int L = 3 + li, end = start + L;
        const int endc = end > S_ ? S_ : end;
        const float fL = (float)L;
        float avg = (cum[endc] - cum[start]) / fL + 0.01f * fL / 20.0f;
        if (end > vl) avg = -1e30f;
        if (avg > bestV) { bestV = avg; bestI = flat; }
    }
    bvs[t] = bestV; bis[t] = bestI; __syncthreads();
    for (int o = 128; o > 0; o >>= 1) {
        if (t < o) {
            if (bvs[t + o] > bvs[t] || (bvs[t + o] == bvs[t] && bis[t + o] < bis[t])) {
                bvs[t] = bvs[t + o]; bis[t] = bis[t + o];
            }
        }
        __syncthreads();
    }
    if (t == 0) {
        const int fi = bis[0];
        int start = fi & 2047, L = 3 + (fi >> 11);
        if (vl <= 3) { start = 0; L = vl; }
        s_start = start; s_len = L;
    }
    __syncthreads();

    const int start = s_start, L = s_len;
    const float inv = 1.0f / ((float)L + 1e-6f);
    for (int h = t; h < H_; h += 256) {
        float s = 0.f;
        for (int r = 0; r < L; r++) s += x[((size_t)b * S_ + start + r) * H_ + h];
        pooled[b * H_ + h] = s * inv;
    }
}

// ---------------- classification head ----------------------------------------
__global__ __launch_bounds__(384)
void head_kernel(const float* __restrict__ pooled, const float* __restrict__ x,
                 const float* __restrict__ Wc1, const float* __restrict__ bc1,
                 const float* __restrict__ g2, const float* __restrict__ be2,
                 const float* __restrict__ Wc2, const float* __restrict__ bc2,
                 const float* __restrict__ Mint,
                 const float* __restrict__ Wcls, const float* __restrict__ bcls,
                 float* __restrict__ out)
{
    __shared__ float pl[768];
    __shared__ float hc[384];
    __shared__ float cs[64];
    __shared__ float cp[64];
    __shared__ float red[512];
    const int b = blockIdx.x, t = threadIdx.x;

    for (int i = t; i < H_; i += 384) pl[i] = pooled[b * H_ + i];
    if (t < 128) red[384 + t] = 0.f;
    __syncthreads();

    float acc = bc1[t];
    for (int k = 0; k < H_; k++) acc += pl[k] * Wc1[(size_t)k * HH_ + t];

    red[t] = acc; __syncthreads();
    for (int o = 256; o > 0; o >>= 1) { if (t < o) red[t] += red[t + o]; __syncthreads(); }
    const float mean = red[0] * (1.f / HH_);
    __syncthreads();
    const float d = acc - mean;
    red[t] = d * d; __syncthreads();
    for (int o = 256; o > 0; o >>= 1) { if (t < o) red[t] += red[t + o]; __syncthreads(); }
    const float var = red[0] * (1.f / HH_);
    const float yn = d * rsqrtf(var + 1e-5f) * g2[t] + be2[t];
    hc[t] = fmaxf(yn, 0.f);
    __syncthreads();

    if (t < C_) {
        float c = bc2[t];
        for (int k = 0; k < HH_; k++) c += hc[k] * Wc2[(size_t)k * C_ + t];
        cs[t] = c;
    }
    __syncthreads();
    if (t < C_) {
        float add = cs[t];
        for (int i = 0; i < C_; i++) {
            const float m = 0.5f * (Mint[i * C_ + t] + Mint[t * C_ + i]);
            const float sg = 1.f / (1.f + expf(-m));
            add += cs[i] * sg;
        }
        cp[t] = 1.f / (1.f + expf(-add));
    }
    __syncthreads();
    if (t < L_) {
        float lg = bcls[t];
        for (int c = 0; c < C_; c++) lg += cp[c] * Wcls[c * L_ + t];
        const float* xr = x + (size_t)b * S_ * H_;
        for (int h = 0; h < H_; h++) lg += xr[h] * Wcls[(C_ + h) * L_ + t];
        out[b * L_ + t] = lg;
    }
}

// ---------------------------- launcher ---------------------------------------
extern "C" void kernel_launch(void* const* d_in, const int* in_sizes, int n_in,
                              void* d_out, int out_size)
{
    const float* x    = (const float*)d_in[0];
    const int*   am   = (const int*)  d_in[1];
    const float* Wq   = (const float*)d_in[2];
    const float* bq   = (const float*)d_in[3];
    const float* Wk   = (const float*)d_in[4];
    const float* bk   = (const float*)d_in[5];
    const float* W1   = (const float*)d_in[6];
    const float* b1   = (const float*)d_in[7];
    const float* g1   = (const float*)d_in[8];
    const float* be1  = (const float*)d_in[9];
    const float* W2   = (const float*)d_in[10];
    const float* b2   = (const float*)d_in[11];
    const float* Wc1  = (const float*)d_in[12];
    const float* bc1  = (const float*)d_in[13];
    const float* g2   = (const float*)d_in[14];
    const float* be2  = (const float*)d_in[15];
    const float* Wc2  = (const float*)d_in[16];
    const float* bc2  = (const float*)d_in[17];
    const float* Mint = (const float*)d_in[18];
    const float* Wcls = (const float*)d_in[19];
    const float* bcls = (const float*)d_in[20];
    float* out = (float*)d_out;

    __nv_bfloat16 *xhi, *xlo, *xThi, *xTlo, *qhi, *qlo, *khi, *klo;
    __nv_bfloat16 *phi, *plo, *chi, *clo;
    __nv_bfloat16 *WqThi, *WqTlo, *WkThi, *WkTlo, *W1Thi, *W1Tlo;
    float *ap, *hp, *tp, *pp;
    cudaGetSymbolAddress((void**)&xhi,  g_xhi);  cudaGetSymbolAddress((void**)&xlo,  g_xlo);
    cudaGetSymbolAddress((void**)&xThi, g_xThi); cudaGetSymbolAddress((void**)&xTlo, g_xTlo);
    cudaGetSymbolAddress((void**)&qhi,  g_qhi);  cudaGetSymbolAddress((void**)&qlo,  g_qlo);
    cudaGetSymbolAddress((void**)&khi,  g_khi);  cudaGetSymbolAddress((void**)&klo,  g_klo);
    cudaGetSymbolAddress((void**)&phi,  g_phi);  cudaGetSymbolAddress((void**)&plo,  g_plo);
    cudaGetSymbolAddress((void**)&chi,  g_chi);  cudaGetSymbolAddress((void**)&clo,  g_clo);
    cudaGetSymbolAddress((void**)&WqThi, g_WqThi); cudaGetSymbolAddress((void**)&WqTlo, g_WqTlo);
    cudaGetSymbolAddress((void**)&WkThi, g_WkThi); cudaGetSymbolAddress((void**)&WkTlo, g_WkTlo);
    cudaGetSymbolAddress((void**)&W1Thi, g_W1Thi); cudaGetSymbolAddress((void**)&W1Tlo, g_W1Tlo);
    cudaGetSymbolAddress((void**)&ap, g_attn);
    cudaGetSymbolAddress((void**)&hp, g_hpre);
    cudaGetSymbolAddress((void**)&tp, g_ts);
    cudaGetSymbolAddress((void**)&pp, g_pool);

    cudaFuncSetAttribute(gemm_bf16x3<false>, cudaFuncAttributeMaxDynamicSharedMemorySize, GEMM_SMEM);
    cudaFuncSetAttribute(gemm_bf16x3<true>,  cudaFuncAttributeMaxDynamicSharedMemorySize, GEMM_SMEM);

    // 0. weight transposes + splits: W [768,384] -> W^T [384,768] hi/lo
    transpose_split_kernel<<<dim3(24, 12, 1), dim3(32, 8)>>>(Wq, WqThi, WqTlo, H_, HH_);
    transpose_split_kernel<<<dim3(24, 12, 1), dim3(32, 8)>>>(Wk, WkThi, WkTlo, H_, HH_);
    transpose_split_kernel<<<dim3(24, 12, 1), dim3(32, 8)>>>(W1, W1Thi, W1Tlo, H_, HH_);

    // 1. x split (A of projections) + x^T split per batch (B of ctx)
    split_f32_kernel<<<25165824 / 1024, 256>>>(x, xhi, xlo);
    transpose_split_kernel<<<dim3(64, 24, 16), dim3(32, 8)>>>(x, xThi, xTlo, S_, H_);

    // 2. q/k projections: [32768,768] @ W^T[384,768] -> split bf16 + bias
    gemm_bf16x3<true><<<dim3(3, 256, 1), 256, GEMM_SMEM>>>(
        xhi, xlo, WqThi, WqTlo, nullptr, qhi, qlo, bq, HH_, H_, 1.f, 0, 0, 0);
    gemm_bf16x3<true><<<dim3(3, 256, 1), 256, GEMM_SMEM>>>(
        xhi, xlo, WkThi, WkTlo, nullptr, khi, klo, bk, HH_, H_, 1.f, 0, 0, 0);

    // 3. attn = q @ k^T / sqrt(HH): per batch [2048,384] x [2048,384]^T -> fp32
    const float alpha = 1.0f / sqrtf((float)HH_);
    gemm_bf16x3<false><<<dim3(16, 16, B_), 256, GEMM_SMEM>>>(
        qhi, qlo, khi, klo, ap, nullptr, nullptr, nullptr, S_, HH_, alpha,
        (size_t)S_ * HH_, (size_t)S_ * HH_, (size_t)S_ * S_);

    // 4. softmax -> split bf16 p
    softmax_split_kernel<<<B_ * S_, 256>>>(ap, am, phi, plo);

    // 5. ctx = p @ x: per batch [2048,2048] x xT[768,2048] -> split bf16
    gemm_bf16x3<true><<<dim3(6, 16, B_), 256, GEMM_SMEM>>>(
        phi, plo, xThi, xTlo, nullptr, chi, clo, nullptr, H_, S_, 1.f,
        (size_t)S_ * S_, (size_t)H_ * S_, (size_t)S_ * H_);

    // 6. h_pre = ctx @ W1 + b1 -> fp32
    gemm_bf16x3<false><<<dim3(3, 256, 1), 256, GEMM_SMEM>>>(
        chi, clo, W1Thi, W1Tlo, hp, nullptr, nullptr, b1, HH_, H_, 1.f, 0, 0, 0);

    // 7-9. scores, span+pool, head
    lnscore_kernel<<<B_ * S_, 128>>>(hp, g1, be1, W2, b2, am, tp);
    span_pool_kernel<<<B_, 256>>>(tp, am, x, pp);
    head_kernel<<<B_, 384>>>(pp, x, Wc1, bc1, g2, be2, Wc2, bc2, Mint, Wcls, bcls, out);
}

// round 5
// speedup vs baseline: 3.2670x; 1.2457x over previous
#include <cuda_runtime.h>
#include <cuda_bf16.h>
#include <math.h>
#include <stdint.h>

// Problem constants
#define B_  16
#define S_  2048
#define H_  768
#define HH_ 384
#define C_  64
#define L_  4

// ---------------- scratch (static __device__ arrays; no allocation) ----------
__device__ __nv_bfloat16 g_xhi [25165824], g_xlo [25165824];   // x split       [B*S,H]
__device__ __nv_bfloat16 g_qhi [12582912], g_qlo [12582912];   // q split       [B*S,HH]
__device__ __nv_bfloat16 g_khi [12582912], g_klo [12582912];   // k split       [B*S,HH]
__device__ float         g_attn[67108864];                     // attn logits   [B,S,S]
__device__ __nv_bfloat16 g_phi [67108864], g_plo [67108864];   // softmax split [B,S,S]
__device__ float         g_y   [12582912];                     // y=x@W1+b1     [B*S,HH]
__device__ __nv_bfloat16 g_yThi[12582912], g_yTlo[12582912];   // y^T split     [B,HH,S]
__device__ float         g_hpre[12582912];                     // h_pre fp32    [B*S,HH]
__device__ float         g_ts  [32768];
__device__ float         g_pool[12288];
__device__ __nv_bfloat16 g_WqThi[294912], g_WqTlo[294912];     // Wq^T split [HH,H]
__device__ __nv_bfloat16 g_WkThi[294912], g_WkTlo[294912];
__device__ __nv_bfloat16 g_W1Thi[294912], g_W1Tlo[294912];

// ============================ PTX helpers ====================================
__device__ __forceinline__ uint32_t smem_u32(const void* p) {
    return (uint32_t)__cvta_generic_to_shared(p);
}

__device__ __forceinline__ void cp16(uint32_t dst, const void* src) {
    asm volatile("cp.async.cg.shared.global [%0], [%1], 16;" :: "r"(dst), "l"(src));
}
#define CP_COMMIT() asm volatile("cp.async.commit_group;" ::: "memory")
#define CP_WAIT1()  asm volatile("cp.async.wait_group 1;" ::: "memory")
#define CP_WAIT0()  asm volatile("cp.async.wait_group 0;" ::: "memory")

#define LDSM4(r, addr) \
    asm volatile("ldmatrix.sync.aligned.m8n8.x4.shared.b16 {%0,%1,%2,%3}, [%4];" \
        : "=r"((r)[0]), "=r"((r)[1]), "=r"((r)[2]), "=r"((r)[3]) : "r"(addr))

#define MMA16816(d, a, b) \
    asm volatile("mma.sync.aligned.m16n8k16.row.col.f32.bf16.bf16.f32 " \
        "{%0,%1,%2,%3}, {%4,%5,%6,%7}, {%8,%9}, {%0,%1,%2,%3};" \
        : "+f"((d)[0]), "+f"((d)[1]), "+f"((d)[2]), "+f"((d)[3]) \
        : "r"((a)[0]), "r"((a)[1]), "r"((a)[2]), "r"((a)[3]), \
          "r"((b)[0]), "r"((b)[1]))

// SMEM tile geometry: 128 rows x 32 bf16 (64B data) padded to 80B/row
#define LDSROW 80
#define TILEB  (128 * LDSROW)         // 10240 B
#define BUFB   (4 * TILEB)            // Ahi, Alo, Bhi, Blo = 40960 B
#define GEMM_SMEM (2 * BUFB)          // double buffered = 81920 B

// =============== split conversions ==========================================
__device__ __forceinline__ void split_one(float v, __nv_bfloat16& hi, __nv_bfloat16& lo) {
    hi = __float2bfloat16(v);
    lo = __float2bfloat16(v - __bfloat162float(hi));
}

__global__ __launch_bounds__(256)
void split_f32_kernel(const float* __restrict__ src, __nv_bfloat16* __restrict__ hi,
                      __nv_bfloat16* __restrict__ lo)
{
    const size_t i = ((size_t)blockIdx.x * 256 + threadIdx.x) * 4;
    float4 v = *(const float4*)(src + i);
    __nv_bfloat16 h[4], l[4];
    split_one(v.x, h[0], l[0]); split_one(v.y, h[1], l[1]);
    split_one(v.z, h[2], l[2]); split_one(v.w, h[3], l[3]);
    *(uint2*)(hi + i) = *(const uint2*)h;
    *(uint2*)(lo + i) = *(const uint2*)l;
}

// in [R, C] -> out [C, R] with bf16 split; per-z offset = z*R*C
__global__ __launch_bounds__(256)
void transpose_split_kernel(const float* __restrict__ in, __nv_bfloat16* __restrict__ ohi,
                            __nv_bfloat16* __restrict__ olo, int R, int Cc)
{
    __shared__ float tile[32][33];
    const size_t zoff = (size_t)blockIdx.z * R * Cc;
    in += zoff; ohi += zoff; olo += zoff;
    const int r0 = blockIdx.x * 32, c0 = blockIdx.y * 32;
    const int tx = threadIdx.x, ty = threadIdx.y;   // block (32,8)
#pragma unroll
    for (int j = 0; j < 32; j += 8)
        tile[ty + j][tx] = in[(size_t)(r0 + ty + j) * Cc + c0 + tx];
    __syncthreads();
    const int t = ty * 32 + tx;     // 0..255
#pragma unroll
    for (int pidx = t; pidx < 512; pidx += 256) {
        const int oc = pidx >> 4;            // output row (= input col) 0..31
        const int pr = (pidx & 15) * 2;      // input row pair
        __nv_bfloat16 h[2], l[2];
        split_one(tile[pr][oc],     h[0], l[0]);
        split_one(tile[pr + 1][oc], h[1], l[1]);
        size_t o = (size_t)(c0 + oc) * R + r0 + pr;
        *(uint32_t*)(ohi + o) = *(const uint32_t*)h;
        *(uint32_t*)(olo + o) = *(const uint32_t*)l;
    }
}

// =============== warp-MMA bf16x3 GEMM =======================================
// C[M,N] = alpha * A @ B^T (+bias). A:[M,K] K-major split, B:[N,K] K-major split.
// CTA tile 128x128, 8 warps of 64x32, K chunk 32, double-buffered cp.async.
// Requires M%128==0, N%128==0, K%32==0.
template<bool OUT_SPLIT>
__global__ __launch_bounds__(256)
void gemm_bf16x3(const __nv_bfloat16* __restrict__ Ahi, const __nv_bfloat16* __restrict__ Alo,
                 const __nv_bfloat16* __restrict__ Bhi, const __nv_bfloat16* __restrict__ Blo,
                 float* __restrict__ Cf, __nv_bfloat16* __restrict__ Chi,
                 __nv_bfloat16* __restrict__ Clo, const float* __restrict__ bias,
                 int N, int K, float alpha, size_t sA, size_t sB, size_t sC)
{
    extern __shared__ char smem[];
    const uint32_t sbase = smem_u32(smem);
    const int t = threadIdx.x;
    const int mBase = blockIdx.y * 128, nBase = blockIdx.x * 128;
    Ahi += (size_t)blockIdx.z * sA; Alo += (size_t)blockIdx.z * sA;
    Bhi += (size_t)blockIdx.z * sB; Blo += (size_t)blockIdx.z * sB;

    const int lane = t & 31, w = t >> 5;
    const int mW = (w & 1) * 64, nW = (w >> 1) * 32;
    // ldmatrix lane address offsets (within a 16-row x 32B k16 window)
    const uint32_t aOff = (uint32_t)(lane & 15) * LDSROW + (uint32_t)(lane >> 4) * 16;
    const uint32_t bOff = (uint32_t)(((lane >> 4) << 3) + (lane & 7)) * LDSROW
                        + (uint32_t)((lane >> 3) & 1) * 16;

    // loader mapping: 512 x 16B chunks per tile, 2 per thread
    const int lrow0 = t >> 2,           lseg0 = t & 3;          // chunk t
    const int lrow1 = (t + 256) >> 2,   lseg1 = t & 3;          // chunk t+256

    float acc[4][4][4];
#pragma unroll
    for (int i = 0; i < 4; i++)
#pragma unroll
        for (int j = 0; j < 4; j++)
#pragma unroll
            for (int r = 0; r < 4; r++) acc[i][j][r] = 0.f;

    const __nv_bfloat16* srcs[4] = { Ahi, Alo, Bhi, Blo };

    auto load_chunk = [&](int c, int buf) {
        const int kt = c * 32;
        const uint32_t bb = sbase + (uint32_t)buf * BUFB;
#pragma unroll
        for (int tl = 0; tl < 4; tl++) {
            const int rb = (tl < 2) ? mBase : nBase;
            const __nv_bfloat16* sp = srcs[tl];
            cp16(bb + tl * TILEB + lrow0 * LDSROW + lseg0 * 16,
                 sp + (size_t)(rb + lrow0) * K + kt + lseg0 * 8);
            cp16(bb + tl * TILEB + lrow1 * LDSROW + lseg1 * 16,
                 sp + (size_t)(rb + lrow1) * K + kt + lseg1 * 8);
        }
    };

    const int NC = K >> 5;

    load_chunk(0, 0);
    CP_COMMIT();

    for (int c = 0; c < NC; c++) {
        if (c + 1 < NC) {
            load_chunk(c + 1, (c + 1) & 1);
            CP_COMMIT();
            CP_WAIT1();
        } else {
            CP_WAIT0();
        }
        __syncthreads();

        const uint32_t bb  = sbase + (uint32_t)(c & 1) * BUFB;
        const uint32_t bAh = bb + (uint32_t)mW * LDSROW;
        const uint32_t bAl = bAh + TILEB;
        const uint32_t bBh = bb + 2 * TILEB + (uint32_t)nW * LDSROW;
        const uint32_t bBl = bBh + TILEB;

#pragma unroll
        for (int ks = 0; ks < 2; ks++) {
            const uint32_t ko = (uint32_t)ks * 32;
            uint32_t aH[4][4], aL[4][4], bH[4][2], bL[4][2];
#pragma unroll
            for (int i = 0; i < 4; i++)
                LDSM4(aH[i], bAh + (uint32_t)(i * 16) * LDSROW + ko + aOff);
#pragma unroll
            for (int i = 0; i < 4; i++)
                LDSM4(aL[i], bAl + (uint32_t)(i * 16) * LDSROW + ko + aOff);
#pragma unroll
            for (int j = 0; j < 2; j++) {
                uint32_t r[4];
                LDSM4(r, bBh + (uint32_t)(j * 16) * LDSROW + ko + bOff);
                bH[2*j][0] = r[0]; bH[2*j][1] = r[1];
                bH[2*j+1][0] = r[2]; bH[2*j+1][1] = r[3];
            }
#pragma unroll
            for (int j = 0; j < 2; j++) {
                uint32_t r[4];
                LDSM4(r, bBl + (uint32_t)(j * 16) * LDSROW + ko + bOff);
                bL[2*j][0] = r[0]; bL[2*j][1] = r[1];
                bL[2*j+1][0] = r[2]; bL[2*j+1][1] = r[3];
            }
#pragma unroll
            for (int i = 0; i < 4; i++)
#pragma unroll
                for (int j = 0; j < 4; j++) {
                    MMA16816(acc[i][j], aH[i], bH[j]);
                    MMA16816(acc[i][j], aH[i], bL[j]);
                    MMA16816(acc[i][j], aL[i], bH[j]);
                }
        }
        __syncthreads();
    }

    // ---------------- epilogue: direct coalesced writes ----------------------
    const int g = lane >> 2, tg2 = (lane & 3) * 2;
    if (OUT_SPLIT) {
        __nv_bfloat16* ohi = Chi + (size_t)blockIdx.z * sC;
        __nv_bfloat16* olo = Clo + (size_t)blockIdx.z * sC;
#pragma unroll
        for (int i = 0; i < 4; i++) {
            const int r0 = mBase + mW + i * 16 + g, r1 = r0 + 8;
#pragma unroll
            for (int j = 0; j < 4; j++) {
                const int c0 = nBase + nW + j * 8 + tg2;
                float b0 = 0.f, b1 = 0.f;
                if (bias) { b0 = bias[c0]; b1 = bias[c0 + 1]; }
                float v00 = acc[i][j][0] * alpha + b0, v01 = acc[i][j][1] * alpha + b1;
                float v10 = acc[i][j][2] * alpha + b0, v11 = acc[i][j][3] * alpha + b1;
                __nv_bfloat16 h0, l0, h1, l1;
                split_one(v00, h0, l0); split_one(v01, h1, l1);
                *(__nv_bfloat162*)(ohi + (size_t)r0 * N + c0) = __nv_bfloat162(h0, h1);
                *(__nv_bfloat162*)(olo + (size_t)r0 * N + c0) = __nv_bfloat162(l0, l1);
                split_one(v10, h0, l0); split_one(v11, h1, l1);
                *(__nv_bfloat162*)(ohi + (size_t)r1 * N + c0) = __nv_bfloat162(h0, h1);
                *(__nv_bfloat162*)(olo + (size_t)r1 * N + c0) = __nv_bfloat162(l0, l1);
            }
        }
    } else {
        float* oc = Cf + (size_t)blockIdx.z * sC;
#pragma unroll
        for (int i = 0; i < 4; i++) {
            const int r0 = mBase + mW + i * 16 + g, r1 = r0 + 8;
#pragma unroll
            for (int j = 0; j < 4; j++) {
                const int c0 = nBase + nW + j * 8 + tg2;
                float b0 = 0.f, b1 = 0.f;
                if (bias) { b0 = bias[c0]; b1 = bias[c0 + 1]; }
                float2 va = make_float2(acc[i][j][0] * alpha + b0, acc[i][j][1] * alpha + b1);
                float2 vb = make_float2(acc[i][j][2] * alpha + b0, acc[i][j][3] * alpha + b1);
                *(float2*)(oc + (size_t)r0 * N + c0) = va;
                *(float2*)(oc + (size_t)r1 * N + c0) = vb;
            }
        }
    }
}

// ---------------- softmax over last dim (2048) -> split bf16 p ---------------
__global__ __launch_bounds__(256)
void softmax_split_kernel(const float* __restrict__ attn, const int* __restrict__ am,
                          __nv_bfloat16* __restrict__ phi, __nv_bfloat16* __restrict__ plo)
{
    __shared__ float red[256];
    const size_t row = blockIdx.x;
    const int b = (int)(row >> 11);
    const float* a = attn + row * (size_t)S_;
    const int* amb = am + (size_t)b * S_;
    const int t = threadIdx.x;

    float vals[8];
    float mx = -3.0e38f;
#pragma unroll
    for (int i = 0; i < 4; i++) {
        const int idx = t * 2 + i * 512;
        float2 v = *(const float2*)(a + idx);
        if (amb[idx] == 0)     v.x = -10000.f;
        if (amb[idx + 1] == 0) v.y = -10000.f;
        vals[2*i] = v.x; vals[2*i+1] = v.y;
        mx = fmaxf(mx, fmaxf(v.x, v.y));
    }
    red[t] = mx; __syncthreads();
    for (int o = 128; o > 0; o >>= 1) { if (t < o) red[t] = fmaxf(red[t], red[t + o]); __syncthreads(); }
    const float rmax = red[0];
    __syncthreads();

    float se = 0.f;
#pragma unroll
    for (int i = 0; i < 8; i++) { float e = __expf(vals[i] - rmax); vals[i] = e; se += e; }
    red[t] = se; __syncthreads();
    for (int o = 128; o > 0; o >>= 1) { if (t < o) red[t] += red[t + o]; __syncthreads(); }
    const float inv = 1.f / red[0];
#pragma unroll
    for (int i = 0; i < 4; i++) {
        const size_t o = row * (size_t)S_ + t * 2 + i * 512;
        __nv_bfloat16 h[2], l[2];
        split_one(vals[2*i]   * inv, h[0], l[0]);
        split_one(vals[2*i+1] * inv, h[1], l[1]);
        *(uint32_t*)(phi + o) = *(const uint32_t*)h;
        *(uint32_t*)(plo + o) = *(const uint32_t*)l;
    }
}

// ---------------- per-row LayerNorm + ReLU + dot(W2) -> token score ----------
__global__ __launch_bounds__(128)
void lnscore_kernel(const float* __restrict__ hpre, const float* __restrict__ g1,
                    const float* __restrict__ be1, const float* __restrict__ W2,
                    const float* __restrict__ b2, const int* __restrict__ am,
                    float* __restrict__ ts)
{
    __shared__ float red[128];
    const int row = blockIdx.x, t = threadIdx.x;
    const float* hr = hpre + (size_t)row * HH_;
    const float v0 = hr[t], v1 = hr[t + 128], v2 = hr[t + 256];

    red[t] = v0 + v1 + v2; __syncthreads();
    for (int o = 64; o > 0; o >>= 1) { if (t < o) red[t] += red[t + o]; __syncthreads(); }
    const float mean = red[0] * (1.f / HH_);
    __syncthreads();

    const float d0 = v0 - mean, d1 = v1 - mean, d2 = v2 - mean;
    red[t] = d0 * d0 + d1 * d1 + d2 * d2; __syncthreads();
    for (int o = 64; o > 0; o >>= 1) { if (t < o) red[t] += red[t + o]; __syncthreads(); }
    const float inv = rsqrtf(red[0] * (1.f / HH_) + 1e-5f);
    __syncthreads();

    float sp = fmaxf(d0 * inv * g1[t]       + be1[t],       0.f) * W2[t]
             + fmaxf(d1 * inv * g1[t + 128] + be1[t + 128], 0.f) * W2[t + 128]
             + fmaxf(d2 * inv * g1[t + 256] + be1[t + 256], 0.f) * W2[t + 256];
    red[t] = sp; __syncthreads();
    for (int o = 64; o > 0; o >>= 1) { if (t < o) red[t] += red[t + o]; __syncthreads(); }
    if (t == 0) {
        float v = red[0] + b2[0];
        if (am[row] == 0) v = -10000.f;
        ts[row] = v;
    }
}

// ---------------- span search + mean pooling ---------------------------------
__global__ __launch_bounds__(256)
void span_pool_kernel(const float* __restrict__ ts, const int* __restrict__ am,
                      const float* __restrict__ x, float* __restrict__ pooled)
{
    __shared__ float sc[2048];
    __shared__ float cum[2049];
    __shared__ float part[256];
    __shared__ int   ired[256];
    __shared__ float bvs[256];
    __shared__ int   bis[256];
    __shared__ int   s_start, s_len;

    const int b = blockIdx.x, t = threadIdx.x;

    int vc = 0;
    for (int i = t; i < S_; i += 256) {
        sc[i] = ts[(size_t)b * S_ + i];
        vc += am[(size_t)b * S_ + i];
    }
    ired[t] = vc; __syncthreads();
    for (int o = 128; o > 0; o >>= 1) { if (t < o) ired[t] += ired[t + o]; __syncthreads(); }
    const int vl = ired[0];

    float ps = 0.f;
    for (int i = 0; i < 8; i++) ps += sc[t * 8 + i];
    part[t] = ps; __syncthreads();
    if (t == 0) {
        float run = 0.f;
        for (int i = 0; i < 256; i++) { float v = part[i]; part[i] = run; run += v; }
        cum[2048] = run;
    }
    __syncthreads();
    float run = part[t];
    for (int i = 0; i < 8; i++) { int idx = t * 8 + i; cum[idx] = run; run += sc[idx]; }
    __syncthreads();

    float bestV = -3.0e38f; int bestI = 0x7fffffff;
    for (int flat = t; flat < 18 * S_; flat += 256) {
        const int li = flat >> 11, start = flat & 2047;
        const int L = 3 + li, end = start + L;
        const int endc = end > S_ ? S_ : end;
        const float fL = (float)L;
        float avg = (cum[endc] - cum[start]) / fL + 0.01f * fL / 20.0f;
        if (end > vl) avg = -1e30f;
        if (avg > bestV) { bestV = avg; bestI = flat; }
    }
    bvs[t] = bestV; bis[t] = bestI; __syncthreads();
    for (int o = 128; o > 0; o >>= 1) {
        if (t < o) {
            if (bvs[t + o] > bvs[t] || (bvs[t + o] == bvs[t] && bis[t + o] < bis[t])) {
                bvs[t] = bvs[t + o]; bis[t] = bis[t + o];
            }
        }
        __syncthreads();
    }
    if (t == 0) {
        const int fi = bis[0];
        int start = fi & 2047, L = 3 + (fi >> 11);
        if (vl <= 3) { start = 0; L = vl; }
        s_start = start; s_len = L;
    }
    __syncthreads();

    const int start = s_start, L = s_len;
    const float inv = 1.0f / ((float)L + 1e-6f);
    for (int h = t; h < H_; h += 256) {
        float s = 0.f;
        for (int r = 0; r < L; r++) s += x[((size_t)b * S_ + start + r) * H_ + h];
        pooled[b * H_ + h] = s * inv;
    }
}

// ---------------- classification head ----------------------------------------
__global__ __launch_bounds__(384)
void head_kernel(const float* __restrict__ pooled, const float* __restrict__ x,
                 const float* __restrict__ Wc1, const float* __restrict__ bc1,
                 const float* __restrict__ g2, const float* __restrict__ be2,
                 const float* __restrict__ Wc2, const float* __restrict__ bc2,
                 const float* __restrict__ Mint,
                 const float* __restrict__ Wcls, const float* __restrict__ bcls,
                 float* __restrict__ out)
{
    __shared__ float pl[768];
    __shared__ float hc[384];
    __shared__ float cs[64];
    __shared__ float cp[64];
    __shared__ float red[512];
    const int b = blockIdx.x, t = threadIdx.x;

    for (int i = t; i < H_; i += 384) pl[i] = pooled[b * H_ + i];
    if (t < 128) red[384 + t] = 0.f;
    __syncthreads();

    float acc = bc1[t];
    for (int k = 0; k < H_; k++) acc += pl[k] * Wc1[(size_t)k * HH_ + t];

    red[t] = acc; __syncthreads();
    for (int o = 256; o > 0; o >>= 1) { if (t < o) red[t] += red[t + o]; __syncthreads(); }
    const float mean = red[0] * (1.f / HH_);
    __syncthreads();
    const float d = acc - mean;
    red[t] = d * d; __syncthreads();
    for (int o = 256; o > 0; o >>= 1) { if (t < o) red[t] += red[t + o]; __syncthreads(); }
    const float var = red[0] * (1.f / HH_);
    const float yn = d * rsqrtf(var + 1e-5f) * g2[t] + be2[t];
    hc[t] = fmaxf(yn, 0.f);
    __syncthreads();

    if (t < C_) {
        float c = bc2[t];
        for (int k = 0; k < HH_; k++) c += hc[k] * Wc2[(size_t)k * C_ + t];
        cs[t] = c;
    }
    __syncthreads();
    if (t < C_) {
        float add = cs[t];
        for (int i = 0; i < C_; i++) {
            const float m = 0.5f * (Mint[i * C_ + t] + Mint[t * C_ + i]);
            const float sg = 1.f / (1.f + expf(-m));
            add += cs[i] * sg;
        }
        cp[t] = 1.f / (1.f + expf(-add));
    }
    __syncthreads();
    if (t < L_) {
        float lg = bcls[t];
        for (int c = 0; c < C_; c++) lg += cp[c] * Wcls[c * L_ + t];
        const float* xr = x + (size_t)b * S_ * H_;
        for (int h = 0; h < H_; h++) lg += xr[h] * Wcls[(C_ + h) * L_ + t];
        out[b * L_ + t] = lg;
    }
}

// ---------------------------- launcher ---------------------------------------
extern "C" void kernel_launch(void* const* d_in, const int* in_sizes, int n_in,
                              void* d_out, int out_size)
{
    const float* x    = (const float*)d_in[0];
    const int*   am   = (const int*)  d_in[1];
    const float* Wq   = (const float*)d_in[2];
    const float* bq   = (const float*)d_in[3];
    const float* Wk   = (const float*)d_in[4];
    const float* bk   = (const float*)d_in[5];
    const float* W1   = (const float*)d_in[6];
    const float* b1   = (const float*)d_in[7];
    const float* g1   = (const float*)d_in[8];
    const float* be1  = (const float*)d_in[9];
    const float* W2   = (const float*)d_in[10];
    const float* b2   = (const float*)d_in[11];
    const float* Wc1  = (const float*)d_in[12];
    const float* bc1  = (const float*)d_in[13];
    const float* g2   = (const float*)d_in[14];
    const float* be2  = (const float*)d_in[15];
    const float* Wc2  = (const float*)d_in[16];
    const float* bc2  = (const float*)d_in[17];
    const float* Mint = (const float*)d_in[18];
    const float* Wcls = (const float*)d_in[19];
    const float* bcls = (const float*)d_in[20];
    float* out = (float*)d_out;

    __nv_bfloat16 *xhi, *xlo, *qhi, *qlo, *khi, *klo;
    __nv_bfloat16 *phi, *plo, *yThi, *yTlo;
    __nv_bfloat16 *WqThi, *WqTlo, *WkThi, *WkTlo, *W1Thi, *W1Tlo;
    float *ap, *yp, *hp, *tp, *pp;
    cudaGetSymbolAddress((void**)&xhi,  g_xhi);  cudaGetSymbolAddress((void**)&xlo,  g_xlo);
    cudaGetSymbolAddress((void**)&qhi,  g_qhi);  cudaGetSymbolAddress((void**)&qlo,  g_qlo);
    cudaGetSymbolAddress((void**)&khi,  g_khi);  cudaGetSymbolAddress((void**)&klo,  g_klo);
    cudaGetSymbolAddress((void**)&phi,  g_phi);  cudaGetSymbolAddress((void**)&plo,  g_plo);
    cudaGetSymbolAddress((void**)&yThi, g_yThi); cudaGetSymbolAddress((void**)&yTlo, g_yTlo);
    cudaGetSymbolAddress((void**)&WqThi, g_WqThi); cudaGetSymbolAddress((void**)&WqTlo, g_WqTlo);
    cudaGetSymbolAddress((void**)&WkThi, g_WkThi); cudaGetSymbolAddress((void**)&WkTlo, g_WkTlo);
    cudaGetSymbolAddress((void**)&W1Thi, g_W1Thi); cudaGetSymbolAddress((void**)&W1Tlo, g_W1Tlo);
    cudaGetSymbolAddress((void**)&ap, g_attn);
    cudaGetSymbolAddress((void**)&yp, g_y);
    cudaGetSymbolAddress((void**)&hp, g_hpre);
    cudaGetSymbolAddress((void**)&tp, g_ts);
    cudaGetSymbolAddress((void**)&pp, g_pool);

    cudaFuncSetAttribute(gemm_bf16x3<false>, cudaFuncAttributeMaxDynamicSharedMemorySize, GEMM_SMEM);
    cudaFuncSetAttribute(gemm_bf16x3<true>,  cudaFuncAttributeMaxDynamicSharedMemorySize, GEMM_SMEM);

    // 0. weight transposes + splits: W [768,384] -> W^T [384,768] hi/lo
    transpose_split_kernel<<<dim3(24, 12, 1), dim3(32, 8)>>>(Wq, WqThi, WqTlo, H_, HH_);
    transpose_split_kernel<<<dim3(24, 12, 1), dim3(32, 8)>>>(Wk, WkThi, WkTlo, H_, HH_);
    transpose_split_kernel<<<dim3(24, 12, 1), dim3(32, 8)>>>(W1, W1Thi, W1Tlo, H_, HH_);

    // 1. x split (A operand of the three projections)
    split_f32_kernel<<<25165824 / 1024, 256>>>(x, xhi, xlo);

    // 2. q/k projections -> split bf16 + bias;  y = x@W1 + b1 -> fp32
    gemm_bf16x3<true><<<dim3(3, 256, 1), 256, GEMM_SMEM>>>(
        xhi, xlo, WqThi, WqTlo, nullptr, qhi, qlo, bq, HH_, H_, 1.f, 0, 0, 0);
    gemm_bf16x3<true><<<dim3(3, 256, 1), 256, GEMM_SMEM>>>(
        xhi, xlo, WkThi, WkTlo, nullptr, khi, klo, bk, HH_, H_, 1.f, 0, 0, 0);
    gemm_bf16x3<false><<<dim3(3, 256, 1), 256, GEMM_SMEM>>>(
        xhi, xlo, W1Thi, W1Tlo, yp, nullptr, nullptr, b1, HH_, H_, 1.f, 0, 0, 0);

    // 3. y^T split per batch: y [B,S,HH] -> yT [B,HH,S]
    transpose_split_kernel<<<dim3(64, 12, 16), dim3(32, 8)>>>(yp, yThi, yTlo, S_, HH_);

    // 4. attn = q @ k^T / sqrt(HH): per batch [2048,384] x [2048,384]^T -> fp32
    const float alpha = 1.0f / sqrtf((float)HH_);
    gemm_bf16x3<false><<<dim3(16, 16, B_), 256, GEMM_SMEM>>>(
        qhi, qlo, khi, klo, ap, nullptr, nullptr, nullptr, S_, HH_, alpha,
        (size_t)S_ * HH_, (size_t)S_ * HH_, (size_t)S_ * S_);

    // 5. softmax -> split bf16 p
    softmax_split_kernel<<<B_ * S_, 256>>>(ap, am, phi, plo);

    // 6. h_pre = p @ y  (ctx@W1 by associativity): [2048,2048] x yT[384,2048] -> fp32
    gemm_bf16x3<false><<<dim3(3, 16, B_), 256, GEMM_SMEM>>>(
        phi, plo, yThi, yTlo, hp, nullptr, nullptr, nullptr, HH_, S_, 1.f,
        (size_t)S_ * S_, (size_t)HH_ * S_, (size_t)S_ * HH_);

    // 7-9. scores, span+pool, head
    lnscore_kernel<<<B_ * S_, 128>>>(hp, g1, be1, W2, b2, am, tp);
    span_pool_kernel<<<B_, 256>>>(tp, am, x, pp);
    head_kernel<<<B_, 384>>>(pp, x, Wc1, bc1, g2, be2, Wc2, bc2, Mint, Wcls, bcls, out);
}

// round 6
// speedup vs baseline: 3.8298x; 1.1723x over previous
#include <cuda_runtime.h>
#include <cuda_bf16.h>
#include <math.h>
#include <stdint.h>

// Problem constants
#define B_  16
#define S_  2048
#define H_  768
#define HH_ 384
#define C_  64
#define L_  4

// ---------------- scratch (static __device__ arrays; no allocation) ----------
__device__ __nv_bfloat16 g_xhi [25165824], g_xlo [25165824];   // x split       [B*S,H]
__device__ __nv_bfloat16 g_qhi [12582912], g_qlo [12582912];   // q split       [B*S,HH]
__device__ __nv_bfloat16 g_khi [12582912], g_klo [12582912];   // k split       [B*S,HH]
__device__ float         g_attn[67108864];                     // attn logits   [B,S,S]
__device__ __nv_bfloat16 g_phi [67108864], g_plo [67108864];   // softmax split [B,S,S]
__device__ float         g_y   [12582912];                     // y=x@W1+b1     [B*S,HH]
__device__ __nv_bfloat16 g_yThi[12582912], g_yTlo[12582912];   // y^T split     [B,HH,S]
__device__ float         g_hpre[12582912];                     // h_pre fp32    [B*S,HH]
__device__ float         g_ts  [32768];
__device__ float         g_pool[12288];
__device__ __nv_bfloat16 g_WqThi[294912];                      // Wq^T hi [HH,H]
__device__ __nv_bfloat16 g_WkThi[294912];
__device__ __nv_bfloat16 g_W1Thi[294912];

// ============================ PTX helpers ====================================
__device__ __forceinline__ uint32_t smem_u32(const void* p) {
    return (uint32_t)__cvta_generic_to_shared(p);
}

__device__ __forceinline__ void cp16(uint32_t dst, const void* src) {
    asm volatile("cp.async.cg.shared.global [%0], [%1], 16;" :: "r"(dst), "l"(src));
}
#define CP_COMMIT() asm volatile("cp.async.commit_group;" ::: "memory")
#define CP_WAIT1()  asm volatile("cp.async.wait_group 1;" ::: "memory")
#define CP_WAIT0()  asm volatile("cp.async.wait_group 0;" ::: "memory")

#define LDSM4(r, addr) \
    asm volatile("ldmatrix.sync.aligned.m8n8.x4.shared.b16 {%0,%1,%2,%3}, [%4];" \
        : "=r"((r)[0]), "=r"((r)[1]), "=r"((r)[2]), "=r"((r)[3]) : "r"(addr))

#define MMA16816(d, a, b) \
    asm volatile("mma.sync.aligned.m16n8k16.row.col.f32.bf16.bf16.f32 " \
        "{%0,%1,%2,%3}, {%4,%5,%6,%7}, {%8,%9}, {%0,%1,%2,%3};" \
        : "+f"((d)[0]), "+f"((d)[1]), "+f"((d)[2]), "+f"((d)[3]) \
        : "r"((a)[0]), "r"((a)[1]), "r"((a)[2]), "r"((a)[3]), \
          "r"((b)[0]), "r"((b)[1]))

// SMEM tile geometry: 128 rows x 32 bf16 (64B data) padded to 80B/row
#define LDSROW 80
#define TILEB  (128 * LDSROW)         // 10240 B
#define BUFB   (4 * TILEB)            // up to Ahi, Alo, Bhi, Blo = 40960 B
#define GEMM_SMEM (2 * BUFB)          // double buffered = 81920 B

// =============== split conversions ==========================================
__device__ __forceinline__ void split_one(float v, __nv_bfloat16& hi, __nv_bfloat16& lo) {
    hi = __float2bfloat16(v);
    lo = __float2bfloat16(v - __bfloat162float(hi));
}

__global__ __launch_bounds__(256)
void split_f32_kernel(const float* __restrict__ src, __nv_bfloat16* __restrict__ hi,
                      __nv_bfloat16* __restrict__ lo)
{
    const size_t i = ((size_t)blockIdx.x * 256 + threadIdx.x) * 4;
    float4 v = *(const float4*)(src + i);
    __nv_bfloat16 h[4], l[4];
    split_one(v.x, h[0], l[0]); split_one(v.y, h[1], l[1]);
    split_one(v.z, h[2], l[2]); split_one(v.w, h[3], l[3]);
    *(uint2*)(hi + i) = *(const uint2*)h;
    *(uint2*)(lo + i) = *(const uint2*)l;
}

// in [R, C] -> out [C, R] with bf16 split (optionally hi only); z offset z*R*C
template<bool WRITE_LO>
__global__ __launch_bounds__(256)
void transpose_split_kernel(const float* __restrict__ in, __nv_bfloat16* __restrict__ ohi,
                            __nv_bfloat16* __restrict__ olo, int R, int Cc)
{
    __shared__ float tile[32][33];
    const size_t zoff = (size_t)blockIdx.z * R * Cc;
    in += zoff; ohi += zoff;
    if (WRITE_LO) olo += zoff;
    const int r0 = blockIdx.x * 32, c0 = blockIdx.y * 32;
    const int tx = threadIdx.x, ty = threadIdx.y;   // block (32,8)
#pragma unroll
    for (int j = 0; j < 32; j += 8)
        tile[ty + j][tx] = in[(size_t)(r0 + ty + j) * Cc + c0 + tx];
    __syncthreads();
    const int t = ty * 32 + tx;     // 0..255
#pragma unroll
    for (int pidx = t; pidx < 512; pidx += 256) {
        const int oc = pidx >> 4;            // output row (= input col) 0..31
        const int pr = (pidx & 15) * 2;      // input row pair
        __nv_bfloat16 h[2], l[2];
        split_one(tile[pr][oc],     h[0], l[0]);
        split_one(tile[pr + 1][oc], h[1], l[1]);
        size_t o = (size_t)(c0 + oc) * R + r0 + pr;
        *(uint32_t*)(ohi + o) = *(const uint32_t*)h;
        if (WRITE_LO) *(uint32_t*)(olo + o) = *(const uint32_t*)l;
    }
}

// =============== warp-MMA bf16 split GEMM ===================================
// C[M,N] = alpha * A @ B^T (+bias). A:[M,K] K-major split, B:[N,K] K-major split.
// NTERMS==3: aH*bH + aH*bL + aL*bH.  NTERMS==2: aH*bH + aL*bH (B lo unused).
// CTA tile 128x128, 8 warps of 64x32, K chunk 32, double-buffered cp.async.
// Requires M%128==0, N%128==0, K%32==0.
template<int NTERMS, bool OUT_SPLIT>
__global__ __launch_bounds__(256)
void gemm_bf16s(const __nv_bfloat16* __restrict__ Ahi, const __nv_bfloat16* __restrict__ Alo,
                const __nv_bfloat16* __restrict__ Bhi, const __nv_bfloat16* __restrict__ Blo,
                float* __restrict__ Cf, __nv_bfloat16* __restrict__ Chi,
                __nv_bfloat16* __restrict__ Clo, const float* __restrict__ bias,
                int N, int K, float alpha, size_t sA, size_t sB, size_t sC)
{
    extern __shared__ char smem[];
    const uint32_t sbase = smem_u32(smem);
    const int t = threadIdx.x;
    const int mBase = blockIdx.y * 128, nBase = blockIdx.x * 128;
    Ahi += (size_t)blockIdx.z * sA; Alo += (size_t)blockIdx.z * sA;
    Bhi += (size_t)blockIdx.z * sB;
    if (NTERMS == 3) Blo += (size_t)blockIdx.z * sB;

    const int lane = t & 31, w = t >> 5;
    const int mW = (w & 1) * 64, nW = (w >> 1) * 32;
    // ldmatrix lane address offsets (within a 16-row x 32B k16 window)
    const uint32_t aOff = (uint32_t)(lane & 15) * LDSROW + (uint32_t)(lane >> 4) * 16;
    const uint32_t bOff = (uint32_t)(((lane >> 4) << 3) + (lane & 7)) * LDSROW
                        + (uint32_t)((lane >> 3) & 1) * 16;

    // loader mapping: 512 x 16B chunks per tile, 2 per thread
    const int lrow0 = t >> 2,           lseg0 = t & 3;          // chunk t
    const int lrow1 = (t + 256) >> 2,   lseg1 = t & 3;          // chunk t+256

    float acc[4][4][4];
#pragma unroll
    for (int i = 0; i < 4; i++)
#pragma unroll
        for (int j = 0; j < 4; j++)
#pragma unroll
            for (int r = 0; r < 4; r++) acc[i][j][r] = 0.f;

    const int NTILES = (NTERMS == 3) ? 4 : 3;
    const __nv_bfloat16* srcs[4] = { Ahi, Alo, Bhi, Blo };

    auto load_chunk = [&](int c, int buf) {
        const int kt = c * 32;
        const uint32_t bb = sbase + (uint32_t)buf * BUFB;
#pragma unroll
        for (int tl = 0; tl < NTILES; tl++) {
            const int rb = (tl < 2) ? mBase : nBase;
            const __nv_bfloat16* sp = srcs[tl];
            cp16(bb + tl * TILEB + lrow0 * LDSROW + lseg0 * 16,
                 sp + (size_t)(rb + lrow0) * K + kt + lseg0 * 8);
            cp16(bb + tl * TILEB + lrow1 * LDSROW + lseg1 * 16,
                 sp + (size_t)(rb + lrow1) * K + kt + lseg1 * 8);
        }
    };

    const int NC = K >> 5;

    load_chunk(0, 0);
    CP_COMMIT();

    for (int c = 0; c < NC; c++) {
        if (c + 1 < NC) {
            load_chunk(c + 1, (c + 1) & 1);
            CP_COMMIT();
            CP_WAIT1();
        } else {
            CP_WAIT0();
        }
        __syncthreads();

        const uint32_t bb  = sbase + (uint32_t)(c & 1) * BUFB;
        const uint32_t bAh = bb + (uint32_t)mW * LDSROW;
        const uint32_t bAl = bAh + TILEB;
        const uint32_t bBh = bb + 2 * TILEB + (uint32_t)nW * LDSROW;
        const uint32_t bBl = bBh + TILEB;

#pragma unroll
        for (int ks = 0; ks < 2; ks++) {
            const uint32_t ko = (uint32_t)ks * 32;
            uint32_t aH[4][4], aL[4][4], bH[4][2];
#pragma unroll
            for (int i = 0; i < 4; i++)
                LDSM4(aH[i], bAh + (uint32_t)(i * 16) * LDSROW + ko + aOff);
#pragma unroll
            for (int i = 0; i < 4; i++)
                LDSM4(aL[i], bAl + (uint32_t)(i * 16) * LDSROW + ko + aOff);
#pragma unroll
            for (int j = 0; j < 2; j++) {
                uint32_t r[4];
                LDSM4(r, bBh + (uint32_t)(j * 16) * LDSROW + ko + bOff);
                bH[2*j][0] = r[0]; bH[2*j][1] = r[1];
                bH[2*j+1][0] = r[2]; bH[2*j+1][1] = r[3];
            }
            if (NTERMS == 3) {
                uint32_t bL[4][2];
#pragma unroll
                for (int j = 0; j < 2; j++) {
                    uint32_t r[4];
                    LDSM4(r, bBl + (uint32_t)(j * 16) * LDSROW + ko + bOff);
                    bL[2*j][0] = r[0]; bL[2*j][1] = r[1];
                    bL[2*j+1][0] = r[2]; bL[2*j+1][1] = r[3];
                }
#pragma unroll
                for (int i = 0; i < 4; i++)
#pragma unroll
                    for (int j = 0; j < 4; j++) {
                        MMA16816(acc[i][j], aH[i], bH[j]);
                        MMA16816(acc[i][j], aH[i], bL[j]);
                        MMA16816(acc[i][j], aL[i], bH[j]);
                    }
            } else {
#pragma unroll
                for (int i = 0; i < 4; i++)
#pragma unroll
                    for (int j = 0; j < 4; j++) {
                        MMA16816(acc[i][j], aH[i], bH[j]);
                        MMA16816(acc[i][j], aL[i], bH[j]);
                    }
            }
        }
        __syncthreads();
    }

    // ---------------- epilogue: direct coalesced writes ----------------------
    const int g = lane >> 2, tg2 = (lane & 3) * 2;
    if (OUT_SPLIT) {
        __nv_bfloat16* ohi = Chi + (size_t)blockIdx.z * sC;
        __nv_bfloat16* olo = Clo + (size_t)blockIdx.z * sC;
#pragma unroll
        for (int i = 0; i < 4; i++) {
            const int r0 = mBase + mW + i * 16 + g, r1 = r0 + 8;
#pragma unroll
            for (int j = 0; j < 4; j++) {
                const int c0 = nBase + nW + j * 8 + tg2;
                float b0 = 0.f, b1 = 0.f;
                if (bias) { b0 = bias[c0]; b1 = bias[c0 + 1]; }
                float v00 = acc[i][j][0] * alpha + b0, v01 = acc[i][j][1] * alpha + b1;
                float v10 = acc[i][j][2] * alpha + b0, v11 = acc[i][j][3] * alpha + b1;
                __nv_bfloat16 h0, l0, h1, l1;
                split_one(v00, h0, l0); split_one(v01, h1, l1);
                *(__nv_bfloat162*)(ohi + (size_t)r0 * N + c0) = __nv_bfloat162(h0, h1);
                *(__nv_bfloat162*)(olo + (size_t)r0 * N + c0) = __nv_bfloat162(l0, l1);
                split_one(v10, h0, l0); split_one(v11, h1, l1);
                *(__nv_bfloat162*)(ohi + (size_t)r1 * N + c0) = __nv_bfloat162(h0, h1);
                *(__nv_bfloat162*)(olo + (size_t)r1 * N + c0) = __nv_bfloat162(l0, l1);
            }
        }
    } else {
        float* oc = Cf + (size_t)blockIdx.z * sC;
#pragma unroll
        for (int i = 0; i < 4; i++) {
            const int r0 = mBase + mW + i * 16 + g, r1 = r0 + 8;
#pragma unroll
            for (int j = 0; j < 4; j++) {
                const int c0 = nBase + nW + j * 8 + tg2;
                float b0 = 0.f, b1 = 0.f;
                if (bias) { b0 = bias[c0]; b1 = bias[c0 + 1]; }
                float2 va = make_float2(acc[i][j][0] * alpha + b0, acc[i][j][1] * alpha + b1);
                float2 vb = make_float2(acc[i][j][2] * alpha + b0, acc[i][j][3] * alpha + b1);
                *(float2*)(oc + (size_t)r0 * N + c0) = va;
                *(float2*)(oc + (size_t)r1 * N + c0) = vb;
            }
        }
    }
}

// ---------------- softmax over last dim (2048) -> split bf16 p ---------------
__global__ __launch_bounds__(256)
void softmax_split_kernel(const float* __restrict__ attn, const int* __restrict__ am,
                          __nv_bfloat16* __restrict__ phi, __nv_bfloat16* __restrict__ plo)
{
    __shared__ float red[256];
    const size_t row = blockIdx.x;
    const int b = (int)(row >> 11);
    const float* a = attn + row * (size_t)S_;
    const int* amb = am + (size_t)b * S_;
    const int t = threadIdx.x;

    float vals[8];
    float mx = -3.0e38f;
#pragma unroll
    for (int i = 0; i < 4; i++) {
        const int idx = t * 2 + i * 512;
        float2 v = *(const float2*)(a + idx);
        if (amb[idx] == 0)     v.x = -10000.f;
        if (amb[idx + 1] == 0) v.y = -10000.f;
        vals[2*i] = v.x; vals[2*i+1] = v.y;
        mx = fmaxf(mx, fmaxf(v.x, v.y));
    }
    red[t] = mx; __syncthreads();
    for (int o = 128; o > 0; o >>= 1) { if (t < o) red[t] = fmaxf(red[t], red[t + o]); __syncthreads(); }
    const float rmax = red[0];
    __syncthreads();

    float se = 0.f;
#pragma unroll
    for (int i = 0; i < 8; i++) { float e = __expf(vals[i] - rmax); vals[i] = e; se += e; }
    red[t] = se; __syncthreads();
    for (int o = 128; o > 0; o >>= 1) { if (t < o) red[t] += red[t + o]; __syncthreads(); }
    const float inv = 1.f / red[0];
#pragma unroll
    for (int i = 0; i < 4; i++) {
        const size_t o = row * (size_t)S_ + t * 2 + i * 512;
        __nv_bfloat16 h[2], l[2];
        split_one(vals[2*i]   * inv, h[0], l[0]);
        split_one(vals[2*i+1] * inv, h[1], l[1]);
        *(uint32_t*)(phi + o) = *(const uint32_t*)h;
        *(uint32_t*)(plo + o) = *(const uint32_t*)l;
    }
}

// ---------------- per-row LayerNorm + ReLU + dot(W2) -> token score ----------
__global__ __launch_bounds__(128)
void lnscore_kernel(const float* __restrict__ hpre, const float* __restrict__ g1,
                    const float* __restrict__ be1, const float* __restrict__ W2,
                    const float* __restrict__ b2, const int* __restrict__ am,
                    float* __restrict__ ts)
{
    __shared__ float red[128];
    const int row = blockIdx.x, t = threadIdx.x;
    const float* hr = hpre + (size_t)row * HH_;
    const float v0 = hr[t], v1 = hr[t + 128], v2 = hr[t + 256];

    red[t] = v0 + v1 + v2; __syncthreads();
    for (int o = 64; o > 0; o >>= 1) { if (t < o) red[t] += red[t + o]; __syncthreads(); }
    const float mean = red[0] * (1.f / HH_);
    __syncthreads();

    const float d0 = v0 - mean, d1 = v1 - mean, d2 = v2 - mean;
    red[t] = d0 * d0 + d1 * d1 + d2 * d2; __syncthreads();
    for (int o = 64; o > 0; o >>= 1) { if (t < o) red[t] += red[t + o]; __syncthreads(); }
    const float inv = rsqrtf(red[0] * (1.f / HH_) + 1e-5f);
    __syncthreads();

    float sp = fmaxf(d0 * inv * g1[t]       + be1[t],       0.f) * W2[t]
             + fmaxf(d1 * inv * g1[t + 128] + be1[t + 128], 0.f) * W2[t + 128]
             + fmaxf(d2 * inv * g1[t + 256] + be1[t + 256], 0.f) * W2[t + 256];
    red[t] = sp; __syncthreads();
    for (int o = 64; o > 0; o >>= 1) { if (t < o) red[t] += red[t + o]; __syncthreads(); }
    if (t == 0) {
        float v = red[0] + b2[0];
        if (am[row] == 0) v = -10000.f;
        ts[row] = v;
    }
}

// ---------------- span search + mean pooling ---------------------------------
__global__ __launch_bounds__(256)
void span_pool_kernel(const float* __restrict__ ts, const int* __restrict__ am,
                      const float* __restrict__ x, float* __restrict__ pooled)
{
    __shared__ float sc[2048];
    __shared__ float cum[2049];
    __shared__ float part[256];
    __shared__ int   ired[256];
    __shared__ float bvs[256];
    __shared__ int   bis[256];
    __shared__ int   s_start, s_len;

    const int b = blockIdx.x, t = threadIdx.x;

    int vc = 0;
    for (int i = t; i < S_; i += 256) {
        sc[i] = ts[(size_t)b * S_ + i];
        vc += am[(size_t)b * S_ + i];
    }
    ired[t] = vc; __syncthreads();
    for (int o = 128; o > 0; o >>= 1) { if (t < o) ired[t] += ired[t + o]; __syncthreads(); }
    const int vl = ired[0];

    float ps = 0.f;
    for (int i = 0; i < 8; i++) ps += sc[t * 8 + i];
    part[t] = ps; __syncthreads();
    if (t == 0) {
        float run = 0.f;
        for (int i = 0; i < 256; i++) { float v = part[i]; part[i] = run; run += v; }
        cum[2048] = run;
    }
    __syncthreads();
    float run = part[t];
    for (int i = 0; i < 8; i++) { int idx = t * 8 + i; cum[idx] = run; run += sc[idx]; }
    __syncthreads();

    float bestV = -3.0e38f; int bestI = 0x7fffffff;
    for (int flat = t; flat < 18 * S_; flat += 256) {
        const int li = flat >> 11, start = flat & 2047;
        const int L = 3 + li, end = start + L;
        const int endc = end > S_ ? S_ : end;
        const float fL = (float)L;
        float avg = (cum[endc] - cum[start]) / fL + 0.01f * fL / 20.0f;
        if (end > vl) avg = -1e30f;
        if (avg > bestV) { bestV = avg; bestI = flat; }
    }
    bvs[t] = bestV; bis[t] = bestI; __syncthreads();
    for (int o = 128; o > 0; o >>= 1) {
        if (t < o) {
            if (bvs[t + o] > bvs[t] || (bvs[t + o] == bvs[t] && bis[t + o] < bis[t])) {
                bvs[t] = bvs[t + o]; bis[t] = bis[t + o];
            }
        }
        __syncthreads();
    }
    if (t == 0) {
        const int fi = bis[0];
        int start = fi & 2047, L = 3 + (fi >> 11);
        if (vl <= 3) { start = 0; L = vl; }
        s_start = start; s_len = L;
    }
    __syncthreads();

    const int start = s_start, L = s_len;
    const float inv = 1.0f / ((float)L + 1e-6f);
    for (int h = t; h < H_; h += 256) {
        float s = 0.f;
        for (int r = 0; r < L; r++) s += x[((size_t)b * S_ + start + r) * H_ + h];
        pooled[b * H_ + h] = s * inv;
    }
}

// ---------------- classification head ----------------------------------------
__global__ __launch_bounds__(384)
void head_kernel(const float* __restrict__ pooled, const float* __restrict__ x,
                 const float* __restrict__ Wc1, const float* __restrict__ bc1,
                 const float* __restrict__ g2, const float* __restrict__ be2,
                 const float* __restrict__ Wc2, const float* __restrict__ bc2,
                 const float* __restrict__ Mint,
                 const float* __restrict__ Wcls, const float* __restrict__ bcls,
                 float* __restrict__ out)
{
    __shared__ float pl[768];
    __shared__ float hc[384];
    __shared__ float cs[64];
    __shared__ float cp[64];
    __shared__ float red[512];
    const int b = blockIdx.x, t = threadIdx.x;

    for (int i = t; i < H_; i += 384) pl[i] = pooled[b * H_ + i];
    if (t < 128) red[384 + t] = 0.f;
    __syncthreads();

    float acc = bc1[t];
    for (int k = 0; k < H_; k++) acc += pl[k] * Wc1[(size_t)k * HH_ + t];

    red[t] = acc; __syncthreads();
    for (int o = 256; o > 0; o >>= 1) { if (t < o) red[t] += red[t + o]; __syncthreads(); }
    const float mean = red[0] * (1.f / HH_);
    __syncthreads();
    const float d = acc - mean;
    red[t] = d * d; __syncthreads();
    for (int o = 256; o > 0; o >>= 1) { if (t < o) red[t] += red[t + o]; __syncthreads(); }
    const float var = red[0] * (1.f / HH_);
    const float yn = d * rsqrtf(var + 1e-5f) * g2[t] + be2[t];
    hc[t] = fmaxf(yn, 0.f);
    __syncthreads();

    if (t < C_) {
        float c = bc2[t];
        for (int k = 0; k < HH_; k++) c += hc[k] * Wc2[(size_t)k * C_ + t];
        cs[t] = c;
    }
    __syncthreads();
    if (t < C_) {
        float add = cs[t];
        for (int i = 0; i < C_; i++) {
            const float m = 0.5f * (Mint[i * C_ + t] + Mint[t * C_ + i]);
            const float sg = 1.f / (1.f + expf(-m));
            add += cs[i] * sg;
        }
        cp[t] = 1.f / (1.f + expf(-add));
    }
    __syncthreads();
    if (t < L_) {
        float lg = bcls[t];
        for (int c = 0; c < C_; c++) lg += cp[c] * Wcls[c * L_ + t];
        const float* xr = x + (size_t)b * S_ * H_;
        for (int h = 0; h < H_; h++) lg += xr[h] * Wcls[(C_ + h) * L_ + t];
        out[b * L_ + t] = lg;
    }
}

// ---------------------------- launcher ---------------------------------------
extern "C" void kernel_launch(void* const* d_in, const int* in_sizes, int n_in,
                              void* d_out, int out_size)
{
    const float* x    = (const float*)d_in[0];
    const int*   am   = (const int*)  d_in[1];
    const float* Wq   = (const float*)d_in[2];
    const float* bq   = (const float*)d_in[3];
    const float* Wk   = (const float*)d_in[4];
    const float* bk   = (const float*)d_in[5];
    const float* W1   = (const float*)d_in[6];
    const float* b1   = (const float*)d_in[7];
    const float* g1   = (const float*)d_in[8];
    const float* be1  = (const float*)d_in[9];
    const float* W2   = (const float*)d_in[10];
    const float* b2   = (const float*)d_in[11];
    const float* Wc1  = (const float*)d_in[12];
    const float* bc1  = (const float*)d_in[13];
    const float* g2   = (const float*)d_in[14];
    const float* be2  = (const float*)d_in[15];
    const float* Wc2  = (const float*)d_in[16];
    const float* bc2  = (const float*)d_in[17];
    const float* Mint = (const float*)d_in[18];
    const float* Wcls = (const float*)d_in[19];
    const float* bcls = (const float*)d_in[20];
    float* out = (float*)d_out;

    __nv_bfloat16 *xhi, *xlo, *qhi, *qlo, *khi, *klo;
    __nv_bfloat16 *phi, *plo, *yThi, *yTlo;
    __nv_bfloat16 *WqThi, *WkThi, *W1Thi;
    float *ap, *yp, *hp, *tp, *pp;
    cudaGetSymbolAddress((void**)&xhi,  g_xhi);  cudaGetSymbolAddress((void**)&xlo,  g_xlo);
    cudaGetSymbolAddress((void**)&qhi,  g_qhi);  cudaGetSymbolAddress((void**)&qlo,  g_qlo);
    cudaGetSymbolAddress((void**)&khi,  g_khi);  cudaGetSymbolAddress((void**)&klo,  g_klo);
    cudaGetSymbolAddress((void**)&phi,  g_phi);  cudaGetSymbolAddress((void**)&plo,  g_plo);
    cudaGetSymbolAddress((void**)&yThi, g_yThi); cudaGetSymbolAddress((void**)&yTlo, g_yTlo);
    cudaGetSymbolAddress((void**)&WqThi, g_WqThi);
    cudaGetSymbolAddress((void**)&WkThi, g_WkThi);
    cudaGetSymbolAddress((void**)&W1Thi, g_W1Thi);
    cudaGetSymbolAddress((void**)&ap, g_attn);
    cudaGetSymbolAddress((void**)&yp, g_y);
    cudaGetSymbolAddress((void**)&hp, g_hpre);
    cudaGetSymbolAddress((void**)&tp, g_ts);
    cudaGetSymbolAddress((void**)&pp, g_pool);

    cudaFuncSetAttribute(gemm_bf16s<2, true>,  cudaFuncAttributeMaxDynamicSharedMemorySize, GEMM_SMEM);
    cudaFuncSetAttribute(gemm_bf16s<2, false>, cudaFuncAttributeMaxDynamicSharedMemorySize, GEMM_SMEM);
    cudaFuncSetAttribute(gemm_bf16s<3, false>, cudaFuncAttributeMaxDynamicSharedMemorySize, GEMM_SMEM);

    // 0. weight transposes: W [768,384] -> W^T [384,768] hi only (2-term B side)
    transpose_split_kernel<false><<<dim3(24, 12, 1), dim3(32, 8)>>>(Wq, WqThi, nullptr, H_, HH_);
    transpose_split_kernel<false><<<dim3(24, 12, 1), dim3(32, 8)>>>(Wk, WkThi, nullptr, H_, HH_);
    transpose_split_kernel<false><<<dim3(24, 12, 1), dim3(32, 8)>>>(W1, W1Thi, nullptr, H_, HH_);

    // 1. x split (A operand of the three projections)
    split_f32_kernel<<<25165824 / 1024, 256>>>(x, xhi, xlo);

    // 2. projections (2-term: x_hi/lo @ W_hi): q/k -> split bf16 + bias; y -> fp32
    gemm_bf16s<2, true><<<dim3(3, 256, 1), 256, GEMM_SMEM>>>(
        xhi, xlo, WqThi, nullptr, nullptr, qhi, qlo, bq, HH_, H_, 1.f, 0, 0, 0);
    gemm_bf16s<2, true><<<dim3(3, 256, 1), 256, GEMM_SMEM>>>(
        xhi, xlo, WkThi, nullptr, nullptr, khi, klo, bk, HH_, H_, 1.f, 0, 0, 0);
    gemm_bf16s<2, false><<<dim3(3, 256, 1), 256, GEMM_SMEM>>>(
        xhi, xlo, W1Thi, nullptr, yp, nullptr, nullptr, b1, HH_, H_, 1.f, 0, 0, 0);

    // 3. y^T split per batch: y [B,S,HH] -> yT [B,HH,S] hi+lo (3-term B side)
    transpose_split_kernel<true><<<dim3(64, 12, 16), dim3(32, 8)>>>(yp, yThi, yTlo, S_, HH_);

    // 4. attn = q @ k^T / sqrt(HH) (2-term: q_hi/lo @ k_hi) -> fp32
    const float alpha = 1.0f / sqrtf((float)HH_);
    gemm_bf16s<2, false><<<dim3(16, 16, B_), 256, GEMM_SMEM>>>(
        qhi, qlo, khi, nullptr, ap, nullptr, nullptr, nullptr, S_, HH_, alpha,
        (size_t)S_ * HH_, (size_t)S_ * HH_, (size_t)S_ * S_);

    // 5. softmax -> split bf16 p
    softmax_split_kernel<<<B_ * S_, 256>>>(ap, am, phi, plo);

    // 6. h_pre = p @ y (3-term — score-critical): [2048,2048] x yT[384,2048] -> fp32
    gemm_bf16s<3, false><<<dim3(3, 16, B_), 256, GEMM_SMEM>>>(
        phi, plo, yThi, yTlo, hp, nullptr, nullptr, nullptr, HH_, S_, 1.f,
        (size_t)S_ * S_, (size_t)HH_ * S_, (size_t)S_ * HH_);

    // 7-9. scores, span+pool, head
    lnscore_kernel<<<B_ * S_, 128>>>(hp, g1, be1, W2, b2, am, tp);
    span_pool_kernel<<<B_, 256>>>(tp, am, x, pp);
    head_kernel<<<B_, 384>>>(pp, x, Wc1, bc1, g2, be2, Wc2, bc2, Mint, Wcls, bcls, out);
}

// round 7
// speedup vs baseline: 3.8338x; 1.0011x over previous
#include <cuda_runtime.h>
#include <cuda_bf16.h>
#include <math.h>
#include <stdint.h>

// Problem constants
#define B_  16
#define S_  2048
#define H_  768
#define HH_ 384
#define C_  64
#define L_  4

// ---------------- scratch (static __device__ arrays; no allocation) ----------
__device__ __nv_bfloat16 g_xhi [25165824], g_xlo [25165824];   // x split       [B*S,H]
__device__ __nv_bfloat16 g_qhi [12582912], g_qlo [12582912];   // q split       [B*S,HH]
__device__ __nv_bfloat16 g_khi [12582912], g_klo [12582912];   // k split       [B*S,HH]
__device__ float         g_attn[67108864];                     // attn logits   [B,S,S]
__device__ __nv_bfloat16 g_phi [67108864], g_plo [67108864];   // softmax split [B,S,S]
__device__ float         g_y   [12582912];                     // y=x@W1+b1     [B*S,HH]
__device__ __nv_bfloat16 g_yThi[12582912], g_yTlo[12582912];   // y^T split     [B,HH,S]
__device__ float         g_hpre[12582912];                     // h_pre fp32    [B*S,HH]
__device__ float         g_ts  [32768];
__device__ float         g_pool[12288];
__device__ __nv_bfloat16 g_WqThi[294912];                      // Wq^T hi [HH,H]
__device__ __nv_bfloat16 g_WkThi[294912];
__device__ __nv_bfloat16 g_W1Thi[294912];

// ============================ PTX helpers ====================================
__device__ __forceinline__ uint32_t smem_u32(const void* p) {
    return (uint32_t)__cvta_generic_to_shared(p);
}

__device__ __forceinline__ void cp16(uint32_t dst, const void* src) {
    asm volatile("cp.async.cg.shared.global [%0], [%1], 16;" :: "r"(dst), "l"(src));
}
#define CP_COMMIT() asm volatile("cp.async.commit_group;" ::: "memory")
#define CP_WAIT1()  asm volatile("cp.async.wait_group 1;" ::: "memory")
#define CP_WAIT0()  asm volatile("cp.async.wait_group 0;" ::: "memory")

#define LDSM4(r, addr) \
    asm volatile("ldmatrix.sync.aligned.m8n8.x4.shared.b16 {%0,%1,%2,%3}, [%4];" \
        : "=r"((r)[0]), "=r"((r)[1]), "=r"((r)[2]), "=r"((r)[3]) : "r"(addr))

#define MMA16816(d, a, b) \
    asm volatile("mma.sync.aligned.m16n8k16.row.col.f32.bf16.bf16.f32 " \
        "{%0,%1,%2,%3}, {%4,%5,%6,%7}, {%8,%9}, {%0,%1,%2,%3};" \
        : "+f"((d)[0]), "+f"((d)[1]), "+f"((d)[2]), "+f"((d)[3]) \
        : "r"((a)[0]), "r"((a)[1]), "r"((a)[2]), "r"((a)[3]), \
          "r"((b)[0]), "r"((b)[1]))

// SMEM tile geometry: 128 rows x 32 bf16 (64B data) padded to 80B/row
#define LDSROW 80
#define TILEB  (128 * LDSROW)         // 10240 B
#define BUFB   (4 * TILEB)            // up to Ahi, Alo, Bhi, Blo = 40960 B
#define GEMM_SMEM (2 * BUFB)          // double buffered = 81920 B

// =============== split conversions ==========================================
__device__ __forceinline__ void split_one(float v, __nv_bfloat16& hi, __nv_bfloat16& lo) {
    hi = __float2bfloat16(v);
    lo = __float2bfloat16(v - __bfloat162float(hi));
}

__global__ __launch_bounds__(256)
void split_f32_kernel(const float* __restrict__ src, __nv_bfloat16* __restrict__ hi,
                      __nv_bfloat16* __restrict__ lo)
{
    const size_t i = ((size_t)blockIdx.x * 256 + threadIdx.x) * 4;
    float4 v = *(const float4*)(src + i);
    __nv_bfloat16 h[4], l[4];
    split_one(v.x, h[0], l[0]); split_one(v.y, h[1], l[1]);
    split_one(v.z, h[2], l[2]); split_one(v.w, h[3], l[3]);
    *(uint2*)(hi + i) = *(const uint2*)h;
    *(uint2*)(lo + i) = *(const uint2*)l;
}

// in [R, C] -> out [C, R] with bf16 split (optionally hi only); z offset z*R*C
template<bool WRITE_LO>
__global__ __launch_bounds__(256)
void transpose_split_kernel(const float* __restrict__ in, __nv_bfloat16* __restrict__ ohi,
                            __nv_bfloat16* __restrict__ olo, int R, int Cc)
{
    __shared__ float tile[32][33];
    const size_t zoff = (size_t)blockIdx.z * R * Cc;
    in += zoff; ohi += zoff;
    if (WRITE_LO) olo += zoff;
    const int r0 = blockIdx.x * 32, c0 = blockIdx.y * 32;
    const int tx = threadIdx.x, ty = threadIdx.y;   // block (32,8)
#pragma unroll
    for (int j = 0; j < 32; j += 8)
        tile[ty + j][tx] = in[(size_t)(r0 + ty + j) * Cc + c0 + tx];
    __syncthreads();
    const int t = ty * 32 + tx;     // 0..255
#pragma unroll
    for (int pidx = t; pidx < 512; pidx += 256) {
        const int oc = pidx >> 4;            // output row (= input col) 0..31
        const int pr = (pidx & 15) * 2;      // input row pair
        __nv_bfloat16 h[2], l[2];
        split_one(tile[pr][oc],     h[0], l[0]);
        split_one(tile[pr + 1][oc], h[1], l[1]);
        size_t o = (size_t)(c0 + oc) * R + r0 + pr;
        *(uint32_t*)(ohi + o) = *(const uint32_t*)h;
        if (WRITE_LO) *(uint32_t*)(olo + o) = *(const uint32_t*)l;
    }
}

// =============== warp-MMA bf16 split GEMM ===================================
// C[M,N] = alpha * A @ B^T (+bias). A:[M,K] K-major split, B:[N,K] K-major split.
// NTERMS==3: aH*bH + aH*bL + aL*bH.  NTERMS==2: aH*bH + aL*bH (B lo unused).
// CTA tile 128x128, 8 warps of 64x32, K chunk 32, double-buffered cp.async.
// Requires M%128==0, N%128==0, K%32==0.
template<int NTERMS, bool OUT_SPLIT>
__global__ __launch_bounds__(256)
void gemm_bf16s(const __nv_bfloat16* __restrict__ Ahi, const __nv_bfloat16* __restrict__ Alo,
                const __nv_bfloat16* __restrict__ Bhi, const __nv_bfloat16* __restrict__ Blo,
                float* __restrict__ Cf, __nv_bfloat16* __restrict__ Chi,
                __nv_bfloat16* __restrict__ Clo, const float* __restrict__ bias,
                int N, int K, float alpha, size_t sA, size_t sB, size_t sC)
{
    extern __shared__ char smem[];
    const uint32_t sbase = smem_u32(smem);
    const int t = threadIdx.x;
    const int mBase = blockIdx.y * 128, nBase = blockIdx.x * 128;
    Ahi += (size_t)blockIdx.z * sA; Alo += (size_t)blockIdx.z * sA;
    Bhi += (size_t)blockIdx.z * sB;
    if (NTERMS == 3) Blo += (size_t)blockIdx.z * sB;

    const int lane = t & 31, w = t >> 5;
    const int mW = (w & 1) * 64, nW = (w >> 1) * 32;
    // ldmatrix lane address offsets (within a 16-row x 32B k16 window)
    const uint32_t aOff = (uint32_t)(lane & 15) * LDSROW + (uint32_t)(lane >> 4) * 16;
    const uint32_t bOff = (uint32_t)(((lane >> 4) << 3) + (lane & 7)) * LDSROW
                        + (uint32_t)((lane >> 3) & 1) * 16;

    // loader mapping: 512 x 16B chunks per tile, 2 per thread
    const int lrow0 = t >> 2,           lseg0 = t & 3;          // chunk t
    const int lrow1 = (t + 256) >> 2,   lseg1 = t & 3;          // chunk t+256

    float acc[4][4][4];
#pragma unroll
    for (int i = 0; i < 4; i++)
#pragma unroll
        for (int j = 0; j < 4; j++)
#pragma unroll
            for (int r = 0; r < 4; r++) acc[i][j][r] = 0.f;

    const int NTILES = (NTERMS == 3) ? 4 : 3;
    const __nv_bfloat16* srcs[4] = { Ahi, Alo, Bhi, Blo };

    auto load_chunk = [&](int c, int buf) {
        const int kt = c * 32;
        const uint32_t bb = sbase + (uint32_t)buf * BUFB;
#pragma unroll
        for (int tl = 0; tl < NTILES; tl++) {
            const int rb = (tl < 2) ? mBase : nBase;
            const __nv_bfloat16* sp = srcs[tl];
            cp16(bb + tl * TILEB + lrow0 * LDSROW + lseg0 * 16,
                 sp + (size_t)(rb + lrow0) * K + kt + lseg0 * 8);
            cp16(bb + tl * TILEB + lrow1 * LDSROW + lseg1 * 16,
                 sp + (size_t)(rb + lrow1) * K + kt + lseg1 * 8);
        }
    };

    const int NC = K >> 5;

    load_chunk(0, 0);
    CP_COMMIT();

    for (int c = 0; c < NC; c++) {
        if (c + 1 < NC) {
            load_chunk(c + 1, (c + 1) & 1);
            CP_COMMIT();
            CP_WAIT1();
        } else {
            CP_WAIT0();
        }
        __syncthreads();

        const uint32_t bb  = sbase + (uint32_t)(c & 1) * BUFB;
        const uint32_t bAh = bb + (uint32_t)mW * LDSROW;
        const uint32_t bAl = bAh + TILEB;
        const uint32_t bBh = bb + 2 * TILEB + (uint32_t)nW * LDSROW;
        const uint32_t bBl = bBh + TILEB;

#pragma unroll
        for (int ks = 0; ks < 2; ks++) {
            const uint32_t ko = (uint32_t)ks * 32;
            uint32_t aH[4][4], aL[4][4], bH[4][2];
#pragma unroll
            for (int i = 0; i < 4; i++)
                LDSM4(aH[i], bAh + (uint32_t)(i * 16) * LDSROW + ko + aOff);
#pragma unroll
            for (int i = 0; i < 4; i++)
                LDSM4(aL[i], bAl + (uint32_t)(i * 16) * LDSROW + ko + aOff);
#pragma unroll
            for (int j = 0; j < 2; j++) {
                uint32_t r[4];
                LDSM4(r, bBh + (uint32_t)(j * 16) * LDSROW + ko + bOff);
                bH[2*j][0] = r[0]; bH[2*j][1] = r[1];
                bH[2*j+1][0] = r[2]; bH[2*j+1][1] = r[3];
            }
            if (NTERMS == 3) {
                uint32_t bL[4][2];
#pragma unroll
                for (int j = 0; j < 2; j++) {
                    uint32_t r[4];
                    LDSM4(r, bBl + (uint32_t)(j * 16) * LDSROW + ko + bOff);
                    bL[2*j][0] = r[0]; bL[2*j][1] = r[1];
                    bL[2*j+1][0] = r[2]; bL[2*j+1][1] = r[3];
                }
#pragma unroll
                for (int i = 0; i < 4; i++)
#pragma unroll
                    for (int j = 0; j < 4; j++) {
                        MMA16816(acc[i][j], aH[i], bH[j]);
                        MMA16816(acc[i][j], aH[i], bL[j]);
                        MMA16816(acc[i][j], aL[i], bH[j]);
                    }
            } else {
#pragma unroll
                for (int i = 0; i < 4; i++)
#pragma unroll
                    for (int j = 0; j < 4; j++) {
                        MMA16816(acc[i][j], aH[i], bH[j]);
                        MMA16816(acc[i][j], aL[i], bH[j]);
                    }
            }
        }
        __syncthreads();
    }

    // ---------------- epilogue: direct coalesced writes ----------------------
    const int g = lane >> 2, tg2 = (lane & 3) * 2;
    if (OUT_SPLIT) {
        __nv_bfloat16* ohi = Chi + (size_t)blockIdx.z * sC;
        __nv_bfloat16* olo = Clo + (size_t)blockIdx.z * sC;
#pragma unroll
        for (int i = 0; i < 4; i++) {
            const int r0 = mBase + mW + i * 16 + g, r1 = r0 + 8;
#pragma unroll
            for (int j = 0; j < 4; j++) {
                const int c0 = nBase + nW + j * 8 + tg2;
                float b0 = 0.f, b1 = 0.f;
                if (bias) { b0 = bias[c0]; b1 = bias[c0 + 1]; }
                float v00 = acc[i][j][0] * alpha + b0, v01 = acc[i][j][1] * alpha + b1;
                float v10 = acc[i][j][2] * alpha + b0, v11 = acc[i][j][3] * alpha + b1;
                __nv_bfloat16 h0, l0, h1, l1;
                split_one(v00, h0, l0); split_one(v01, h1, l1);
                *(__nv_bfloat162*)(ohi + (size_t)r0 * N + c0) = __nv_bfloat162(h0, h1);
                *(__nv_bfloat162*)(olo + (size_t)r0 * N + c0) = __nv_bfloat162(l0, l1);
                split_one(v10, h0, l0); split_one(v11, h1, l1);
                *(__nv_bfloat162*)(ohi + (size_t)r1 * N + c0) = __nv_bfloat162(h0, h1);
                *(__nv_bfloat162*)(olo + (size_t)r1 * N + c0) = __nv_bfloat162(l0, l1);
            }
        }
    } else {
        float* oc = Cf + (size_t)blockIdx.z * sC;
#pragma unroll
        for (int i = 0; i < 4; i++) {
            const int r0 = mBase + mW + i * 16 + g, r1 = r0 + 8;
#pragma unroll
            for (int j = 0; j < 4; j++) {
                const int c0 = nBase + nW + j * 8 + tg2;
                float b0 = 0.f, b1 = 0.f;
                if (bias) { b0 = bias[c0]; b1 = bias[c0 + 1]; }
                float2 va = make_float2(acc[i][j][0] * alpha + b0, acc[i][j][1] * alpha + b1);
                float2 vb = make_float2(acc[i][j][2] * alpha + b0, acc[i][j][3] * alpha + b1);
                *(float2*)(oc + (size_t)r0 * N + c0) = va;
                *(float2*)(oc + (size_t)r1 * N + c0) = vb;
            }
        }
    }
}

// ---------------- softmax over last dim (2048) -> split bf16 p ---------------
__global__ __launch_bounds__(256)
void softmax_split_kernel(const float* __restrict__ attn, const int* __restrict__ am,
                          __nv_bfloat16* __restrict__ phi, __nv_bfloat16* __restrict__ plo)
{
    __shared__ float red[256];
    const size_t row = blockIdx.x;
    const int b = (int)(row >> 11);
    const float* a = attn + row * (size_t)S_;
    const int* amb = am + (size_t)b * S_;
    const int t = threadIdx.x;

    float vals[8];
    float mx = -3.0e38f;
#pragma unroll
    for (int i = 0; i < 4; i++) {
        const int idx = t * 2 + i * 512;
        float2 v = *(const float2*)(a + idx);
        if (amb[idx] == 0)     v.x = -10000.f;
        if (amb[idx + 1] == 0) v.y = -10000.f;
        vals[2*i] = v.x; vals[2*i+1] = v.y;
        mx = fmaxf(mx, fmaxf(v.x, v.y));
    }
    red[t] = mx; __syncthreads();
    for (int o = 128; o > 0; o >>= 1) { if (t < o) red[t] = fmaxf(red[t], red[t + o]); __syncthreads(); }
    const float rmax = red[0];
    __syncthreads();

    float se = 0.f;
#pragma unroll
    for (int i = 0; i < 8; i++) { float e = __expf(vals[i] - rmax); vals[i] = e; se += e; }
    red[t] = se; __syncthreads();
    for (int o = 128; o > 0; o >>= 1) { if (t < o) red[t] += red[t + o]; __syncthreads(); }
    const float inv = 1.f / red[0];
#pragma unroll
    for (int i = 0; i < 4; i++) {
        const size_t o = row * (size_t)S_ + t * 2 + i * 512;
        __nv_bfloat16 h[2], l[2];
        split_one(vals[2*i]   * inv, h[0], l[0]);
        split_one(vals[2*i+1] * inv, h[1], l[1]);
        *(uint32_t*)(phi + o) = *(const uint32_t*)h;
        *(uint32_t*)(plo + o) = *(const uint32_t*)l;
    }
}

// ---------------- per-row LayerNorm + ReLU + dot(W2) -> token score ----------
__global__ __launch_bounds__(128)
void lnscore_kernel(const float* __restrict__ hpre, const float* __restrict__ g1,
                    const float* __restrict__ be1, const float* __restrict__ W2,
                    const float* __restrict__ b2, const int* __restrict__ am,
                    float* __restrict__ ts)
{
    __shared__ float red[128];
    const int row = blockIdx.x, t = threadIdx.x;
    const float* hr = hpre + (size_t)row * HH_;
    const float v0 = hr[t], v1 = hr[t + 128], v2 = hr[t + 256];

    red[t] = v0 + v1 + v2; __syncthreads();
    for (int o = 64; o > 0; o >>= 1) { if (t < o) red[t] += red[t + o]; __syncthreads(); }
    const float mean = red[0] * (1.f / HH_);
    __syncthreads();

    const float d0 = v0 - mean, d1 = v1 - mean, d2 = v2 - mean;
    red[t] = d0 * d0 + d1 * d1 + d2 * d2; __syncthreads();
    for (int o = 64; o > 0; o >>= 1) { if (t < o) red[t] += red[t + o]; __syncthreads(); }
    const float inv = rsqrtf(red[0] * (1.f / HH_) + 1e-5f);
    __syncthreads();

    float sp = fmaxf(d0 * inv * g1[t]       + be1[t],       0.f) * W2[t]
             + fmaxf(d1 * inv * g1[t + 128] + be1[t + 128], 0.f) * W2[t + 128]
             + fmaxf(d2 * inv * g1[t + 256] + be1[t + 256], 0.f) * W2[t + 256];
    red[t] = sp; __syncthreads();
    for (int o = 64; o > 0; o >>= 1) { if (t < o) red[t] += red[t + o]; __syncthreads(); }
    if (t == 0) {
        float v = red[0] + b2[0];
        if (am[row] == 0) v = -10000.f;
        ts[row] = v;
    }
}

// ---------------- span search + mean pooling ---------------------------------
__global__ __launch_bounds__(256)
void span_pool_kernel(const float* __restrict__ ts, const int* __restrict__ am,
                      const float* __restrict__ x, float* __restrict__ pooled)
{
    __shared__ float sc[2048];
    __shared__ float cum[2049];
    __shared__ float part[256];
    __shared__ int   ired[256];
    __shared__ float bvs[256];
    __shared__ int   bis[256];
    __shared__ int   s_start, s_len;

    const int b = blockIdx.x, t = threadIdx.x;

    int vc = 0;
    for (int i = t; i < S_; i += 256) {
        sc[i] = ts[(size_t)b * S_ + i];
        vc += am[(size_t)b * S_ + i];
    }
    ired[t] = vc; __syncthreads();
    for (int o = 128; o > 0; o >>= 1) { if (t < o) ired[t] += ired[t + o]; __syncthreads(); }
    const int vl = ired[0];

    float ps = 0.f;
    for (int i = 0; i < 8; i++) ps += sc[t * 8 + i];
    part[t] = ps; __syncthreads();
    if (t == 0) {
        float run = 0.f;
        for (int i = 0; i < 256; i++) { float v = part[i]; part[i] = run; run += v; }
        cum[2048] = run;
    }
    __syncthreads();
    float run = part[t];
    for (int i = 0; i < 8; i++) { int idx = t * 8 + i; cum[idx] = run; run += sc[idx]; }
    __syncthreads();

    float bestV = -3.0e38f; int bestI = 0x7fffffff;
    for (int flat = t; flat < 18 * S_; flat += 256) {
        const int li = flat >> 11, start = flat & 2047;
        const int L = 3 + li, end = start + L;
        const int endc = end > S_ ? S_ : end;
        const float fL = (float)L;
        float avg = (cum[endc] - cum[start]) / fL + 0.01f * fL / 20.0f;
        if (end > vl) avg = -1e30f;
        if (avg > bestV) { bestV = avg; bestI = flat; }
    }
    bvs[t] = bestV; bis[t] = bestI; __syncthreads();
    for (int o = 128; o > 0; o >>= 1) {
        if (t < o) {
            if (bvs[t + o] > bvs[t] || (bvs[t + o] == bvs[t] && bis[t + o] < bis[t])) {
                bvs[t] = bvs[t + o]; bis[t] = bis[t + o];
            }
        }
        __syncthreads();
    }
    if (t == 0) {
        const int fi = bis[0];
        int start = fi & 2047, L = 3 + (fi >> 11);
        if (vl <= 3) { start = 0; L = vl; }
        s_start = start; s_len = L;
    }
    __syncthreads();

    const int start = s_start, L = s_len;
    const float inv = 1.0f / ((float)L + 1e-6f);
    for (int h = t; h < H_; h += 256) {
        float s = 0.f;
        for (int r = 0; r < L; r++) s += x[((size_t)b * S_ + start + r) * H_ + h];
        pooled[b * H_ + h] = s * inv;
    }
}

// ---------------- classification head ----------------------------------------
__global__ __launch_bounds__(384)
void head_kernel(const float* __restrict__ pooled, const float* __restrict__ x,
                 const float* __restrict__ Wc1, const float* __restrict__ bc1,
                 const float* __restrict__ g2, const float* __restrict__ be2,
                 const float* __restrict__ Wc2, const float* __restrict__ bc2,
                 const float* __restrict__ Mint,
                 const float* __restrict__ Wcls, const float* __restrict__ bcls,
                 float* __restrict__ out)
{
    __shared__ float pl[768];
    __shared__ float hc[384];
    __shared__ float cs[64];
    __shared__ float cp[64];
    __shared__ float red[512];
    const int b = blockIdx.x, t = threadIdx.x;

    for (int i = t; i < H_; i += 384) pl[i] = pooled[b * H_ + i];
    if (t < 128) red[384 + t] = 0.f;
    __syncthreads();

    float acc = bc1[t];
    for (int k = 0; k < H_; k++) acc += pl[k] * Wc1[(size_t)k * HH_ + t];

    red[t] = acc; __syncthreads();
    for (int o = 256; o > 0; o >>= 1) { if (t < o) red[t] += red[t + o]; __syncthreads(); }
    const float mean = red[0] * (1.f / HH_);
    __syncthreads();
    const float d = acc - mean;
    red[t] = d * d; __syncthreads();
    for (int o = 256; o > 0; o >>= 1) { if (t < o) red[t] += red[t + o]; __syncthreads(); }
    const float var = red[0] * (1.f / HH_);
    const float yn = d * rsqrtf(var + 1e-5f) * g2[t] + be2[t];
    hc[t] = fmaxf(yn, 0.f);
    __syncthreads();

    if (t < C_) {
        float c = bc2[t];
        for (int k = 0; k < HH_; k++) c += hc[k] * Wc2[(size_t)k * C_ + t];
        cs[t] = c;
    }
    __syncthreads();
    if (t < C_) {
        float add = cs[t];
        for (int i = 0; i < C_; i++) {
            const float m = 0.5f * (Mint[i * C_ + t] + Mint[t * C_ + i]);
            const float sg = 1.f / (1.f + expf(-m));
            add += cs[i] * sg;
        }
        cp[t] = 1.f / (1.f + expf(-add));
    }
    __syncthreads();
    if (t < L_) {
        float lg = bcls[t];
        for (int c = 0; c < C_; c++) lg += cp[c] * Wcls[c * L_ + t];
        const float* xr = x + (size_t)b * S_ * H_;
        for (int h = 0; h < H_; h++) lg += xr[h] * Wcls[(C_ + h) * L_ + t];
        out[b * L_ + t] = lg;
    }
}

// ---------------------------- launcher ---------------------------------------
extern "C" void kernel_launch(void* const* d_in, const int* in_sizes, int n_in,
                              void* d_out, int out_size)
{
    const float* x    = (const float*)d_in[0];
    const int*   am   = (const int*)  d_in[1];
    const float* Wq   = (const float*)d_in[2];
    const float* bq   = (const float*)d_in[3];
    const float* Wk   = (const float*)d_in[4];
    const float* bk   = (const float*)d_in[5];
    const float* W1   = (const float*)d_in[6];
    const float* b1   = (const float*)d_in[7];
    const float* g1   = (const float*)d_in[8];
    const float* be1  = (const float*)d_in[9];
    const float* W2   = (const float*)d_in[10];
    const float* b2   = (const float*)d_in[11];
    const float* Wc1  = (const float*)d_in[12];
    const float* bc1  = (const float*)d_in[13];
    const float* g2   = (const float*)d_in[14];
    const float* be2  = (const float*)d_in[15];
    const float* Wc2  = (const float*)d_in[16];
    const float* bc2  = (const float*)d_in[17];
    const float* Mint = (const float*)d_in[18];
    const float* Wcls = (const float*)d_in[19];
    const float* bcls = (const float*)d_in[20];
    float* out = (float*)d_out;

    __nv_bfloat16 *xhi, *xlo, *qhi, *qlo, *khi, *klo;
    __nv_bfloat16 *phi, *plo, *yThi, *yTlo;
    __nv_bfloat16 *WqThi, *WkThi, *W1Thi;
    float *ap, *yp, *hp, *tp, *pp;
    cudaGetSymbolAddress((void**)&xhi,  g_xhi);  cudaGetSymbolAddress((void**)&xlo,  g_xlo);
    cudaGetSymbolAddress((void**)&qhi,  g_qhi);  cudaGetSymbolAddress((void**)&qlo,  g_qlo);
    cudaGetSymbolAddress((void**)&khi,  g_khi);  cudaGetSymbolAddress((void**)&klo,  g_klo);
    cudaGetSymbolAddress((void**)&phi,  g_phi);  cudaGetSymbolAddress((void**)&plo,  g_plo);
    cudaGetSymbolAddress((void**)&yThi, g_yThi); cudaGetSymbolAddress((void**)&yTlo, g_yTlo);
    cudaGetSymbolAddress((void**)&WqThi, g_WqThi);
    cudaGetSymbolAddress((void**)&WkThi, g_WkThi);
    cudaGetSymbolAddress((void**)&W1Thi, g_W1Thi);
    cudaGetSymbolAddress((void**)&ap, g_attn);
    cudaGetSymbolAddress((void**)&yp, g_y);
    cudaGetSymbolAddress((void**)&hp, g_hpre);
    cudaGetSymbolAddress((void**)&tp, g_ts);
    cudaGetSymbolAddress((void**)&pp, g_pool);

    cudaFuncSetAttribute(gemm_bf16s<2, true>,  cudaFuncAttributeMaxDynamicSharedMemorySize, GEMM_SMEM);
    cudaFuncSetAttribute(gemm_bf16s<2, false>, cudaFuncAttributeMaxDynamicSharedMemorySize, GEMM_SMEM);
    cudaFuncSetAttribute(gemm_bf16s<3, false>, cudaFuncAttributeMaxDynamicSharedMemorySize, GEMM_SMEM);

    // 0. weight transposes: W [768,384] -> W^T [384,768] hi only (2-term B side)
    transpose_split_kernel<false><<<dim3(24, 12, 1), dim3(32, 8)>>>(Wq, WqThi, nullptr, H_, HH_);
    transpose_split_kernel<false><<<dim3(24, 12, 1), dim3(32, 8)>>>(Wk, WkThi, nullptr, H_, HH_);
    transpose_split_kernel<false><<<dim3(24, 12, 1), dim3(32, 8)>>>(W1, W1Thi, nullptr, H_, HH_);

    // 1. x split (A operand of the three projections)
    split_f32_kernel<<<25165824 / 1024, 256>>>(x, xhi, xlo);

    // 2. projections (2-term: x_hi/lo @ W_hi): q/k -> split bf16 + bias; y -> fp32
    gemm_bf16s<2, true><<<dim3(3, 256, 1), 256, GEMM_SMEM>>>(
        xhi, xlo, WqThi, nullptr, nullptr, qhi, qlo, bq, HH_, H_, 1.f, 0, 0, 0);
    gemm_bf16s<2, true><<<dim3(3, 256, 1), 256, GEMM_SMEM>>>(
        xhi, xlo, WkThi, nullptr, nullptr, khi, klo, bk, HH_, H_, 1.f, 0, 0, 0);
    gemm_bf16s<2, false><<<dim3(3, 256, 1), 256, GEMM_SMEM>>>(
        xhi, xlo, W1Thi, nullptr, yp, nullptr, nullptr, b1, HH_, H_, 1.f, 0, 0, 0);

    // 3. y^T split per batch: y [B,S,HH] -> yT [B,HH,S] hi+lo (3-term B side)
    transpose_split_kernel<true><<<dim3(64, 12, 16), dim3(32, 8)>>>(yp, yThi, yTlo, S_, HH_);

    // 4. attn = q @ k^T / sqrt(HH) (2-term: q_hi/lo @ k_hi) -> fp32
    const float alpha = 1.0f / sqrtf((float)HH_);
    gemm_bf16s<2, false><<<dim3(16, 16, B_), 256, GEMM_SMEM>>>(
        qhi, qlo, khi, nullptr, ap, nullptr, nullptr, nullptr, S_, HH_, alpha,
        (size_t)S_ * HH_, (size_t)S_ * HH_, (size_t)S_ * S_);

    // 5. softmax -> split bf16 p
    softmax_split_kernel<<<B_ * S_, 256>>>(ap, am, phi, plo);

    // 6. h_pre = p @ y (3-term — score-critical): [2048,2048] x yT[384,2048] -> fp32
    gemm_bf16s<3, false><<<dim3(3, 16, B_), 256, GEMM_SMEM>>>(
        phi, plo, yThi, yTlo, hp, nullptr, nullptr, nullptr, HH_, S_, 1.f,
        (size_t)S_ * S_, (size_t)HH_ * S_, (size_t)S_ * HH_);

    // 7-9. scores, span+pool, head
    lnscore_kernel<<<B_ * S_, 128>>>(hp, g1, be1, W2, b2, am, tp);
    span_pool_kernel<<<B_, 256>>>(tp, am, x, pp);
    head_kernel<<<B_, 384>>>(pp, x, Wc1, bc1, g2, be2, Wc2, bc2, Mint, Wcls, bcls, out);
}

// round 8
// speedup vs baseline: 5.8903x; 1.5364x over previous
#include <cuda_runtime.h>
#include <cuda_bf16.h>
#include <math.h>
#include <stdint.h>

// Problem constants
#define B_  16
#define S_  2048
#define H_  768
#define HH_ 384
#define C_  64
#define L_  4

// ---------------- scratch (static __device__ arrays; no allocation) ----------
__device__ __nv_bfloat16 g_xhi [25165824];     // x bf16        [B*S,H]
__device__ __nv_bfloat16 g_qhi [12582912];     // q bf16        [B*S,HH]
__device__ __nv_bfloat16 g_khi [12582912];     // k bf16        [B*S,HH]
__device__ float         g_attn[67108864];     // attn logits   [B,S,S]
__device__ __nv_bfloat16 g_phi [67108864];     // softmax bf16  [B,S,S]
__device__ float         g_y   [12582912];     // y=x@W1+b1     [B*S,HH]
__device__ __nv_bfloat16 g_yThi[12582912];     // y^T bf16      [B,HH,S]
__device__ float         g_hpre[12582912];     // h_pre fp32    [B*S,HH]
__device__ float         g_ts  [32768];
__device__ float         g_pool[12288];
__device__ __nv_bfloat16 g_WqThi[294912];      // Wq^T bf16 [HH,H]
__device__ __nv_bfloat16 g_WkThi[294912];
__device__ __nv_bfloat16 g_W1Thi[294912];

// ============================ PTX helpers ====================================
__device__ __forceinline__ uint32_t smem_u32(const void* p) {
    return (uint32_t)__cvta_generic_to_shared(p);
}

__device__ __forceinline__ void cp16(uint32_t dst, const void* src) {
    asm volatile("cp.async.cg.shared.global [%0], [%1], 16;" :: "r"(dst), "l"(src));
}
#define CP_COMMIT() asm volatile("cp.async.commit_group;" ::: "memory")
#define CP_WAIT2()  asm volatile("cp.async.wait_group 2;" ::: "memory")

#define LDSM4(r, addr) \
    asm volatile("ldmatrix.sync.aligned.m8n8.x4.shared.b16 {%0,%1,%2,%3}, [%4];" \
        : "=r"((r)[0]), "=r"((r)[1]), "=r"((r)[2]), "=r"((r)[3]) : "r"(addr))

#define MMA16816(d, a, b) \
    asm volatile("mma.sync.aligned.m16n8k16.row.col.f32.bf16.bf16.f32 " \
        "{%0,%1,%2,%3}, {%4,%5,%6,%7}, {%8,%9}, {%0,%1,%2,%3};" \
        : "+f"((d)[0]), "+f"((d)[1]), "+f"((d)[2]), "+f"((d)[3]) \
        : "r"((a)[0]), "r"((a)[1]), "r"((a)[2]), "r"((a)[3]), \
          "r"((b)[0]), "r"((b)[1]))

// SMEM tile geometry: 128 rows x 32 bf16 (64B data) padded to 80B/row
#define LDSROW 80
#define TILEB  (128 * LDSROW)         // 10240 B
#define BUFB   (2 * TILEB)            // A, B tiles = 20480 B
#define GEMM_SMEM (3 * BUFB)          // 3-stage pipeline = 61440 B

// =============== conversions ================================================
__global__ __launch_bounds__(256)
void cvt_bf16_kernel(const float* __restrict__ src, __nv_bfloat16* __restrict__ hi)
{
    const size_t i = ((size_t)blockIdx.x * 256 + threadIdx.x) * 8;
    float4 v0 = *(const float4*)(src + i);
    float4 v1 = *(const float4*)(src + i + 4);
    __nv_bfloat16 h[8];
    h[0] = __float2bfloat16(v0.x); h[1] = __float2bfloat16(v0.y);
    h[2] = __float2bfloat16(v0.z); h[3] = __float2bfloat16(v0.w);
    h[4] = __float2bfloat16(v1.x); h[5] = __float2bfloat16(v1.y);
    h[6] = __float2bfloat16(v1.z); h[7] = __float2bfloat16(v1.w);
    *(uint4*)(hi + i) = *(const uint4*)h;
}

// in [R, C] -> out [C, R] bf16; per-z offset = z*R*C
__global__ __launch_bounds__(256)
void transpose_bf16_kernel(const float* __restrict__ in, __nv_bfloat16* __restrict__ ohi,
                           int R, int Cc)
{
    __shared__ float tile[32][33];
    const size_t zoff = (size_t)blockIdx.z * R * Cc;
    in += zoff; ohi += zoff;
    const int r0 = blockIdx.x * 32, c0 = blockIdx.y * 32;
    const int tx = threadIdx.x, ty = threadIdx.y;   // block (32,8)
#pragma unroll
    for (int j = 0; j < 32; j += 8)
        tile[ty + j][tx] = in[(size_t)(r0 + ty + j) * Cc + c0 + tx];
    __syncthreads();
    const int t = ty * 32 + tx;     // 0..255
#pragma unroll
    for (int pidx = t; pidx < 512; pidx += 256) {
        const int oc = pidx >> 4;            // output row (= input col) 0..31
        const int pr = (pidx & 15) * 2;      // input row pair
        __nv_bfloat16 h[2];
        h[0] = __float2bfloat16(tile[pr][oc]);
        h[1] = __float2bfloat16(tile[pr + 1][oc]);
        size_t o = (size_t)(c0 + oc) * R + r0 + pr;
        *(uint32_t*)(ohi + o) = *(const uint32_t*)h;
    }
}

// =============== warp-MMA bf16 GEMM =========================================
// C[M,N] = alpha * A @ B^T (+bias). A:[M,K] K-major bf16, B:[N,K] K-major bf16.
// CTA tile 128x128, 8 warps of 64x32, K chunk 32, 3-stage cp.async pipeline.
// Requires M%128==0, N%128==0, K%32==0, K/32 >= 2.
template<bool OUT_BF16>
__global__ __launch_bounds__(256)
void gemm_bf16(const __nv_bfloat16* __restrict__ A, const __nv_bfloat16* __restrict__ Bm,
               float* __restrict__ Cf, __nv_bfloat16* __restrict__ Cb,
               const float* __restrict__ bias,
               int N, int K, float alpha, size_t sA, size_t sB, size_t sC)
{
    extern __shared__ char smem[];
    const uint32_t sbase = smem_u32(smem);
    const int t = threadIdx.x;
    const int mBase = blockIdx.y * 128, nBase = blockIdx.x * 128;
    A  += (size_t)blockIdx.z * sA;
    Bm += (size_t)blockIdx.z * sB;

    const int lane = t & 31, w = t >> 5;
    const int mW = (w & 1) * 64, nW = (w >> 1) * 32;
    // ldmatrix lane address offsets (within a 16-row x 32B k16 window)
    const uint32_t aOff = (uint32_t)(lane & 15) * LDSROW + (uint32_t)(lane >> 4) * 16;
    const uint32_t bOff = (uint32_t)(((lane >> 4) << 3) + (lane & 7)) * LDSROW
                        + (uint32_t)((lane >> 3) & 1) * 16;

    // loader mapping: 512 x 16B chunks per tile, 2 per thread per tile
    const int lrow0 = t >> 2,           lseg0 = t & 3;
    const int lrow1 = (t + 256) >> 2,   lseg1 = t & 3;

    float acc[4][4][4];
#pragma unroll
    for (int i = 0; i < 4; i++)
#pragma unroll
        for (int j = 0; j < 4; j++)
#pragma unroll
            for (int r = 0; r < 4; r++) acc[i][j][r] = 0.f;

    auto load_chunk = [&](int c, int buf) {
        const int kt = c * 32;
        const uint32_t bb = sbase + (uint32_t)buf * BUFB;
        cp16(bb + lrow0 * LDSROW + lseg0 * 16,
             A + (size_t)(mBase + lrow0) * K + kt + lseg0 * 8);
        cp16(bb + lrow1 * LDSROW + lseg1 * 16,
             A + (size_t)(mBase + lrow1) * K + kt + lseg1 * 8);
        cp16(bb + TILEB + lrow0 * LDSROW + lseg0 * 16,
             Bm + (size_t)(nBase + lrow0) * K + kt + lseg0 * 8);
        cp16(bb + TILEB + lrow1 * LDSROW + lseg1 * 16,
             Bm + (size_t)(nBase + lrow1) * K + kt + lseg1 * 8);
    };

    const int NC = K >> 5;

    load_chunk(0, 0); CP_COMMIT();
    load_chunk(1, 1); CP_COMMIT();

    int buf = 0;
    for (int c = 0; c < NC; c++) {
        if (c + 2 < NC) load_chunk(c + 2, (c + 2) % 3);
        CP_COMMIT();               // always commit (possibly empty group)
        CP_WAIT2();                // chunk c's group complete
        __syncthreads();

        const uint32_t bb  = sbase + (uint32_t)buf * BUFB;
        const uint32_t bAh = bb + (uint32_t)mW * LDSROW;
        const uint32_t bBh = bb + TILEB + (uint32_t)nW * LDSROW;

#pragma unroll
        for (int ks = 0; ks < 2; ks++) {
            const uint32_t ko = (uint32_t)ks * 32;
            uint32_t aH[4][4], bH[4][2];
#pragma unroll
            for (int i = 0; i < 4; i++)
                LDSM4(aH[i], bAh + (uint32_t)(i * 16) * LDSROW + ko + aOff);
#pragma unroll
            for (int j = 0; j < 2; j++) {
                uint32_t r[4];
                LDSM4(r, bBh + (uint32_t)(j * 16) * LDSROW + ko + bOff);
                bH[2*j][0] = r[0]; bH[2*j][1] = r[1];
                bH[2*j+1][0] = r[2]; bH[2*j+1][1] = r[3];
            }
#pragma unroll
            for (int i = 0; i < 4; i++)
#pragma unroll
                for (int j = 0; j < 4; j++)
                    MMA16816(acc[i][j], aH[i], bH[j]);
        }
        __syncthreads();
        buf = (buf + 1 == 3) ? 0 : buf + 1;
    }

    // ---------------- epilogue: direct coalesced writes ----------------------
    const int g = lane >> 2, tg2 = (lane & 3) * 2;
    if (OUT_BF16) {
        __nv_bfloat16* oc = Cb + (size_t)blockIdx.z * sC;
#pragma unroll
        for (int i = 0; i < 4; i++) {
            const int r0 = mBase + mW + i * 16 + g, r1 = r0 + 8;
#pragma unroll
            for (int j = 0; j < 4; j++) {
                const int c0 = nBase + nW + j * 8 + tg2;
                float b0 = 0.f, b1 = 0.f;
                if (bias) { b0 = bias[c0]; b1 = bias[c0 + 1]; }
                __nv_bfloat16 h0 = __float2bfloat16(acc[i][j][0] * alpha + b0);
                __nv_bfloat16 h1 = __float2bfloat16(acc[i][j][1] * alpha + b1);
                *(__nv_bfloat162*)(oc + (size_t)r0 * N + c0) = __nv_bfloat162(h0, h1);
                h0 = __float2bfloat16(acc[i][j][2] * alpha + b0);
                h1 = __float2bfloat16(acc[i][j][3] * alpha + b1);
                *(__nv_bfloat162*)(oc + (size_t)r1 * N + c0) = __nv_bfloat162(h0, h1);
            }
        }
    } else {
        float* oc = Cf + (size_t)blockIdx.z * sC;
#pragma unroll
        for (int i = 0; i < 4; i++) {
            const int r0 = mBase + mW + i * 16 + g, r1 = r0 + 8;
#pragma unroll
            for (int j = 0; j < 4; j++) {
                const int c0 = nBase + nW + j * 8 + tg2;
                float b0 = 0.f, b1 = 0.f;
                if (bias) { b0 = bias[c0]; b1 = bias[c0 + 1]; }
                float2 va = make_float2(acc[i][j][0] * alpha + b0, acc[i][j][1] * alpha + b1);
                float2 vb = make_float2(acc[i][j][2] * alpha + b0, acc[i][j][3] * alpha + b1);
                *(float2*)(oc + (size_t)r0 * N + c0) = va;
                *(float2*)(oc + (size_t)r1 * N + c0) = vb;
            }
        }
    }
}

// ---------------- softmax over last dim (2048) -> bf16 p ---------------------
__global__ __launch_bounds__(256)
void softmax_bf16_kernel(const float* __restrict__ attn, const int* __restrict__ am,
                         __nv_bfloat16* __restrict__ phi)
{
    __shared__ float red[256];
    const size_t row = blockIdx.x;
    const int b = (int)(row >> 11);
    const float* a = attn + row * (size_t)S_;
    const int* amb = am + (size_t)b * S_;
    const int t = threadIdx.x;

    float vals[8];
    float mx = -3.0e38f;
#pragma unroll
    for (int i = 0; i < 4; i++) {
        const int idx = t * 2 + i * 512;
        float2 v = *(const float2*)(a + idx);
        if (amb[idx] == 0)     v.x = -10000.f;
        if (amb[idx + 1] == 0) v.y = -10000.f;
        vals[2*i] = v.x; vals[2*i+1] = v.y;
        mx = fmaxf(mx, fmaxf(v.x, v.y));
    }
    red[t] = mx; __syncthreads();
    for (int o = 128; o > 0; o >>= 1) { if (t < o) red[t] = fmaxf(red[t], red[t + o]); __syncthreads(); }
    const float rmax = red[0];
    __syncthreads();

    float se = 0.f;
#pragma unroll
    for (int i = 0; i < 8; i++) { float e = __expf(vals[i] - rmax); vals[i] = e; se += e; }
    red[t] = se; __syncthreads();
    for (int o = 128; o > 0; o >>= 1) { if (t < o) red[t] += red[t + o]; __syncthreads(); }
    const float inv = 1.f / red[0];
#pragma unroll
    for (int i = 0; i < 4; i++) {
        const size_t o = row * (size_t)S_ + t * 2 + i * 512;
        __nv_bfloat16 h[2];
        h[0] = __float2bfloat16(vals[2*i]   * inv);
        h[1] = __float2bfloat16(vals[2*i+1] * inv);
        *(uint32_t*)(phi + o) = *(const uint32_t*)h;
    }
}

// ---------------- per-row LayerNorm + ReLU + dot(W2) -> token score ----------
__global__ __launch_bounds__(128)
void lnscore_kernel(const float* __restrict__ hpre, const float* __restrict__ g1,
                    const float* __restrict__ be1, const float* __restrict__ W2,
                    const float* __restrict__ b2, const int* __restrict__ am,
                    float* __restrict__ ts)
{
    __shared__ float red[128];
    const int row = blockIdx.x, t = threadIdx.x;
    const float* hr = hpre + (size_t)row * HH_;
    const float v0 = hr[t], v1 = hr[t + 128], v2 = hr[t + 256];

    red[t] = v0 + v1 + v2; __syncthreads();
    for (int o = 64; o > 0; o >>= 1) { if (t < o) red[t] += red[t + o]; __syncthreads(); }
    const float mean = red[0] * (1.f / HH_);
    __syncthreads();

    const float d0 = v0 - mean, d1 = v1 - mean, d2 = v2 - mean;
    red[t] = d0 * d0 + d1 * d1 + d2 * d2; __syncthreads();
    for (int o = 64; o > 0; o >>= 1) { if (t < o) red[t] += red[t + o]; __syncthreads(); }
    const float inv = rsqrtf(red[0] * (1.f / HH_) + 1e-5f);
    __syncthreads();

    float sp = fmaxf(d0 * inv * g1[t]       + be1[t],       0.f) * W2[t]
             + fmaxf(d1 * inv * g1[t + 128] + be1[t + 128], 0.f) * W2[t + 128]
             + fmaxf(d2 * inv * g1[t + 256] + be1[t + 256], 0.f) * W2[t + 256];
    red[t] = sp; __syncthreads();
    for (int o = 64; o > 0; o >>= 1) { if (t < o) red[t] += red[t + o]; __syncthreads(); }
    if (t == 0) {
        float v = red[0] + b2[0];
        if (am[row] == 0) v = -10000.f;
        ts[row] = v;
    }
}

// ---------------- span search + mean pooling ---------------------------------
__global__ __launch_bounds__(256)
void span_pool_kernel(const float* __restrict__ ts, const int* __restrict__ am,
                      const float* __restrict__ x, float* __restrict__ pooled)
{
    __shared__ float sc[2048];
    __shared__ float cum[2049];
    __shared__ float part[256];
    __shared__ int   ired[256];
    __shared__ float bvs[256];
    __shared__ int   bis[256];
    __shared__ int   s_start, s_len;

    const int b = blockIdx.x, t = threadIdx.x;

    int vc = 0;
    for (int i = t; i < S_; i += 256) {
        sc[i] = ts[(size_t)b * S_ + i];
        vc += am[(size_t)b * S_ + i];
    }
    ired[t] = vc; __syncthreads();
    for (int o = 128; o > 0; o >>= 1) { if (t < o) ired[t] += ired[t + o]; __syncthreads(); }
    const int vl = ired[0];

    float ps = 0.f;
    for (int i = 0; i < 8; i++) ps += sc[t * 8 + i];
    part[t] = ps; __syncthreads();
    if (t == 0) {
        float run = 0.f;
        for (int i = 0; i < 256; i++) { float v = part[i]; part[i] = run; run += v; }
        cum[2048] = run;
    }
    __syncthreads();
    float run = part[t];
    for (int i = 0; i < 8; i++) { int idx = t * 8 + i; cum[idx] = run; run += sc[idx]; }
    __syncthreads();

    float bestV = -3.0e38f; int bestI = 0x7fffffff;
    for (int flat = t; flat < 18 * S_; flat += 256) {
        const int li = flat >> 11, start = flat & 2047;
        const int L = 3 + li, end = start + L;
        const int endc = end > S_ ? S_ : end;
        const float fL = (float)L;
        float avg = (cum[endc] - cum[start]) / fL + 0.01f * fL / 20.0f;
        if (end > vl) avg = -1e30f;
        if (avg > bestV) { bestV = avg; bestI = flat; }
    }
    bvs[t] = bestV; bis[t] = bestI; __syncthreads();
    for (int o = 128; o > 0; o >>= 1) {
        if (t < o) {
            if (bvs[t + o] > bvs[t] || (bvs[t + o] == bvs[t] && bis[t + o] < bis[t])) {
                bvs[t] = bvs[t + o]; bis[t] = bis[t + o];
            }
        }
        __syncthreads();
    }
    if (t == 0) {
        const int fi = bis[0];
        int start = fi & 2047, L = 3 + (fi >> 11);
        if (vl <= 3) { start = 0; L = vl; }
        s_start = start; s_len = L;
    }
    __syncthreads();

    const int start = s_start, L = s_len;
    const float inv = 1.0f / ((float)L + 1e-6f);
    for (int h = t; h < H_; h += 256) {
        float s = 0.f;
        for (int r = 0; r < L; r++) s += x[((size_t)b * S_ + start + r) * H_ + h];
        pooled[b * H_ + h] = s * inv;
    }
}

// ---------------- classification head ----------------------------------------
__global__ __launch_bounds__(384)
void head_kernel(const float* __restrict__ pooled, const float* __restrict__ x,
                 const float* __restrict__ Wc1, const float* __restrict__ bc1,
                 const float* __restrict__ g2, const float* __restrict__ be2,
                 const float* __restrict__ Wc2, const float* __restrict__ bc2,
                 const float* __restrict__ Mint,
                 const float* __restrict__ Wcls, const float* __restrict__ bcls,
                 float* __restrict__ out)
{
    __shared__ float pl[768];
    __shared__ float hc[384];
    __shared__ float cs[64];
    __shared__ float cp[64];
    __shared__ float red[512];
    const int b = blockIdx.x, t = threadIdx.x;

    for (int i = t; i < H_; i += 384) pl[i] = pooled[b * H_ + i];
    if (t < 128) red[384 + t] = 0.f;
    __syncthreads();

    float acc = bc1[t];
    for (int k = 0; k < H_; k++) acc += pl[k] * Wc1[(size_t)k * HH_ + t];

    red[t] = acc; __syncthreads();
    for (int o = 256; o > 0; o >>= 1) { if (t < o) red[t] += red[t + o]; __syncthreads(); }
    const float mean = red[0] * (1.f / HH_);
    __syncthreads();
    const float d = acc - mean;
    red[t] = d * d; __syncthreads();
    for (int o = 256; o > 0; o >>= 1) { if (t < o) red[t] += red[t + o]; __syncthreads(); }
    const float var = red[0] * (1.f / HH_);
    const float yn = d * rsqrtf(var + 1e-5f) * g2[t] + be2[t];
    hc[t] = fmaxf(yn, 0.f);
    __syncthreads();

    if (t < C_) {
        float c = bc2[t];
        for (int k = 0; k < HH_; k++) c += hc[k] * Wc2[(size_t)k * C_ + t];
        cs[t] = c;
    }
    __syncthreads();
    if (t < C_) {
        float add = cs[t];
        for (int i = 0; i < C_; i++) {
            const float m = 0.5f * (Mint[i * C_ + t] + Mint[t * C_ + i]);
            const float sg = 1.f / (1.f + expf(-m));
            add += cs[i] * sg;
        }
        cp[t] = 1.f / (1.f + expf(-add));
    }
    __syncthreads();
    if (t < L_) {
        float lg = bcls[t];
        for (int c = 0; c < C_; c++) lg += cp[c] * Wcls[c * L_ + t];
        const float* xr = x + (size_t)b * S_ * H_;
        for (int h = 0; h < H_; h++) lg += xr[h] * Wcls[(C_ + h) * L_ + t];
        out[b * L_ + t] = lg;
    }
}

// ---------------------------- launcher ---------------------------------------
extern "C" void kernel_launch(void* const* d_in, const int* in_sizes, int n_in,
                              void* d_out, int out_size)
{
    const float* x    = (const float*)d_in[0];
    const int*   am   = (const int*)  d_in[1];
    const float* Wq   = (const float*)d_in[2];
    const float* bq   = (const float*)d_in[3];
    const float* Wk   = (const float*)d_in[4];
    const float* bk   = (const float*)d_in[5];
    const float* W1   = (const float*)d_in[6];
    const float* b1   = (const float*)d_in[7];
    const float* g1   = (const float*)d_in[8];
    const float* be1  = (const float*)d_in[9];
    const float* W2   = (const float*)d_in[10];
    const float* b2   = (const float*)d_in[11];
    const float* Wc1  = (const float*)d_in[12];
    const float* bc1  = (const float*)d_in[13];
    const float* g2   = (const float*)d_in[14];
    const float* be2  = (const float*)d_in[15];
    const float* Wc2  = (const float*)d_in[16];
    const float* bc2  = (const float*)d_in[17];
    const float* Mint = (const float*)d_in[18];
    const float* Wcls = (const float*)d_in[19];
    const float* bcls = (const float*)d_in[20];
    float* out = (float*)d_out;

    __nv_bfloat16 *xhi, *qhi, *khi, *phi, *yThi, *WqThi, *WkThi, *W1Thi;
    float *ap, *yp, *hp, *tp, *pp;
    cudaGetSymbolAddress((void**)&xhi,  g_xhi);
    cudaGetSymbolAddress((void**)&qhi,  g_qhi);
    cudaGetSymbolAddress((void**)&khi,  g_khi);
    cudaGetSymbolAddress((void**)&phi,  g_phi);
    cudaGetSymbolAddress((void**)&yThi, g_yThi);
    cudaGetSymbolAddress((void**)&WqThi, g_WqThi);
    cudaGetSymbolAddress((void**)&WkThi, g_WkThi);
    cudaGetSymbolAddress((void**)&W1Thi, g_W1Thi);
    cudaGetSymbolAddress((void**)&ap, g_attn);
    cudaGetSymbolAddress((void**)&yp, g_y);
    cudaGetSymbolAddress((void**)&hp, g_hpre);
    cudaGetSymbolAddress((void**)&tp, g_ts);
    cudaGetSymbolAddress((void**)&pp, g_pool);

    cudaFuncSetAttribute(gemm_bf16<true>,  cudaFuncAttributeMaxDynamicSharedMemorySize, GEMM_SMEM);
    cudaFuncSetAttribute(gemm_bf16<false>, cudaFuncAttributeMaxDynamicSharedMemorySize, GEMM_SMEM);

    // 0. weight transposes: W [768,384] -> W^T [384,768] bf16
    transpose_bf16_kernel<<<dim3(24, 12, 1), dim3(32, 8)>>>(Wq, WqThi, H_, HH_);
    transpose_bf16_kernel<<<dim3(24, 12, 1), dim3(32, 8)>>>(Wk, WkThi, H_, HH_);
    transpose_bf16_kernel<<<dim3(24, 12, 1), dim3(32, 8)>>>(W1, W1Thi, H_, HH_);

    // 1. x -> bf16
    cvt_bf16_kernel<<<25165824 / 2048, 256>>>(x, xhi);

    // 2. projections: q/k -> bf16 + bias; y = x@W1 + b1 -> fp32
    gemm_bf16<true><<<dim3(3, 256, 1), 256, GEMM_SMEM>>>(
        xhi, WqThi, nullptr, qhi, bq, HH_, H_, 1.f, 0, 0, 0);
    gemm_bf16<true><<<dim3(3, 256, 1), 256, GEMM_SMEM>>>(
        xhi, WkThi, nullptr, khi, bk, HH_, H_, 1.f, 0, 0, 0);
    gemm_bf16<false><<<dim3(3, 256, 1), 256, GEMM_SMEM>>>(
        xhi, W1Thi, yp, nullptr, b1, HH_, H_, 1.f, 0, 0, 0);

    // 3. y^T per batch: y [B,S,HH] -> yT [B,HH,S] bf16
    transpose_bf16_kernel<<<dim3(64, 12, 16), dim3(32, 8)>>>(yp, yThi, S_, HH_);

    // 4. attn = q @ k^T / sqrt(HH) -> fp32
    const float alpha = 1.0f / sqrtf((float)HH_);
    gemm_bf16<false><<<dim3(16, 16, B_), 256, GEMM_SMEM>>>(
        qhi, khi, ap, nullptr, nullptr, S_, HH_, alpha,
        (size_t)S_ * HH_, (size_t)S_ * HH_, (size_t)S_ * S_);

    // 5. softmax -> bf16 p
    softmax_bf16_kernel<<<B_ * S_, 256>>>(ap, am, phi);

    // 6. h_pre = p @ y: [2048,2048] x yT[384,2048] -> fp32
    gemm_bf16<false><<<dim3(3, 16, B_), 256, GEMM_SMEM>>>(
        phi, yThi, hp, nullptr, nullptr, HH_, S_, 1.f,
        (size_t)S_ * S_, (size_t)HH_ * S_, (size_t)S_ * HH_);

    // 7-9. scores, span+pool, head
    lnscore_kernel<<<B_ * S_, 128>>>(hp, g1, be1, W2, b2, am, tp);
    span_pool_kernel<<<B_, 256>>>(tp, am, x, pp);
    head_kernel<<<B_, 384>>>(pp, x, Wc1, bc1, g2, be2, Wc2, bc2, Mint, Wcls, bcls, out);
}

// round 9
// speedup vs baseline: 6.1317x; 1.0410x over previous
#include <cuda_runtime.h>
#include <cuda_bf16.h>
#include <math.h>
#include <stdint.h>

// Problem constants
#define B_  16
#define S_  2048
#define H_  768
#define HH_ 384
#define C_  64
#define L_  4

// ---------------- scratch (static __device__ arrays; no allocation) ----------
__device__ __nv_bfloat16 g_xhi [25165824];     // x bf16        [B*S,H]
__device__ __nv_bfloat16 g_qhi [12582912];     // q bf16        [B*S,HH]
__device__ __nv_bfloat16 g_khi [12582912];     // k bf16        [B*S,HH]
__device__ __nv_bfloat16 g_phi [67108864];     // p=exp(attn) bf16 [B,S,S]
__device__ unsigned long long g_Zq[32768];     // fixed-point row sums of p
__device__ float         g_y   [12582912];     // y=x@W1+b1     [B*S,HH]
__device__ __nv_bfloat16 g_yThi[12582912];     // y^T bf16      [B,HH,S]
__device__ float         g_hpre[12582912];     // h_pre (unnormalized) [B*S,HH]
__device__ float         g_ts  [32768];
__device__ float         g_pool[12288];
__device__ __nv_bfloat16 g_WqThi[294912];      // Wq^T bf16 [HH,H]
__device__ __nv_bfloat16 g_WkThi[294912];
__device__ __nv_bfloat16 g_W1Thi[294912];

// ============================ PTX helpers ====================================
__device__ __forceinline__ uint32_t smem_u32(const void* p) {
    return (uint32_t)__cvta_generic_to_shared(p);
}

__device__ __forceinline__ void cp16(uint32_t dst, const void* src) {
    asm volatile("cp.async.cg.shared.global [%0], [%1], 16;" :: "r"(dst), "l"(src));
}
#define CP_COMMIT() asm volatile("cp.async.commit_group;" ::: "memory")
#define CP_WAIT2()  asm volatile("cp.async.wait_group 2;" ::: "memory")

#define LDSM4(r, addr) \
    asm volatile("ldmatrix.sync.aligned.m8n8.x4.shared.b16 {%0,%1,%2,%3}, [%4];" \
        : "=r"((r)[0]), "=r"((r)[1]), "=r"((r)[2]), "=r"((r)[3]) : "r"(addr))

#define MMA16816(d, a, b) \
    asm volatile("mma.sync.aligned.m16n8k16.row.col.f32.bf16.bf16.f32 " \
        "{%0,%1,%2,%3}, {%4,%5,%6,%7}, {%8,%9}, {%0,%1,%2,%3};" \
        : "+f"((d)[0]), "+f"((d)[1]), "+f"((d)[2]), "+f"((d)[3]) \
        : "r"((a)[0]), "r"((a)[1]), "r"((a)[2]), "r"((a)[3]), \
          "r"((b)[0]), "r"((b)[1]))

// SMEM tile geometry: 128 rows x 32 bf16 (64B data) padded to 80B/row
#define LDSROW 80
#define TILEB  (128 * LDSROW)         // 10240 B
#define BUFB   (2 * TILEB)            // A, B tiles = 20480 B
#define GEMM_SMEM (3 * BUFB)          // 3-stage pipeline = 61440 B

#define ZSCALE 1048576.0f             // 2^20 fixed point for deterministic Z

// =============== conversions ================================================
__global__ __launch_bounds__(256)
void cvt_bf16_kernel(const float* __restrict__ src, __nv_bfloat16* __restrict__ hi)
{
    const size_t i = ((size_t)blockIdx.x * 256 + threadIdx.x) * 8;
    float4 v0 = *(const float4*)(src + i);
    float4 v1 = *(const float4*)(src + i + 4);
    __nv_bfloat16 h[8];
    h[0] = __float2bfloat16(v0.x); h[1] = __float2bfloat16(v0.y);
    h[2] = __float2bfloat16(v0.z); h[3] = __float2bfloat16(v0.w);
    h[4] = __float2bfloat16(v1.x); h[5] = __float2bfloat16(v1.y);
    h[6] = __float2bfloat16(v1.z); h[7] = __float2bfloat16(v1.w);
    *(uint4*)(hi + i) = *(const uint4*)h;
}

// in [R, C] -> out [C, R] bf16; per-z offset = z*R*C
__global__ __launch_bounds__(256)
void transpose_bf16_kernel(const float* __restrict__ in, __nv_bfloat16* __restrict__ ohi,
                           int R, int Cc)
{
    __shared__ float tile[32][33];
    const size_t zoff = (size_t)blockIdx.z * R * Cc;
    in += zoff; ohi += zoff;
    const int r0 = blockIdx.x * 32, c0 = blockIdx.y * 32;
    const int tx = threadIdx.x, ty = threadIdx.y;   // block (32,8)
#pragma unroll
    for (int j = 0; j < 32; j += 8)
        tile[ty + j][tx] = in[(size_t)(r0 + ty + j) * Cc + c0 + tx];
    __syncthreads();
    const int t = ty * 32 + tx;     // 0..255
#pragma unroll
    for (int pidx = t; pidx < 512; pidx += 256) {
        const int oc = pidx >> 4;            // output row (= input col) 0..31
        const int pr = (pidx & 15) * 2;      // input row pair
        __nv_bfloat16 h[2];
        h[0] = __float2bfloat16(tile[pr][oc]);
        h[1] = __float2bfloat16(tile[pr + 1][oc]);
        size_t o = (size_t)(c0 + oc) * R + r0 + pr;
        *(uint32_t*)(ohi + o) = *(const uint32_t*)h;
    }
}

// =============== warp-MMA bf16 GEMM =========================================
// C[M,N] = alpha * A @ B^T (+bias). A:[M,K] K-major bf16, B:[N,K] K-major bf16.
// MODE 0: fp32 out. MODE 1: bf16 out (+bias). MODE 2: p=exp(alpha*acc) masked
//   -> bf16 out, plus deterministic fixed-point row-sum atomics into Zq.
// CTA tile 128x128, 8 warps of 64x32, K chunk 32, 3-stage cp.async pipeline.
template<int MODE>
__global__ __launch_bounds__(256)
void gemm_bf16(const __nv_bfloat16* __restrict__ A, const __nv_bfloat16* __restrict__ Bm,
               float* __restrict__ Cf, __nv_bfloat16* __restrict__ Cb,
               const float* __restrict__ bias,
               const int* __restrict__ am, unsigned long long* __restrict__ Zq,
               int N, int K, float alpha, size_t sA, size_t sB, size_t sC)
{
    extern __shared__ char smem[];
    const uint32_t sbase = smem_u32(smem);
    const int t = threadIdx.x;
    const int mBase = blockIdx.y * 128, nBase = blockIdx.x * 128;
    A  += (size_t)blockIdx.z * sA;
    Bm += (size_t)blockIdx.z * sB;

    const int lane = t & 31, w = t >> 5;
    const int mW = (w & 1) * 64, nW = (w >> 1) * 32;
    const uint32_t aOff = (uint32_t)(lane & 15) * LDSROW + (uint32_t)(lane >> 4) * 16;
    const uint32_t bOff = (uint32_t)(((lane >> 4) << 3) + (lane & 7)) * LDSROW
                        + (uint32_t)((lane >> 3) & 1) * 16;

    const int lrow0 = t >> 2,           lseg0 = t & 3;
    const int lrow1 = (t + 256) >> 2,   lseg1 = t & 3;

    float acc[4][4][4];
#pragma unroll
    for (int i = 0; i < 4; i++)
#pragma unroll
        for (int j = 0; j < 4; j++)
#pragma unroll
            for (int r = 0; r < 4; r++) acc[i][j][r] = 0.f;

    auto load_chunk = [&](int c, int buf) {
        const int kt = c * 32;
        const uint32_t bb = sbase + (uint32_t)buf * BUFB;
        cp16(bb + lrow0 * LDSROW + lseg0 * 16,
             A + (size_t)(mBase + lrow0) * K + kt + lseg0 * 8);
        cp16(bb + lrow1 * LDSROW + lseg1 * 16,
             A + (size_t)(mBase + lrow1) * K + kt + lseg1 * 8);
        cp16(bb + TILEB + lrow0 * LDSROW + lseg0 * 16,
             Bm + (size_t)(nBase + lrow0) * K + kt + lseg0 * 8);
        cp16(bb + TILEB + lrow1 * LDSROW + lseg1 * 16,
             Bm + (size_t)(nBase + lrow1) * K + kt + lseg1 * 8);
    };

    const int NC = K >> 5;

    load_chunk(0, 0); CP_COMMIT();
    load_chunk(1, 1); CP_COMMIT();

    int buf = 0;
    for (int c = 0; c < NC; c++) {
        if (c + 2 < NC) load_chunk(c + 2, (c + 2) % 3);
        CP_COMMIT();
        CP_WAIT2();
        __syncthreads();

        const uint32_t bb  = sbase + (uint32_t)buf * BUFB;
        const uint32_t bAh = bb + (uint32_t)mW * LDSROW;
        const uint32_t bBh = bb + TILEB + (uint32_t)nW * LDSROW;

#pragma unroll
        for (int ks = 0; ks < 2; ks++) {
            const uint32_t ko = (uint32_t)ks * 32;
            uint32_t aH[4][4], bH[4][2];
#pragma unroll
            for (int i = 0; i < 4; i++)
                LDSM4(aH[i], bAh + (uint32_t)(i * 16) * LDSROW + ko + aOff);
#pragma unroll
            for (int j = 0; j < 2; j++) {
                uint32_t r[4];
                LDSM4(r, bBh + (uint32_t)(j * 16) * LDSROW + ko + bOff);
                bH[2*j][0] = r[0]; bH[2*j][1] = r[1];
                bH[2*j+1][0] = r[2]; bH[2*j+1][1] = r[3];
            }
#pragma unroll
            for (int i = 0; i < 4; i++)
#pragma unroll
                for (int j = 0; j < 4; j++)
                    MMA16816(acc[i][j], aH[i], bH[j]);
        }
        __syncthreads();
        buf = (buf + 1 == 3) ? 0 : buf + 1;
    }

    // ---------------- epilogue ----------------------------------------------
    const int g = lane >> 2, tg2 = (lane & 3) * 2;
    if (MODE == 2) {
        // p = exp(alpha*acc) with key mask; deterministic fixed-point Z row sums
        __nv_bfloat16* oc = Cb + (size_t)blockIdx.z * sC;
        const int* amb = am + (size_t)blockIdx.z * S_;
        unsigned long long* zb = Zq + (size_t)blockIdx.z * S_;
#pragma unroll
        for (int i = 0; i < 4; i++) {
            const int r0 = mBase + mW + i * 16 + g, r1 = r0 + 8;
            float s0 = 0.f, s1 = 0.f;
#pragma unroll
            for (int j = 0; j < 4; j++) {
                const int c0 = nBase + nW + j * 8 + tg2;
                const bool m0 = amb[c0] != 0, m1 = amb[c0 + 1] != 0;
                float e00 = m0 ? __expf(acc[i][j][0] * alpha) : 0.f;
                float e01 = m1 ? __expf(acc[i][j][1] * alpha) : 0.f;
                float e10 = m0 ? __expf(acc[i][j][2] * alpha) : 0.f;
                float e11 = m1 ? __expf(acc[i][j][3] * alpha) : 0.f;
                s0 += e00 + e01; s1 += e10 + e11;
                *(__nv_bfloat162*)(oc + (size_t)r0 * N + c0) =
                    __nv_bfloat162(__float2bfloat16(e00), __float2bfloat16(e01));
                *(__nv_bfloat162*)(oc + (size_t)r1 * N + c0) =
                    __nv_bfloat162(__float2bfloat16(e10), __float2bfloat16(e11));
            }
            atomicAdd(zb + r0, (unsigned long long)llrintf(s0 * ZSCALE));
            atomicAdd(zb + r1, (unsigned long long)llrintf(s1 * ZSCALE));
        }
    } else if (MODE == 1) {
        __nv_bfloat16* oc = Cb + (size_t)blockIdx.z * sC;
#pragma unroll
        for (int i = 0; i < 4; i++) {
            const int r0 = mBase + mW + i * 16 + g, r1 = r0 + 8;
#pragma unroll
            for (int j = 0; j < 4; j++) {
                const int c0 = nBase + nW + j * 8 + tg2;
                float b0 = 0.f, b1 = 0.f;
                if (bias) { b0 = bias[c0]; b1 = bias[c0 + 1]; }
                __nv_bfloat16 h0 = __float2bfloat16(acc[i][j][0] * alpha + b0);
                __nv_bfloat16 h1 = __float2bfloat16(acc[i][j][1] * alpha + b1);
                *(__nv_bfloat162*)(oc + (size_t)r0 * N + c0) = __nv_bfloat162(h0, h1);
                h0 = __float2bfloat16(acc[i][j][2] * alpha + b0);
                h1 = __float2bfloat16(acc[i][j][3] * alpha + b1);
                *(__nv_bfloat162*)(oc + (size_t)r1 * N + c0) = __nv_bfloat162(h0, h1);
            }
        }
    } else {
        float* oc = Cf + (size_t)blockIdx.z * sC;
#pragma unroll
        for (int i = 0; i < 4; i++) {
            const int r0 = mBase + mW + i * 16 + g, r1 = r0 + 8;
#pragma unroll
            for (int j = 0; j < 4; j++) {
                const int c0 = nBase + nW + j * 8 + tg2;
                float b0 = 0.f, b1 = 0.f;
                if (bias) { b0 = bias[c0]; b1 = bias[c0 + 1]; }
                float2 va = make_float2(acc[i][j][0] * alpha + b0, acc[i][j][1] * alpha + b1);
                float2 vb = make_float2(acc[i][j][2] * alpha + b0, acc[i][j][3] * alpha + b1);
                *(float2*)(oc + (size_t)r0 * N + c0) = va;
                *(float2*)(oc + (size_t)r1 * N + c0) = vb;
            }
        }
    }
}

// ------- per-row 1/Z rescale + LayerNorm + ReLU + dot(W2) -> token score -----
__global__ __launch_bounds__(128)
void lnscore_kernel(const float* __restrict__ hpre, const unsigned long long* __restrict__ zq,
                    const float* __restrict__ g1, const float* __restrict__ be1,
                    const float* __restrict__ W2, const float* __restrict__ b2,
                    const int* __restrict__ am, float* __restrict__ ts)
{
    __shared__ float red[128];
    const int row = blockIdx.x, t = threadIdx.x;
    const float zf = (float)zq[row];
    const float invZ = zf > 0.f ? (ZSCALE / zf) : 0.f;
    const float* hr = hpre + (size_t)row * HH_;
    const float v0 = hr[t] * invZ, v1 = hr[t + 128] * invZ, v2 = hr[t + 256] * invZ;

    red[t] = v0 + v1 + v2; __syncthreads();
    for (int o = 64; o > 0; o >>= 1) { if (t < o) red[t] += red[t + o]; __syncthreads(); }
    const float mean = red[0] * (1.f / HH_);
    __syncthreads();

    const float d0 = v0 - mean, d1 = v1 - mean, d2 = v2 - mean;
    red[t] = d0 * d0 + d1 * d1 + d2 * d2; __syncthreads();
    for (int o = 64; o > 0; o >>= 1) { if (t < o) red[t] += red[t + o]; __syncthreads(); }
    const float inv = rsqrtf(red[0] * (1.f / HH_) + 1e-5f);
    __syncthreads();

    float sp = fmaxf(d0 * inv * g1[t]       + be1[t],       0.f) * W2[t]
             + fmaxf(d1 * inv * g1[t + 128] + be1[t + 128], 0.f) * W2[t + 128]
             + fmaxf(d2 * inv * g1[t + 256] + be1[t + 256], 0.f) * W2[t + 256];
    red[t] = sp; __syncthreads();
    for (int o = 64; o > 0; o >>= 1) { if (t < o) red[t] += red[t + o]; __syncthreads(); }
    if (t == 0) {
        float v = red[0] + b2[0];
        if (am[row] == 0) v = -10000.f;
        ts[row] = v;
    }
}

// ---------------- span search + mean pooling ---------------------------------
__global__ __launch_bounds__(256)
void span_pool_kernel(const float* __restrict__ ts, const int* __restrict__ am,
                      const float* __restrict__ x, float* __restrict__ pooled)
{
    __shared__ float sc[2048];
    __shared__ float cum[2049];
    __shared__ float part[256];
    __shared__ int   ired[256];
    __shared__ float bvs[256];
    __shared__ int   bis[256];
    __shared__ int   s_start, s_len;

    const int b = blockIdx.x, t = threadIdx.x;

    int vc = 0;
    for (int i = t; i < S_; i += 256) {
        sc[i] = ts[(size_t)b * S_ + i];
        vc += am[(size_t)b * S_ + i];
    }
    ired[t] = vc; __syncthreads();
    for (int o = 128; o > 0; o >>= 1) { if (t < o) ired[t] += ired[t + o]; __syncthreads(); }
    const int vl = ired[0];

    float ps = 0.f;
    for (int i = 0; i < 8; i++) ps += sc[t * 8 + i];
    part[t] = ps; __syncthreads();
    if (t == 0) {
        float run = 0.f;
        for (int i = 0; i < 256; i++) { float v = part[i]; part[i] = run; run += v; }
        cum[2048] = run;
    }
    __syncthreads();
    float run = part[t];
    for (int i = 0; i < 8; i++) { int idx = t * 8 + i; cum[idx] = run; run += sc[idx]; }
    __syncthreads();

    float bestV = -3.0e38f; int bestI = 0x7fffffff;
    for (int flat = t; flat < 18 * S_; flat += 256) {
        const int li = flat >> 11, start = flat & 2047;
        const int L = 3 + li, end = start + L;
        const int endc = end > S_ ? S_ : end;
        const float fL = (float)L;
        float avg = (cum[endc] - cum[start]) / fL + 0.01f * fL / 20.0f;
        if (end > vl) avg = -1e30f;
        if (avg > bestV) { bestV = avg; bestI = flat; }
    }
    bvs[t] = bestV; bis[t] = bestI; __syncthreads();
    for (int o = 128; o > 0; o >>= 1) {
        if (t < o) {
            if (bvs[t + o] > bvs[t] || (bvs[t + o] == bvs[t] && bis[t + o] < bis[t])) {
                bvs[t] = bvs[t + o]; bis[t] = bis[t + o];
            }
        }
        __syncthreads();
    }
    if (t == 0) {
        const int fi = bis[0];
        int start = fi & 2047, L = 3 + (fi >> 11);
        if (vl <= 3) { start = 0; L = vl; }
        s_start = start; s_len = L;
    }
    __syncthreads();

    const int start = s_start, L = s_len;
    const float inv = 1.0f / ((float)L + 1e-6f);
    for (int h = t; h < H_; h += 256) {
        float s = 0.f;
        for (int r = 0; r < L; r++) s += x[((size_t)b * S_ + start + r) * H_ + h];
        pooled[b * H_ + h] = s * inv;
    }
}

// ---------------- classification head ----------------------------------------
__global__ __launch_bounds__(384)
void head_kernel(const float* __restrict__ pooled, const float* __restrict__ x,
                 const float* __restrict__ Wc1, const float* __restrict__ bc1,
                 const float* __restrict__ g2, const float* __restrict__ be2,
                 const float* __restrict__ Wc2, const float* __restrict__ bc2,
                 const float* __restrict__ Mint,
                 const float* __restrict__ Wcls, const float* __restrict__ bcls,
                 float* __restrict__ out)
{
    __shared__ float pl[768];
    __shared__ float hc[384];
    __shared__ float cs[64];
    __shared__ float cp[64];
    __shared__ float red[512];
    const int b = blockIdx.x, t = threadIdx.x;

    for (int i = t; i < H_; i += 384) pl[i] = pooled[b * H_ + i];
    if (t < 128) red[384 + t] = 0.f;
    __syncthreads();

    float acc = bc1[t];
    for (int k = 0; k < H_; k++) acc += pl[k] * Wc1[(size_t)k * HH_ + t];

    red[t] = acc; __syncthreads();
    for (int o = 256; o > 0; o >>= 1) { if (t < o) red[t] += red[t + o]; __syncthreads(); }
    const float mean = red[0] * (1.f / HH_);
    __syncthreads();
    const float d = acc - mean;
    red[t] = d * d; __syncthreads();
    for (int o = 256; o > 0; o >>= 1) { if (t < o) red[t] += red[t + o]; __syncthreads(); }
    const float var = red[0] * (1.f / HH_);
    const float yn = d * rsqrtf(var + 1e-5f) * g2[t] + be2[t];
    hc[t] = fmaxf(yn, 0.f);
    __syncthreads();

    if (t < C_) {
        float c = bc2[t];
        for (int k = 0; k < HH_; k++) c += hc[k] * Wc2[(size_t)k * C_ + t];
        cs[t] = c;
    }
    __syncthreads();
    if (t < C_) {
        float add = cs[t];
        for (int i = 0; i < C_; i++) {
            const float m = 0.5f * (Mint[i * C_ + t] + Mint[t * C_ + i]);
            const float sg = 1.f / (1.f + expf(-m));
            add += cs[i] * sg;
        }
        cp[t] = 1.f / (1.f + expf(-add));
    }
    __syncthreads();
    if (t < L_) {
        float lg = bcls[t];
        for (int c = 0; c < C_; c++) lg += cp[c] * Wcls[c * L_ + t];
        const float* xr = x + (size_t)b * S_ * H_;
        for (int h = 0; h < H_; h++) lg += xr[h] * Wcls[(C_ + h) * L_ + t];
        out[b * L_ + t] = lg;
    }
}

// ---------------------------- launcher ---------------------------------------
extern "C" void kernel_launch(void* const* d_in, const int* in_sizes, int n_in,
                              void* d_out, int out_size)
{
    const float* x    = (const float*)d_in[0];
    const int*   am   = (const int*)  d_in[1];
    const float* Wq   = (const float*)d_in[2];
    const float* bq   = (const float*)d_in[3];
    const float* Wk   = (const float*)d_in[4];
    const float* bk   = (const float*)d_in[5];
    const float* W1   = (const float*)d_in[6];
    const float* b1   = (const float*)d_in[7];
    const float* g1   = (const float*)d_in[8];
    const float* be1  = (const float*)d_in[9];
    const float* W2   = (const float*)d_in[10];
    const float* b2   = (const float*)d_in[11];
    const float* Wc1  = (const float*)d_in[12];
    const float* bc1  = (const float*)d_in[13];
    const float* g2   = (const float*)d_in[14];
    const float* be2  = (const float*)d_in[15];
    const float* Wc2  = (const float*)d_in[16];
    const float* bc2  = (const float*)d_in[17];
    const float* Mint = (const float*)d_in[18];
    const float* Wcls = (const float*)d_in[19];
    const float* bcls = (const float*)d_in[20];
    float* out = (float*)d_out;

    __nv_bfloat16 *xhi, *qhi, *khi, *phi, *yThi, *WqThi, *WkThi, *W1Thi;
    unsigned long long* zq;
    float *yp, *hp, *tp, *pp;
    cudaGetSymbolAddress((void**)&xhi,  g_xhi);
    cudaGetSymbolAddress((void**)&qhi,  g_qhi);
    cudaGetSymbolAddress((void**)&khi,  g_khi);
    cudaGetSymbolAddress((void**)&phi,  g_phi);
    cudaGetSymbolAddress((void**)&zq,   g_Zq);
    cudaGetSymbolAddress((void**)&yThi, g_yThi);
    cudaGetSymbolAddress((void**)&WqThi, g_WqThi);
    cudaGetSymbolAddress((void**)&WkThi, g_WkThi);
    cudaGetSymbolAddress((void**)&W1Thi, g_W1Thi);
    cudaGetSymbolAddress((void**)&yp, g_y);
    cudaGetSymbolAddress((void**)&hp, g_hpre);
    cudaGetSymbolAddress((void**)&tp, g_ts);
    cudaGetSymbolAddress((void**)&pp, g_pool);

    cudaFuncSetAttribute(gemm_bf16<0>, cudaFuncAttributeMaxDynamicSharedMemorySize, GEMM_SMEM);
    cudaFuncSetAttribute(gemm_bf16<1>, cudaFuncAttributeMaxDynamicSharedMemorySize, GEMM_SMEM);
    cudaFuncSetAttribute(gemm_bf16<2>, cudaFuncAttributeMaxDynamicSharedMemorySize, GEMM_SMEM);

    // 0. zero Z accumulators (graph-capturable async memset)
    cudaMemsetAsync(zq, 0, 32768 * sizeof(unsigned long long));

    // 1. weight transposes: W [768,384] -> W^T [384,768] bf16
    transpose_bf16_kernel<<<dim3(24, 12, 1), dim3(32, 8)>>>(Wq, WqThi, H_, HH_);
    transpose_bf16_kernel<<<dim3(24, 12, 1), dim3(32, 8)>>>(Wk, WkThi, H_, HH_);
    transpose_bf16_kernel<<<dim3(24, 12, 1), dim3(32, 8)>>>(W1, W1Thi, H_, HH_);

    // 2. x -> bf16
    cvt_bf16_kernel<<<25165824 / 2048, 256>>>(x, xhi);

    // 3. projections: q/k -> bf16 + bias; y = x@W1 + b1 -> fp32
    gemm_bf16<1><<<dim3(3, 256, 1), 256, GEMM_SMEM>>>(
        xhi, WqThi, nullptr, qhi, bq, nullptr, nullptr, HH_, H_, 1.f, 0, 0, 0);
    gemm_bf16<1><<<dim3(3, 256, 1), 256, GEMM_SMEM>>>(
        xhi, WkThi, nullptr, khi, bk, nullptr, nullptr, HH_, H_, 1.f, 0, 0, 0);
    gemm_bf16<0><<<dim3(3, 256, 1), 256, GEMM_SMEM>>>(
        xhi, W1Thi, yp, nullptr, b1, nullptr, nullptr, HH_, H_, 1.f, 0, 0, 0);

    // 4. y^T per batch: y [B,S,HH] -> yT [B,HH,S] bf16
    transpose_bf16_kernel<<<dim3(64, 12, 16), dim3(32, 8)>>>(yp, yThi, S_, HH_);

    // 5. fused attn+exp: p = exp(q@k^T/sqrt(HH)) masked -> bf16, Z row sums
    const float alpha = 1.0f / sqrtf((float)HH_);
    gemm_bf16<2><<<dim3(16, 16, B_), 256, GEMM_SMEM>>>(
        qhi, khi, nullptr, phi, nullptr, am, zq, S_, HH_, alpha,
        (size_t)S_ * HH_, (size_t)S_ * HH_, (size_t)S_ * S_);

    // 6. h_pre_unnorm = p @ y: [2048,2048] x yT[384,2048] -> fp32
    gemm_bf16<0><<<dim3(3, 16, B_), 256, GEMM_SMEM>>>(
        phi, yThi, hp, nullptr, nullptr, nullptr, nullptr, HH_, S_, 1.f,
        (size_t)S_ * S_, (size_t)HH_ * S_, (size_t)S_ * HH_);

    // 7-9. scores (with 1/Z rescale), span+pool, head
    lnscore_kernel<<<B_ * S_, 128>>>(hp, zq, g1, be1, W2, b2, am, tp);
    span_pool_kernel<<<B_, 256>>>(tp, am, x, pp);
    head_kernel<<<B_, 384>>>(pp, x, Wc1, bc1, g2, be2, Wc2, bc2, Mint, Wcls, bcls, out);
}

// round 10
// speedup vs baseline: 6.5428x; 1.0670x over previous
#include <cuda_runtime.h>
#include <cuda_bf16.h>
#include <math.h>
#include <stdint.h>

// Problem constants
#define B_  16
#define S_  2048
#define H_  768
#define HH_ 384
#define C_  64
#define L_  4

// ---------------- scratch (static __device__ arrays; no allocation) ----------
__device__ __nv_bfloat16 g_xhi [25165824];     // x bf16        [B*S,H]
__device__ __nv_bfloat16 g_qhi [12582912];     // q bf16        [B*S,HH]
__device__ __nv_bfloat16 g_khi [12582912];     // k bf16        [B*S,HH]
__device__ __nv_bfloat16 g_yhi [12582912];     // y bf16        [B*S,HH]
__device__ __nv_bfloat16 g_phi [67108864];     // p=exp(attn) bf16 [B,S,S]
__device__ unsigned long long g_Zq[32768];     // fixed-point row sums of p
__device__ __nv_bfloat16 g_yThi[12582912];     // y^T bf16      [B,HH,S]
__device__ float         g_hpre[12582912];     // h_pre (unnormalized) [B*S,HH]
__device__ float         g_ts  [32768];
__device__ float         g_pool[12288];
__device__ __nv_bfloat16 g_Wcat[884736];       // [Wq|Wk|W1]^T bf16 [1152,768]

// ============================ PTX helpers ====================================
__device__ __forceinline__ uint32_t smem_u32(const void* p) {
    return (uint32_t)__cvta_generic_to_shared(p);
}

__device__ __forceinline__ void cp16(uint32_t dst, const void* src) {
    asm volatile("cp.async.cg.shared.global [%0], [%1], 16;" :: "r"(dst), "l"(src));
}
#define CP_COMMIT() asm volatile("cp.async.commit_group;" ::: "memory")
#define CP_WAIT2()  asm volatile("cp.async.wait_group 2;" ::: "memory")

#define LDSM4(r, addr) \
    asm volatile("ldmatrix.sync.aligned.m8n8.x4.shared.b16 {%0,%1,%2,%3}, [%4];" \
        : "=r"((r)[0]), "=r"((r)[1]), "=r"((r)[2]), "=r"((r)[3]) : "r"(addr))

#define MMA16816(d, a, b) \
    asm volatile("mma.sync.aligned.m16n8k16.row.col.f32.bf16.bf16.f32 " \
        "{%0,%1,%2,%3}, {%4,%5,%6,%7}, {%8,%9}, {%0,%1,%2,%3};" \
        : "+f"((d)[0]), "+f"((d)[1]), "+f"((d)[2]), "+f"((d)[3]) \
        : "r"((a)[0]), "r"((a)[1]), "r"((a)[2]), "r"((a)[3]), \
          "r"((b)[0]), "r"((b)[1]))

// SMEM tile geometry: 128 rows x 32 bf16 (64B data) padded to 80B/row
#define LDSROW 80
#define TILEB  (128 * LDSROW)         // 10240 B
#define BUFB   (2 * TILEB)            // A, B tiles = 20480 B
#define GEMM_SMEM (3 * BUFB)          // 3-stage pipeline = 61440 B

#define ZSCALE 1048576.0f             // 2^20 fixed point for deterministic Z

// =============== conversions ================================================
__global__ __launch_bounds__(256)
void cvt_bf16_kernel(const float* __restrict__ src, __nv_bfloat16* __restrict__ hi)
{
    const size_t i = ((size_t)blockIdx.x * 256 + threadIdx.x) * 8;
    float4 v0 = *(const float4*)(src + i);
    float4 v1 = *(const float4*)(src + i + 4);
    __nv_bfloat16 h[8];
    h[0] = __float2bfloat16(v0.x); h[1] = __float2bfloat16(v0.y);
    h[2] = __float2bfloat16(v0.z); h[3] = __float2bfloat16(v0.w);
    h[4] = __float2bfloat16(v1.x); h[5] = __float2bfloat16(v1.y);
    h[6] = __float2bfloat16(v1.z); h[7] = __float2bfloat16(v1.w);
    *(uint4*)(hi + i) = *(const uint4*)h;
}

// Wq/Wk/W1 [768,384] fp32 -> concatenated W^T [1152,768] bf16 (z picks weight)
__global__ __launch_bounds__(256)
void transpose_w_kernel(const float* __restrict__ Wq, const float* __restrict__ Wk,
                        const float* __restrict__ W1, __nv_bfloat16* __restrict__ out)
{
    __shared__ float tile[32][33];
    const float* in = (blockIdx.z == 0) ? Wq : (blockIdx.z == 1) ? Wk : W1;
    __nv_bfloat16* o = out + (size_t)blockIdx.z * (HH_ * H_);
    const int r0 = blockIdx.x * 32, c0 = blockIdx.y * 32;   // r: 0..767, c: 0..383
    const int tx = threadIdx.x, ty = threadIdx.y;
#pragma unroll
    for (int j = 0; j < 32; j += 8)
        tile[ty + j][tx] = in[(size_t)(r0 + ty + j) * HH_ + c0 + tx];
    __syncthreads();
    const int t = ty * 32 + tx;
#pragma unroll
    for (int pidx = t; pidx < 512; pidx += 256) {
        const int oc = pidx >> 4;
        const int pr = (pidx & 15) * 2;
        __nv_bfloat16 h[2];
        h[0] = __float2bfloat16(tile[pr][oc]);
        h[1] = __float2bfloat16(tile[pr + 1][oc]);
        size_t off = (size_t)(c0 + oc) * H_ + r0 + pr;
        *(uint32_t*)(o + off) = *(const uint32_t*)h;
    }
}

// bf16 in [R, C] -> bf16 out [C, R]; per-z offset = z*R*C
__global__ __launch_bounds__(256)
void transpose_bb_kernel(const __nv_bfloat16* __restrict__ in,
                         __nv_bfloat16* __restrict__ out, int R, int Cc)
{
    __shared__ __nv_bfloat16 tile[32][34];
    const size_t zoff = (size_t)blockIdx.z * R * Cc;
    in += zoff; out += zoff;
    const int r0 = blockIdx.x * 32, c0 = blockIdx.y * 32;
    const int tx = threadIdx.x, ty = threadIdx.y;
#pragma unroll
    for (int j = 0; j < 32; j += 8)
        tile[ty + j][tx] = in[(size_t)(r0 + ty + j) * Cc + c0 + tx];
    __syncthreads();
    const int t = ty * 32 + tx;
#pragma unroll
    for (int pidx = t; pidx < 512; pidx += 256) {
        const int oc = pidx >> 4;
        const int pr = (pidx & 15) * 2;
        __nv_bfloat16 h[2] = { tile[pr][oc], tile[pr + 1][oc] };
        size_t o = (size_t)(c0 + oc) * R + r0 + pr;
        *(uint32_t*)(out + o) = *(const uint32_t*)h;
    }
}

// =============== warp-MMA bf16 GEMM =========================================
// C[M,N] = alpha * A @ B^T. A:[M,K] K-major bf16, B:[N,K] K-major bf16.
// MODE 0: fp32 out Cf.
// MODE 2: p=exp(alpha*acc) masked -> bf16 Cb + fixed-point row-sum atomics Zq.
// MODE 3: triple bf16 out (q|k|y segments of 384 cols each) + per-seg bias.
// CTA tile 128x128, 8 warps of 64x32, K chunk 32, 3-stage cp.async pipeline.
template<int MODE>
__global__ __launch_bounds__(256)
void gemm_bf16(const __nv_bfloat16* __restrict__ A, const __nv_bfloat16* __restrict__ Bm,
               float* __restrict__ Cf, __nv_bfloat16* __restrict__ Cb,
               __nv_bfloat16* __restrict__ Cb2, __nv_bfloat16* __restrict__ Cb3,
               const float* __restrict__ bias, const float* __restrict__ bias2,
               const float* __restrict__ bias3,
               const int* __restrict__ am, unsigned long long* __restrict__ Zq,
               int N, int K, float alpha, size_t sA, size_t sB, size_t sC)
{
    extern __shared__ char smem[];
    const uint32_t sbase = smem_u32(smem);
    const int t = threadIdx.x;
    const int mBase = blockIdx.y * 128, nBase = blockIdx.x * 128;
    A  += (size_t)blockIdx.z * sA;
    Bm += (size_t)blockIdx.z * sB;

    const int lane = t & 31, w = t >> 5;
    const int mW = (w & 1) * 64, nW = (w >> 1) * 32;
    const uint32_t aOff = (uint32_t)(lane & 15) * LDSROW + (uint32_t)(lane >> 4) * 16;
    const uint32_t bOff = (uint32_t)(((lane >> 4) << 3) + (lane & 7)) * LDSROW
                        + (uint32_t)((lane >> 3) & 1) * 16;

    const int lrow0 = t >> 2,           lseg0 = t & 3;
    const int lrow1 = (t + 256) >> 2,   lseg1 = t & 3;

    float acc[4][4][4];
#pragma unroll
    for (int i = 0; i < 4; i++)
#pragma unroll
        for (int j = 0; j < 4; j++)
#pragma unroll
            for (int r = 0; r < 4; r++) acc[i][j][r] = 0.f;

    auto load_chunk = [&](int c, int buf) {
        const int kt = c * 32;
        const uint32_t bb = sbase + (uint32_t)buf * BUFB;
        cp16(bb + lrow0 * LDSROW + lseg0 * 16,
             A + (size_t)(mBase + lrow0) * K + kt + lseg0 * 8);
        cp16(bb + lrow1 * LDSROW + lseg1 * 16,
             A + (size_t)(mBase + lrow1) * K + kt + lseg1 * 8);
        cp16(bb + TILEB + lrow0 * LDSROW + lseg0 * 16,
             Bm + (size_t)(nBase + lrow0) * K + kt + lseg0 * 8);
        cp16(bb + TILEB + lrow1 * LDSROW + lseg1 * 16,
             Bm + (size_t)(nBase + lrow1) * K + kt + lseg1 * 8);
    };

    const int NC = K >> 5;

    load_chunk(0, 0); CP_COMMIT();
    load_chunk(1, 1); CP_COMMIT();

    int buf = 0;
    for (int c = 0; c < NC; c++) {
        if (c + 2 < NC) load_chunk(c + 2, (c + 2) % 3);
        CP_COMMIT();
        CP_WAIT2();
        __syncthreads();

        const uint32_t bb  = sbase + (uint32_t)buf * BUFB;
        const uint32_t bAh = bb + (uint32_t)mW * LDSROW;
        const uint32_t bBh = bb + TILEB + (uint32_t)nW * LDSROW;

#pragma unroll
        for (int ks = 0; ks < 2; ks++) {
            const uint32_t ko = (uint32_t)ks * 32;
            uint32_t aH[4][4], bH[4][2];
#pragma unroll
            for (int i = 0; i < 4; i++)
                LDSM4(aH[i], bAh + (uint32_t)(i * 16) * LDSROW + ko + aOff);
#pragma unroll
            for (int j = 0; j < 2; j++) {
                uint32_t r[4];
                LDSM4(r, bBh + (uint32_t)(j * 16) * LDSROW + ko + bOff);
                bH[2*j][0] = r[0]; bH[2*j][1] = r[1];
                bH[2*j+1][0] = r[2]; bH[2*j+1][1] = r[3];
            }
#pragma unroll
            for (int i = 0; i < 4; i++)
#pragma unroll
                for (int j = 0; j < 4; j++)
                    MMA16816(acc[i][j], aH[i], bH[j]);
        }
        __syncthreads();
        buf = (buf + 1 == 3) ? 0 : buf + 1;
    }

    // ---------------- epilogue ----------------------------------------------
    const int g = lane >> 2, tg2 = (lane & 3) * 2;
    if (MODE == 2) {
        // p = exp(alpha*acc) with key mask; quad-reduced fixed-point Z atomics
        __nv_bfloat16* oc = Cb + (size_t)blockIdx.z * sC;
        const int* amb = am + (size_t)blockIdx.z * S_;
        unsigned long long* zb = Zq + (size_t)blockIdx.z * S_;
#pragma unroll
        for (int i = 0; i < 4; i++) {
            const int r0 = mBase + mW + i * 16 + g, r1 = r0 + 8;
            float s0 = 0.f, s1 = 0.f;
#pragma unroll
            for (int j = 0; j < 4; j++) {
                const int c0 = nBase + nW + j * 8 + tg2;
                const bool m0 = amb[c0] != 0, m1 = amb[c0 + 1] != 0;
                float e00 = m0 ? __expf(acc[i][j][0] * alpha) : 0.f;
                float e01 = m1 ? __expf(acc[i][j][1] * alpha) : 0.f;
                float e10 = m0 ? __expf(acc[i][j][2] * alpha) : 0.f;
                float e11 = m1 ? __expf(acc[i][j][3] * alpha) : 0.f;
                s0 += e00 + e01; s1 += e10 + e11;
                *(__nv_bfloat162*)(oc + (size_t)r0 * N + c0) =
                    __nv_bfloat162(__float2bfloat16(e00), __float2bfloat16(e01));
                *(__nv_bfloat162*)(oc + (size_t)r1 * N + c0) =
                    __nv_bfloat162(__float2bfloat16(e10), __float2bfloat16(e11));
            }
            // reduce across the 4 lanes sharing this row, leader does the atomic
            s0 += __shfl_xor_sync(0xffffffffu, s0, 1);
            s0 += __shfl_xor_sync(0xffffffffu, s0, 2);
            s1 += __shfl_xor_sync(0xffffffffu, s1, 1);
            s1 += __shfl_xor_sync(0xffffffffu, s1, 2);
            if ((lane & 3) == 0) {
                atomicAdd(zb + r0, (unsigned long long)llrintf(s0 * ZSCALE));
                atomicAdd(zb + r1, (unsigned long long)llrintf(s1 * ZSCALE));
            }
        }
    } else if (MODE == 3) {
        // triple output: cols [0,384)=q, [384,768)=k, [768,1152)=y
        const int seg  = blockIdx.x / 3;
        const int nLoc = (blockIdx.x % 3) * 128;
        __nv_bfloat16* oc = (seg == 0) ? Cb : (seg == 1) ? Cb2 : Cb3;
        const float* bs   = (seg == 0) ? bias : (seg == 1) ? bias2 : bias3;
#pragma unroll
        for (int i = 0; i < 4; i++) {
            const int r0 = mBase + mW + i * 16 + g, r1 = r0 + 8;
#pragma unroll
            for (int j = 0; j < 4; j++) {
                const int c0 = nLoc + nW + j * 8 + tg2;
                const float b0 = bs[c0], b1 = bs[c0 + 1];
                __nv_bfloat16 h0 = __float2bfloat16(acc[i][j][0] + b0);
                __nv_bfloat16 h1 = __float2bfloat16(acc[i][j][1] + b1);
                *(__nv_bfloat162*)(oc + (size_t)r0 * HH_ + c0) = __nv_bfloat162(h0, h1);
                h0 = __float2bfloat16(acc[i][j][2] + b0);
                h1 = __float2bfloat16(acc[i][j][3] + b1);
                *(__nv_bfloat162*)(oc + (size_t)r1 * HH_ + c0) = __nv_bfloat162(h0, h1);
            }
        }
    } else {
        float* oc = Cf + (size_t)blockIdx.z * sC;
#pragma unroll
        for (int i = 0; i < 4; i++) {
            const int r0 = mBase + mW + i * 16 + g, r1 = r0 + 8;
#pragma unroll
            for (int j = 0; j < 4; j++) {
                const int c0 = nBase + nW + j * 8 + tg2;
                float2 va = make_float2(acc[i][j][0] * alpha, acc[i][j][1] * alpha);
                float2 vb = make_float2(acc[i][j][2] * alpha, acc[i][j][3] * alpha);
                *(float2*)(oc + (size_t)r0 * N + c0) = va;
                *(float2*)(oc + (size_t)r1 * N + c0) = vb;
            }
        }
    }
}

// ------- per-row 1/Z rescale + LayerNorm + ReLU + dot(W2) -> token score -----
__global__ __launch_bounds__(128)
void lnscore_kernel(const float* __restrict__ hpre, const unsigned long long* __restrict__ zq,
                    const float* __restrict__ g1, const float* __restrict__ be1,
                    const float* __restrict__ W2, const float* __restrict__ b2,
                    const int* __restrict__ am, float* __restrict__ ts)
{
    __shared__ float red[128];
    const int row = blockIdx.x, t = threadIdx.x;
    const float zf = (float)zq[row];
    const float invZ = zf > 0.f ? (ZSCALE / zf) : 0.f;
    const float* hr = hpre + (size_t)row * HH_;
    const float v0 = hr[t] * invZ, v1 = hr[t + 128] * invZ, v2 = hr[t + 256] * invZ;

    red[t] = v0 + v1 + v2; __syncthreads();
    for (int o = 64; o > 0; o >>= 1) { if (t < o) red[t] += red[t + o]; __syncthreads(); }
    const float mean = red[0] * (1.f / HH_);
    __syncthreads();

    const float d0 = v0 - mean, d1 = v1 - mean, d2 = v2 - mean;
    red[t] = d0 * d0 + d1 * d1 + d2 * d2; __syncthreads();
    for (int o = 64; o > 0; o >>= 1) { if (t < o) red[t] += red[t + o]; __syncthreads(); }
    const float inv = rsqrtf(red[0] * (1.f / HH_) + 1e-5f);
    __syncthreads();

    float sp = fmaxf(d0 * inv * g1[t]       + be1[t],       0.f) * W2[t]
             + fmaxf(d1 * inv * g1[t + 128] + be1[t + 128], 0.f) * W2[t + 128]
             + fmaxf(d2 * inv * g1[t + 256] + be1[t + 256], 0.f) * W2[t + 256];
    red[t] = sp; __syncthreads();
    for (int o = 64; o > 0; o >>= 1) { if (t < o) red[t] += red[t + o]; __syncthreads(); }
    if (t == 0) {
        float v = red[0] + b2[0];
        if (am[row] == 0) v = -10000.f;
        ts[row] = v;
    }
}

// ---------------- span search + mean pooling ---------------------------------
__global__ __launch_bounds__(256)
void span_pool_kernel(const float* __restrict__ ts, const int* __restrict__ am,
                      const float* __restrict__ x, float* __restrict__ pooled)
{
    __shared__ float sc[2048];
    __shared__ float cum[2049];
    __shared__ float part[256];
    __shared__ int   ired[256];
    __shared__ float bvs[256];
    __shared__ int   bis[256];
    __shared__ int   s_start, s_len;

    const int b = blockIdx.x, t = threadIdx.x;

    int vc = 0;
    for (int i = t; i < S_; i += 256) {
        sc[i] = ts[(size_t)b * S_ + i];
        vc += am[(size_t)b * S_ + i];
    }
    ired[t] = vc; __syncthreads();
    for (int o = 128; o > 0; o >>= 1) { if (t < o) ired[t] += ired[t + o]; __syncthreads(); }
    const int vl = ired[0];

    float ps = 0.f;
    for (int i = 0; i < 8; i++) ps += sc[t * 8 + i];
    part[t] = ps; __syncthreads();
    if (t == 0) {
        float run = 0.f;
        for (int i = 0; i < 256; i++) { float v = part[i]; part[i] = run; run += v; }
        cum[2048] = run;
    }
    __syncthreads();
    float run = part[t];
    for (int i = 0; i < 8; i++) { int idx = t * 8 + i; cum[idx] = run; run += sc[idx]; }
    __syncthreads();

    float bestV = -3.0e38f; int bestI = 0x7fffffff;
    for (int flat = t; flat < 18 * S_; flat += 256) {
        const int li = flat >> 11, start = flat & 2047;
        const int L = 3 + li, end = start + L;
        const int endc = end > S_ ? S_ : end;
        const float fL = (float)L;
        float avg = (cum[endc] - cum[start]) / fL + 0.01f * fL / 20.0f;
        if (end > vl) avg = -1e30f;
        if (avg > bestV) { bestV = avg; bestI = flat; }
    }
    bvs[t] = bestV; bis[t] = bestI; __syncthreads();
    for (int o = 128; o > 0; o >>= 1) {
        if (t < o) {
            if (bvs[t + o] > bvs[t] || (bvs[t + o] == bvs[t] && bis[t + o] < bis[t])) {
                bvs[t] = bvs[t + o]; bis[t] = bis[t + o];
            }
        }
        __syncthreads();
    }
    if (t == 0) {
        const int fi = bis[0];
        int start = fi & 2047, L = 3 + (fi >> 11);
        if (vl <= 3) { start = 0; L = vl; }
        s_start = start; s_len = L;
    }
    __syncthreads();

    const int start = s_start, L = s_len;
    const float inv = 1.0f / ((float)L + 1e-6f);
    for (int h = t; h < H_; h += 256) {
        float s = 0.f;
        for (int r = 0; r < L; r++) s += x[((size_t)b * S_ + start + r) * H_ + h];
        pooled[b * H_ + h] = s * inv;
    }
}

// ---------------- classification head ----------------------------------------
__global__ __launch_bounds__(384)
void head_kernel(const float* __restrict__ pooled, const float* __restrict__ x,
                 const float* __restrict__ Wc1, const float* __restrict__ bc1,
                 const float* __restrict__ g2, const float* __restrict__ be2,
                 const float* __restrict__ Wc2, const float* __restrict__ bc2,
                 const float* __restrict__ Mint,
                 const float* __restrict__ Wcls, const float* __restrict__ bcls,
                 float* __restrict__ out)
{
    __shared__ float pl[768];
    __shared__ float hc[384];
    __shared__ float cs[64];
    __shared__ float cp[64];
    __shared__ float red[512];
    const int b = blockIdx.x, t = threadIdx.x;

    for (int i = t; i < H_; i += 384) pl[i] = pooled[b * H_ + i];
    if (t < 128) red[384 + t] = 0.f;
    __syncthreads();

    float acc = bc1[t];
    for (int k = 0; k < H_; k++) acc += pl[k] * Wc1[(size_t)k * HH_ + t];

    red[t] = acc; __syncthreads();
    for (int o = 256; o > 0; o >>= 1) { if (t < o) red[t] += red[t + o]; __syncthreads(); }
    const float mean = red[0] * (1.f / HH_);
    __syncthreads();
    const float d = acc - mean;
    red[t] = d * d; __syncthreads();
    for (int o = 256; o > 0; o >>= 1) { if (t < o) red[t] += red[t + o]; __syncthreads(); }
    const float var = red[0] * (1.f / HH_);
    const float yn = d * rsqrtf(var + 1e-5f) * g2[t] + be2[t];
    hc[t] = fmaxf(yn, 0.f);
    __syncthreads();

    if (t < C_) {
        float c = bc2[t];
        for (int k = 0; k < HH_; k++) c += hc[k] * Wc2[(size_t)k * C_ + t];
        cs[t] = c;
    }
    __syncthreads();
    if (t < C_) {
        float add = cs[t];
        for (int i = 0; i < C_; i++) {
            const float m = 0.5f * (Mint[i * C_ + t] + Mint[t * C_ + i]);
            const float sg = 1.f / (1.f + expf(-m));
            add += cs[i] * sg;
        }
        cp[t] = 1.f / (1.f + expf(-add));
    }
    __syncthreads();
    if (t < L_) {
        float lg = bcls[t];
        for (int c = 0; c < C_; c++) lg += cp[c] * Wcls[c * L_ + t];
        const float* xr = x + (size_t)b * S_ * H_;
        for (int h = 0; h < H_; h++) lg += xr[h] * Wcls[(C_ + h) * L_ + t];
        out[b * L_ + t] = lg;
    }
}

// ---------------------------- launcher ---------------------------------------
extern "C" void kernel_launch(void* const* d_in, const int* in_sizes, int n_in,
                              void* d_out, int out_size)
{
    const float* x    = (const float*)d_in[0];
    const int*   am   = (const int*)  d_in[1];
    const float* Wq   = (const float*)d_in[2];
    const float* bq   = (const float*)d_in[3];
    const float* Wk   = (const float*)d_in[4];
    const float* bk   = (const float*)d_in[5];
    const float* W1   = (const float*)d_in[6];
    const float* b1   = (const float*)d_in[7];
    const float* g1   = (const float*)d_in[8];
    const float* be1  = (const float*)d_in[9];
    const float* W2   = (const float*)d_in[10];
    const float* b2   = (const float*)d_in[11];
    const float* Wc1  = (const float*)d_in[12];
    const float* bc1  = (const float*)d_in[13];
    const float* g2   = (const float*)d_in[14];
    const float* be2  = (const float*)d_in[15];
    const float* Wc2  = (const float*)d_in[16];
    const float* bc2  = (const float*)d_in[17];
    const float* Mint = (const float*)d_in[18];
    const float* Wcls = (const float*)d_in[19];
    const float* bcls = (const float*)d_in[20];
    float* out = (float*)d_out;

    __nv_bfloat16 *xhi, *qhi, *khi, *yhi, *phi, *yThi, *Wcat;
    unsigned long long* zq;
    float *hp, *tp, *pp;
    cudaGetSymbolAddress((void**)&xhi,  g_xhi);
    cudaGetSymbolAddress((void**)&qhi,  g_qhi);
    cudaGetSymbolAddress((void**)&khi,  g_khi);
    cudaGetSymbolAddress((void**)&yhi,  g_yhi);
    cudaGetSymbolAddress((void**)&phi,  g_phi);
    cudaGetSymbolAddress((void**)&zq,   g_Zq);
    cudaGetSymbolAddress((void**)&yThi, g_yThi);
    cudaGetSymbolAddress((void**)&Wcat, g_Wcat);
    cudaGetSymbolAddress((void**)&hp, g_hpre);
    cudaGetSymbolAddress((void**)&tp, g_ts);
    cudaGetSymbolAddress((void**)&pp, g_pool);

    cudaFuncSetAttribute(gemm_bf16<0>, cudaFuncAttributeMaxDynamicSharedMemorySize, GEMM_SMEM);
    cudaFuncSetAttribute(gemm_bf16<2>, cudaFuncAttributeMaxDynamicSharedMemorySize, GEMM_SMEM);
    cudaFuncSetAttribute(gemm_bf16<3>, cudaFuncAttributeMaxDynamicSharedMemorySize, GEMM_SMEM);

    // 0. zero Z accumulators (graph-capturable async memset)
    cudaMemsetAsync(zq, 0, 32768 * sizeof(unsigned long long));

    // 1. weight transposes into concatenated [1152,768] bf16
    transpose_w_kernel<<<dim3(24, 12, 3), dim3(32, 8)>>>(Wq, Wk, W1, Wcat);

    // 2. x -> bf16
    cvt_bf16_kernel<<<25165824 / 2048, 256>>>(x, xhi);

    // 3. fused projections: [32768,768] @ Wcat^T -> q|k|y bf16 (+bias)
    gemm_bf16<3><<<dim3(9, 256, 1), 256, GEMM_SMEM>>>(
        xhi, Wcat, nullptr, qhi, khi, yhi, bq, bk, b1,
        nullptr, nullptr, 1152, H_, 1.f, 0, 0, 0);

    // 4. y^T per batch: y [B,S,HH] bf16 -> yT [B,HH,S] bf16
    transpose_bb_kernel<<<dim3(64, 12, 16), dim3(32, 8)>>>(yhi, yThi, S_, HH_);

    // 5. fused attn+exp: p = exp(q@k^T/sqrt(HH)) masked -> bf16, Z row sums
    const float alpha = 1.0f / sqrtf((float)HH_);
    gemm_bf16<2><<<dim3(16, 16, B_), 256, GEMM_SMEM>>>(
        qhi, khi, nullptr, phi, nullptr, nullptr, nullptr, nullptr, nullptr,
        am, zq, S_, HH_, alpha,
        (size_t)S_ * HH_, (size_t)S_ * HH_, (size_t)S_ * S_);

    // 6. h_pre_unnorm = p @ y: [2048,2048] x yT[384,2048] -> fp32
    gemm_bf16<0><<<dim3(3, 16, B_), 256, GEMM_SMEM>>>(
        phi, yThi, hp, nullptr, nullptr, nullptr, nullptr, nullptr, nullptr,
        nullptr, nullptr, HH_, S_, 1.f,
        (size_t)S_ * S_, (size_t)HH_ * S_, (size_t)S_ * HH_);

    // 7-9. scores (with 1/Z rescale), span+pool, head
    lnscore_kernel<<<B_ * S_, 128>>>(hp, zq, g1, be1, W2, b2, am, tp);
    span_pool_kernel<<<B_, 256>>>(tp, am, x, pp);
    head_kernel<<<B_, 384>>>(pp, x, Wc1, bc1, g2, be2, Wc2, bc2, Mint, Wcls, bcls, out);
}

// round 11
// speedup vs baseline: 6.5581x; 1.0023x over previous
#include <cuda_runtime.h>
#include <cuda_bf16.h>
#include <math.h>
#include <stdint.h>

// Problem constants
#define B_  16
#define S_  2048
#define H_  768
#define HH_ 384
#define C_  64
#define L_  4

// ---------------- scratch (static __device__ arrays; no allocation) ----------
__device__ __nv_bfloat16 g_xhi [25165824];     // x bf16        [B*S,H]
__device__ __nv_bfloat16 g_qhi [12582912];     // q bf16        [B*S,HH]
__device__ __nv_bfloat16 g_khi [12582912];     // k bf16        [B*S,HH]
__device__ __nv_bfloat16 g_yhi [12582912];     // y bf16        [B*S,HH]
__device__ __nv_bfloat16 g_phi [67108864];     // p=exp(attn) bf16 [B,S,S]
__device__ unsigned long long g_Zq[32768];     // fixed-point row sums of p
__device__ __nv_bfloat16 g_yThi[12582912];     // y^T bf16      [B,HH,S]
__device__ float         g_hpre[12582912];     // h_pre (unnormalized) [B*S,HH]
__device__ float         g_ts  [32768];
__device__ float         g_pool[12288];
__device__ __nv_bfloat16 g_Wcat[884736];       // [Wq|Wk|W1]^T bf16 [1152,768]

// ============================ PTX helpers ====================================
__device__ __forceinline__ uint32_t smem_u32(const void* p) {
    return (uint32_t)__cvta_generic_to_shared(p);
}

__device__ __forceinline__ void cp16(uint32_t dst, const void* src) {
    asm volatile("cp.async.cg.shared.global [%0], [%1], 16;" :: "r"(dst), "l"(src));
}
#define CP_COMMIT() asm volatile("cp.async.commit_group;" ::: "memory")
#define CP_WAIT2()  asm volatile("cp.async.wait_group 2;" ::: "memory")

#define LDSM4(r, addr) \
    asm volatile("ldmatrix.sync.aligned.m8n8.x4.shared.b16 {%0,%1,%2,%3}, [%4];" \
        : "=r"((r)[0]), "=r"((r)[1]), "=r"((r)[2]), "=r"((r)[3]) : "r"(addr))

#define MMA16816(d, a, b) \
    asm volatile("mma.sync.aligned.m16n8k16.row.col.f32.bf16.bf16.f32 " \
        "{%0,%1,%2,%3}, {%4,%5,%6,%7}, {%8,%9}, {%0,%1,%2,%3};" \
        : "+f"((d)[0]), "+f"((d)[1]), "+f"((d)[2]), "+f"((d)[3]) \
        : "r"((a)[0]), "r"((a)[1]), "r"((a)[2]), "r"((a)[3]), \
          "r"((b)[0]), "r"((b)[1]))

// SMEM tile geometry: 128 rows x 32 bf16 (64B data) padded to 80B/row
#define LDSROW 80
#define TILEB  (128 * LDSROW)         // 10240 B
#define BUFB   (2 * TILEB)            // A, B tiles = 20480 B
#define GEMM_SMEM (3 * BUFB)          // 3-stage pipeline = 61440 B

#define ZSCALE 1048576.0f             // 2^20 fixed point for deterministic Z

// =============== conversions ================================================
__global__ __launch_bounds__(256)
void cvt_bf16_kernel(const float* __restrict__ src, __nv_bfloat16* __restrict__ hi)
{
    const size_t i = ((size_t)blockIdx.x * 256 + threadIdx.x) * 8;
    float4 v0 = *(const float4*)(src + i);
    float4 v1 = *(const float4*)(src + i + 4);
    __nv_bfloat16 h[8];
    h[0] = __float2bfloat16(v0.x); h[1] = __float2bfloat16(v0.y);
    h[2] = __float2bfloat16(v0.z); h[3] = __float2bfloat16(v0.w);
    h[4] = __float2bfloat16(v1.x); h[5] = __float2bfloat16(v1.y);
    h[6] = __float2bfloat16(v1.z); h[7] = __float2bfloat16(v1.w);
    *(uint4*)(hi + i) = *(const uint4*)h;
}

// Wq/Wk/W1 [768,384] fp32 -> concatenated W^T [1152,768] bf16 (z picks weight)
__global__ __launch_bounds__(256)
void transpose_w_kernel(const float* __restrict__ Wq, const float* __restrict__ Wk,
                        const float* __restrict__ W1, __nv_bfloat16* __restrict__ out)
{
    __shared__ float tile[32][33];
    const float* in = (blockIdx.z == 0) ? Wq : (blockIdx.z == 1) ? Wk : W1;
    __nv_bfloat16* o = out + (size_t)blockIdx.z * (HH_ * H_);
    const int r0 = blockIdx.x * 32, c0 = blockIdx.y * 32;   // r: 0..767, c: 0..383
    const int tx = threadIdx.x, ty = threadIdx.y;
#pragma unroll
    for (int j = 0; j < 32; j += 8)
        tile[ty + j][tx] = in[(size_t)(r0 + ty + j) * HH_ + c0 + tx];
    __syncthreads();
    const int t = ty * 32 + tx;
#pragma unroll
    for (int pidx = t; pidx < 512; pidx += 256) {
        const int oc = pidx >> 4;
        const int pr = (pidx & 15) * 2;
        __nv_bfloat16 h[2];
        h[0] = __float2bfloat16(tile[pr][oc]);
        h[1] = __float2bfloat16(tile[pr + 1][oc]);
        size_t off = (size_t)(c0 + oc) * H_ + r0 + pr;
        *(uint32_t*)(o + off) = *(const uint32_t*)h;
    }
}

// bf16 in [R, C] -> bf16 out [C, R]; per-z offset = z*R*C
__global__ __launch_bounds__(256)
void transpose_bb_kernel(const __nv_bfloat16* __restrict__ in,
                         __nv_bfloat16* __restrict__ out, int R, int Cc)
{
    __shared__ __nv_bfloat16 tile[32][34];
    const size_t zoff = (size_t)blockIdx.z * R * Cc;
    in += zoff; out += zoff;
    const int r0 = blockIdx.x * 32, c0 = blockIdx.y * 32;
    const int tx = threadIdx.x, ty = threadIdx.y;
#pragma unroll
    for (int j = 0; j < 32; j += 8)
        tile[ty + j][tx] = in[(size_t)(r0 + ty + j) * Cc + c0 + tx];
    __syncthreads();
    const int t = ty * 32 + tx;
#pragma unroll
    for (int pidx = t; pidx < 512; pidx += 256) {
        const int oc = pidx >> 4;
        const int pr = (pidx & 15) * 2;
        __nv_bfloat16 h[2] = { tile[pr][oc], tile[pr + 1][oc] };
        size_t o = (size_t)(c0 + oc) * R + r0 + pr;
        *(uint32_t*)(out + o) = *(const uint32_t*)h;
    }
}

// =============== warp-MMA bf16 GEMM =========================================
// C[M,N] = alpha * A @ B^T. A:[M,K] K-major bf16, B:[N,K] K-major bf16.
// MODE 0: fp32 out Cf.
// MODE 2: p=exp(alpha*acc) masked -> bf16 Cb + fixed-point row-sum atomics Zq.
// MODE 3: triple bf16 out (q|k|y segments of 384 cols each) + per-seg bias.
// CTA tile 128x128, 8 warps of 64x32, K chunk 32, 3-stage cp.async pipeline.
template<int MODE>
__global__ __launch_bounds__(256)
void gemm_bf16(const __nv_bfloat16* __restrict__ A, const __nv_bfloat16* __restrict__ Bm,
               float* __restrict__ Cf, __nv_bfloat16* __restrict__ Cb,
               __nv_bfloat16* __restrict__ Cb2, __nv_bfloat16* __restrict__ Cb3,
               const float* __restrict__ bias, const float* __restrict__ bias2,
               const float* __restrict__ bias3,
               const int* __restrict__ am, unsigned long long* __restrict__ Zq,
               int N, int K, float alpha, size_t sA, size_t sB, size_t sC)
{
    extern __shared__ char smem[];
    const uint32_t sbase = smem_u32(smem);
    const int t = threadIdx.x;
    const int mBase = blockIdx.y * 128, nBase = blockIdx.x * 128;
    A  += (size_t)blockIdx.z * sA;
    Bm += (size_t)blockIdx.z * sB;

    const int lane = t & 31, w = t >> 5;
    const int mW = (w & 1) * 64, nW = (w >> 1) * 32;
    const uint32_t aOff = (uint32_t)(lane & 15) * LDSROW + (uint32_t)(lane >> 4) * 16;
    const uint32_t bOff = (uint32_t)(((lane >> 4) << 3) + (lane & 7)) * LDSROW
                        + (uint32_t)((lane >> 3) & 1) * 16;

    const int lrow0 = t >> 2,           lseg0 = t & 3;
    const int lrow1 = (t + 256) >> 2,   lseg1 = t & 3;

    float acc[4][4][4];
#pragma unroll
    for (int i = 0; i < 4; i++)
#pragma unroll
        for (int j = 0; j < 4; j++)
#pragma unroll
            for (int r = 0; r < 4; r++) acc[i][j][r] = 0.f;

    auto load_chunk = [&](int c, int buf) {
        const int kt = c * 32;
        const uint32_t bb = sbase + (uint32_t)buf * BUFB;
        cp16(bb + lrow0 * LDSROW + lseg0 * 16,
             A + (size_t)(mBase + lrow0) * K + kt + lseg0 * 8);
        cp16(bb + lrow1 * LDSROW + lseg1 * 16,
             A + (size_t)(mBase + lrow1) * K + kt + lseg1 * 8);
        cp16(bb + TILEB + lrow0 * LDSROW + lseg0 * 16,
             Bm + (size_t)(nBase + lrow0) * K + kt + lseg0 * 8);
        cp16(bb + TILEB + lrow1 * LDSROW + lseg1 * 16,
             Bm + (size_t)(nBase + lrow1) * K + kt + lseg1 * 8);
    };

    const int NC = K >> 5;

    load_chunk(0, 0); CP_COMMIT();
    load_chunk(1, 1); CP_COMMIT();

    int buf = 0;
    for (int c = 0; c < NC; c++) {
        if (c + 2 < NC) load_chunk(c + 2, (c + 2) % 3);
        CP_COMMIT();
        CP_WAIT2();
        __syncthreads();

        const uint32_t bb  = sbase + (uint32_t)buf * BUFB;
        const uint32_t bAh = bb + (uint32_t)mW * LDSROW;
        const uint32_t bBh = bb + TILEB + (uint32_t)nW * LDSROW;

#pragma unroll
        for (int ks = 0; ks < 2; ks++) {
            const uint32_t ko = (uint32_t)ks * 32;
            uint32_t aH[4][4], bH[4][2];
#pragma unroll
            for (int i = 0; i < 4; i++)
                LDSM4(aH[i], bAh + (uint32_t)(i * 16) * LDSROW + ko + aOff);
#pragma unroll
            for (int j = 0; j < 2; j++) {
                uint32_t r[4];
                LDSM4(r, bBh + (uint32_t)(j * 16) * LDSROW + ko + bOff);
                bH[2*j][0] = r[0]; bH[2*j][1] = r[1];
                bH[2*j+1][0] = r[2]; bH[2*j+1][1] = r[3];
            }
#pragma unroll
            for (int i = 0; i < 4; i++)
#pragma unroll
                for (int j = 0; j < 4; j++)
                    MMA16816(acc[i][j], aH[i], bH[j]);
        }
        __syncthreads();
        buf = (buf + 1 == 3) ? 0 : buf + 1;
    }

    // ---------------- epilogue ----------------------------------------------
    const int g = lane >> 2, tg2 = (lane & 3) * 2;
    if (MODE == 2) {
        // p = exp(alpha*acc) with key mask; quad-reduced fixed-point Z atomics
        __nv_bfloat16* oc = Cb + (size_t)blockIdx.z * sC;
        const int* amb = am + (size_t)blockIdx.z * S_;
        unsigned long long* zb = Zq + (size_t)blockIdx.z * S_;
#pragma unroll
        for (int i = 0; i < 4; i++) {
            const int r0 = mBase + mW + i * 16 + g, r1 = r0 + 8;
            float s0 = 0.f, s1 = 0.f;
#pragma unroll
            for (int j = 0; j < 4; j++) {
                const int c0 = nBase + nW + j * 8 + tg2;
                const bool m0 = amb[c0] != 0, m1 = amb[c0 + 1] != 0;
                float e00 = m0 ? __expf(acc[i][j][0] * alpha) : 0.f;
                float e01 = m1 ? __expf(acc[i][j][1] * alpha) : 0.f;
                float e10 = m0 ? __expf(acc[i][j][2] * alpha) : 0.f;
                float e11 = m1 ? __expf(acc[i][j][3] * alpha) : 0.f;
                s0 += e00 + e01; s1 += e10 + e11;
                *(__nv_bfloat162*)(oc + (size_t)r0 * N + c0) =
                    __nv_bfloat162(__float2bfloat16(e00), __float2bfloat16(e01));
                *(__nv_bfloat162*)(oc + (size_t)r1 * N + c0) =
                    __nv_bfloat162(__float2bfloat16(e10), __float2bfloat16(e11));
            }
            // reduce across the 4 lanes sharing this row, leader does the atomic
            s0 += __shfl_xor_sync(0xffffffffu, s0, 1);
            s0 += __shfl_xor_sync(0xffffffffu, s0, 2);
            s1 += __shfl_xor_sync(0xffffffffu, s1, 1);
            s1 += __shfl_xor_sync(0xffffffffu, s1, 2);
            if ((lane & 3) == 0) {
                atomicAdd(zb + r0, (unsigned long long)llrintf(s0 * ZSCALE));
                atomicAdd(zb + r1, (unsigned long long)llrintf(s1 * ZSCALE));
            }
        }
    } else if (MODE == 3) {
        // triple output: cols [0,384)=q, [384,768)=k, [768,1152)=y
        const int seg  = blockIdx.x / 3;
        const int nLoc = (blockIdx.x % 3) * 128;
        __nv_bfloat16* oc = (seg == 0) ? Cb : (seg == 1) ? Cb2 : Cb3;
        const float* bs   = (seg == 0) ? bias : (seg == 1) ? bias2 : bias3;
#pragma unroll
        for (int i = 0; i < 4; i++) {
            const int r0 = mBase + mW + i * 16 + g, r1 = r0 + 8;
#pragma unroll
            for (int j = 0; j < 4; j++) {
                const int c0 = nLoc + nW + j * 8 + tg2;
                const float b0 = bs[c0], b1 = bs[c0 + 1];
                __nv_bfloat16 h0 = __float2bfloat16(acc[i][j][0] + b0);
                __nv_bfloat16 h1 = __float2bfloat16(acc[i][j][1] + b1);
                *(__nv_bfloat162*)(oc + (size_t)r0 * HH_ + c0) = __nv_bfloat162(h0, h1);
                h0 = __float2bfloat16(acc[i][j][2] + b0);
                h1 = __float2bfloat16(acc[i][j][3] + b1);
                *(__nv_bfloat162*)(oc + (size_t)r1 * HH_ + c0) = __nv_bfloat162(h0, h1);
            }
        }
    } else {
        float* oc = Cf + (size_t)blockIdx.z * sC;
#pragma unroll
        for (int i = 0; i < 4; i++) {
            const int r0 = mBase + mW + i * 16 + g, r1 = r0 + 8;
#pragma unroll
            for (int j = 0; j < 4; j++) {
                const int c0 = nBase + nW + j * 8 + tg2;
                float2 va = make_float2(acc[i][j][0] * alpha, acc[i][j][1] * alpha);
                float2 vb = make_float2(acc[i][j][2] * alpha, acc[i][j][3] * alpha);
                *(float2*)(oc + (size_t)r0 * N + c0) = va;
                *(float2*)(oc + (size_t)r1 * N + c0) = vb;
            }
        }
    }
}

// ------- per-row 1/Z rescale + LayerNorm + ReLU + dot(W2) -> token score -----
__global__ __launch_bounds__(128)
void lnscore_kernel(const float* __restrict__ hpre, const unsigned long long* __restrict__ zq,
                    const float* __restrict__ g1, const float* __restrict__ be1,
                    const float* __restrict__ W2, const float* __restrict__ b2,
                    const int* __restrict__ am, float* __restrict__ ts)
{
    __shared__ float red[128];
    const int row = blockIdx.x, t = threadIdx.x;
    const float zf = (float)zq[row];
    const float invZ = zf > 0.f ? (ZSCALE / zf) : 0.f;
    const float* hr = hpre + (size_t)row * HH_;
    const float v0 = hr[t] * invZ, v1 = hr[t + 128] * invZ, v2 = hr[t + 256] * invZ;

    red[t] = v0 + v1 + v2; __syncthreads();
    for (int o = 64; o > 0; o >>= 1) { if (t < o) red[t] += red[t + o]; __syncthreads(); }
    const float mean = red[0] * (1.f / HH_);
    __syncthreads();

    const float d0 = v0 - mean, d1 = v1 - mean, d2 = v2 - mean;
    red[t] = d0 * d0 + d1 * d1 + d2 * d2; __syncthreads();
    for (int o = 64; o > 0; o >>= 1) { if (t < o) red[t] += red[t + o]; __syncthreads(); }
    const float inv = rsqrtf(red[0] * (1.f / HH_) + 1e-5f);
    __syncthreads();

    float sp = fmaxf(d0 * inv * g1[t]       + be1[t],       0.f) * W2[t]
             + fmaxf(d1 * inv * g1[t + 128] + be1[t + 128], 0.f) * W2[t + 128]
             + fmaxf(d2 * inv * g1[t + 256] + be1[t + 256], 0.f) * W2[t + 256];
    red[t] = sp; __syncthreads();
    for (int o = 64; o > 0; o >>= 1) { if (t < o) red[t] += red[t + o]; __syncthreads(); }
    if (t == 0) {
        float v = red[0] + b2[0];
        if (am[row] == 0) v = -10000.f;
        ts[row] = v;
    }
}

// ---------------- span search + mean pooling ---------------------------------
__global__ __launch_bounds__(256)
void span_pool_kernel(const float* __restrict__ ts, const int* __restrict__ am,
                      const float* __restrict__ x, float* __restrict__ pooled)
{
    __shared__ float sc[2048];
    __shared__ float cum[2049];
    __shared__ float part[256];
    __shared__ int   ired[256];
    __shared__ float bvs[256];
    __shared__ int   bis[256];
    __shared__ int   s_start, s_len;

    const int b = blockIdx.x, t = threadIdx.x;

    int vc = 0;
    for (int i = t; i < S_; i += 256) {
        sc[i] = ts[(size_t)b * S_ + i];
        vc += am[(size_t)b * S_ + i];
    }
    ired[t] = vc; __syncthreads();
    for (int o = 128; o > 0; o >>= 1) { if (t < o) ired[t] += ired[t + o]; __syncthreads(); }
    const int vl = ired[0];

    float ps = 0.f;
    for (int i = 0; i < 8; i++) ps += sc[t * 8 + i];
    part[t] = ps; __syncthreads();
    if (t == 0) {
        float run = 0.f;
        for (int i = 0; i < 256; i++) { float v = part[i]; part[i] = run; run += v; }
        cum[2048] = run;
    }
    __syncthreads();
    float run = part[t];
    for (int i = 0; i < 8; i++) { int idx = t * 8 + i; cum[idx] = run; run += sc[idx]; }
    __syncthreads();

    float bestV = -3.0e38f; int bestI = 0x7fffffff;
    for (int flat = t; flat < 18 * S_; flat += 256) {
        const int li = flat >> 11, start = flat & 2047;
        const int L = 3 + li, end = start + L;
        const int endc = end > S_ ? S_ : end;
        const float fL = (float)L;
        float avg = (cum[endc] - cum[start]) / fL + 0.01f * fL / 20.0f;
        if (end > vl) avg = -1e30f;
        if (avg > bestV) { bestV = avg; bestI = flat; }
    }
    bvs[t] = bestV; bis[t] = bestI; __syncthreads();
    for (int o = 128; o > 0; o >>= 1) {
        if (t < o) {
            if (bvs[t + o] > bvs[t] || (bvs[t + o] == bvs[t] && bis[t + o] < bis[t])) {
                bvs[t] = bvs[t + o]; bis[t] = bis[t + o];
            }
        }
        __syncthreads();
    }
    if (t == 0) {
        const int fi = bis[0];
        int start = fi & 2047, L = 3 + (fi >> 11);
        if (vl <= 3) { start = 0; L = vl; }
        s_start = start; s_len = L;
    }
    __syncthreads();

    const int start = s_start, L = s_len;
    const float inv = 1.0f / ((float)L + 1e-6f);
    for (int h = t; h < H_; h += 256) {
        float s = 0.f;
        for (int r = 0; r < L; r++) s += x[((size_t)b * S_ + start + r) * H_ + h];
        pooled[b * H_ + h] = s * inv;
    }
}

// ---------------- classification head ----------------------------------------
__global__ __launch_bounds__(384)
void head_kernel(const float* __restrict__ pooled, const float* __restrict__ x,
                 const float* __restrict__ Wc1, const float* __restrict__ bc1,
                 const float* __restrict__ g2, const float* __restrict__ be2,
                 const float* __restrict__ Wc2, const float* __restrict__ bc2,
                 const float* __restrict__ Mint,
                 const float* __restrict__ Wcls, const float* __restrict__ bcls,
                 float* __restrict__ out)
{
    __shared__ float pl[768];
    __shared__ float hc[384];
    __shared__ float cs[64];
    __shared__ float cp[64];
    __shared__ float red[512];
    const int b = blockIdx.x, t = threadIdx.x;

    for (int i = t; i < H_; i += 384) pl[i] = pooled[b * H_ + i];
    if (t < 128) red[384 + t] = 0.f;
    __syncthreads();

    float acc = bc1[t];
    for (int k = 0; k < H_; k++) acc += pl[k] * Wc1[(size_t)k * HH_ + t];

    red[t] = acc; __syncthreads();
    for (int o = 256; o > 0; o >>= 1) { if (t < o) red[t] += red[t + o]; __syncthreads(); }
    const float mean = red[0] * (1.f / HH_);
    __syncthreads();
    const float d = acc - mean;
    red[t] = d * d; __syncthreads();
    for (int o = 256; o > 0; o >>= 1) { if (t < o) red[t] += red[t + o]; __syncthreads(); }
    const float var = red[0] * (1.f / HH_);
    const float yn = d * rsqrtf(var + 1e-5f) * g2[t] + be2[t];
    hc[t] = fmaxf(yn, 0.f);
    __syncthreads();

    if (t < C_) {
        float c = bc2[t];
        for (int k = 0; k < HH_; k++) c += hc[k] * Wc2[(size_t)k * C_ + t];
        cs[t] = c;
    }
    __syncthreads();
    if (t < C_) {
        float add = cs[t];
        for (int i = 0; i < C_; i++) {
            const float m = 0.5f * (Mint[i * C_ + t] + Mint[t * C_ + i]);
            const float sg = 1.f / (1.f + expf(-m));
            add += cs[i] * sg;
        }
        cp[t] = 1.f / (1.f + expf(-add));
    }
    __syncthreads();
    if (t < L_) {
        float lg = bcls[t];
        for (int c = 0; c < C_; c++) lg += cp[c] * Wcls[c * L_ + t];
        const float* xr = x + (size_t)b * S_ * H_;
        for (int h = 0; h < H_; h++) lg += xr[h] * Wcls[(C_ + h) * L_ + t];
        out[b * L_ + t] = lg;
    }
}

// ---------------------------- launcher ---------------------------------------
extern "C" void kernel_launch(void* const* d_in, const int* in_sizes, int n_in,
                              void* d_out, int out_size)
{
    const float* x    = (const float*)d_in[0];
    const int*   am   = (const int*)  d_in[1];
    const float* Wq   = (const float*)d_in[2];
    const float* bq   = (const float*)d_in[3];
    const float* Wk   = (const float*)d_in[4];
    const float* bk   = (const float*)d_in[5];
    const float* W1   = (const float*)d_in[6];
    const float* b1   = (const float*)d_in[7];
    const float* g1   = (const float*)d_in[8];
    const float* be1  = (const float*)d_in[9];
    const float* W2   = (const float*)d_in[10];
    const float* b2   = (const float*)d_in[11];
    const float* Wc1  = (const float*)d_in[12];
    const float* bc1  = (const float*)d_in[13];
    const float* g2   = (const float*)d_in[14];
    const float* be2  = (const float*)d_in[15];
    const float* Wc2  = (const float*)d_in[16];
    const float* bc2  = (const float*)d_in[17];
    const float* Mint = (const float*)d_in[18];
    const float* Wcls = (const float*)d_in[19];
    const float* bcls = (const float*)d_in[20];
    float* out = (float*)d_out;

    __nv_bfloat16 *xhi, *qhi, *khi, *yhi, *phi, *yThi, *Wcat;
    unsigned long long* zq;
    float *hp, *tp, *pp;
    cudaGetSymbolAddress((void**)&xhi,  g_xhi);
    cudaGetSymbolAddress((void**)&qhi,  g_qhi);
    cudaGetSymbolAddress((void**)&khi,  g_khi);
    cudaGetSymbolAddress((void**)&yhi,  g_yhi);
    cudaGetSymbolAddress((void**)&phi,  g_phi);
    cudaGetSymbolAddress((void**)&zq,   g_Zq);
    cudaGetSymbolAddress((void**)&yThi, g_yThi);
    cudaGetSymbolAddress((void**)&Wcat, g_Wcat);
    cudaGetSymbolAddress((void**)&hp, g_hpre);
    cudaGetSymbolAddress((void**)&tp, g_ts);
    cudaGetSymbolAddress((void**)&pp, g_pool);

    cudaFuncSetAttribute(gemm_bf16<0>, cudaFuncAttributeMaxDynamicSharedMemorySize, GEMM_SMEM);
    cudaFuncSetAttribute(gemm_bf16<2>, cudaFuncAttributeMaxDynamicSharedMemorySize, GEMM_SMEM);
    cudaFuncSetAttribute(gemm_bf16<3>, cudaFuncAttributeMaxDynamicSharedMemorySize, GEMM_SMEM);

    // 0. zero Z accumulators (graph-capturable async memset)
    cudaMemsetAsync(zq, 0, 32768 * sizeof(unsigned long long));

    // 1. weight transposes into concatenated [1152,768] bf16
    transpose_w_kernel<<<dim3(24, 12, 3), dim3(32, 8)>>>(Wq, Wk, W1, Wcat);

    // 2. x -> bf16
    cvt_bf16_kernel<<<25165824 / 2048, 256>>>(x, xhi);

    // 3. fused projections: [32768,768] @ Wcat^T -> q|k|y bf16 (+bias)
    gemm_bf16<3><<<dim3(9, 256, 1), 256, GEMM_SMEM>>>(
        xhi, Wcat, nullptr, qhi, khi, yhi, bq, bk, b1,
        nullptr, nullptr, 1152, H_, 1.f, 0, 0, 0);

    // 4. y^T per batch: y [B,S,HH] bf16 -> yT [B,HH,S] bf16
    transpose_bb_kernel<<<dim3(64, 12, 16), dim3(32, 8)>>>(yhi, yThi, S_, HH_);

    // 5. fused attn+exp: p = exp(q@k^T/sqrt(HH)) masked -> bf16, Z row sums
    const float alpha = 1.0f / sqrtf((float)HH_);
    gemm_bf16<2><<<dim3(16, 16, B_), 256, GEMM_SMEM>>>(
        qhi, khi, nullptr, phi, nullptr, nullptr, nullptr, nullptr, nullptr,
        am, zq, S_, HH_, alpha,
        (size_t)S_ * HH_, (size_t)S_ * HH_, (size_t)S_ * S_);

    // 6. h_pre_unnorm = p @ y: [2048,2048] x yT[384,2048] -> fp32
    gemm_bf16<0><<<dim3(3, 16, B_), 256, GEMM_SMEM>>>(
        phi, yThi, hp, nullptr, nullptr, nullptr, nullptr, nullptr, nullptr,
        nullptr, nullptr, HH_, S_, 1.f,
        (size_t)S_ * S_, (size_t)HH_ * S_, (size_t)S_ * HH_);

    // 7-9. scores (with 1/Z rescale), span+pool, head
    lnscore_kernel<<<B_ * S_, 128>>>(hp, zq, g1, be1, W2, b2, am, tp);
    span_pool_kernel<<<B_, 256>>>(tp, am, x, pp);
    head_kernel<<<B_, 384>>>(pp, x, Wc1, bc1, g2, be2, Wc2, bc2, Mint, Wcls, bcls, out);
}